// round 1
// baseline (speedup 1.0000x reference)
#include <cuda_runtime.h>

#define S_LEN 2048
#define EMB   2048
#define NH    16
#define DH    128
#define BATCH 2

// Scratch (no cudaMalloc allowed): qkv activations + attention output
__device__ float g_qkv[(size_t)BATCH * S_LEN * 3 * EMB];   // ~100.7 MB
__device__ float g_attn[(size_t)BATCH * S_LEN * EMB];      // ~33.6 MB

// ---------------------------------------------------------------------------
// SGEMM with bias: C[M,N] = A[M,K] @ B[K,N] + bias[N]
// Row-major. Requires M%128==0, N%128==0, K%8==0 (true for all calls here).
// BM=BN=128, BK=8, 256 threads, 8x8 per-thread microtile.
// ---------------------------------------------------------------------------
__global__ __launch_bounds__(256) void sgemm_bias_kernel(
    int M, int N, int K,
    const float* __restrict__ A, const float* __restrict__ B,
    const float* __restrict__ bias, float* __restrict__ C)
{
    constexpr int BM = 128, BN = 128, BK = 8, TM = 8, TN = 8;
    __shared__ float As[BK][BM];   // A tile stored transposed
    __shared__ float Bs[BK][BN];

    const int tid = threadIdx.x;
    const int bx = blockIdx.x, by = blockIdx.y;
    const int tcol = tid & 15;         // 0..15
    const int trow = tid >> 4;         // 0..15

    // Global-load mapping
    const int a_row = tid >> 1;            // 0..127
    const int a_col = (tid & 1) << 2;      // 0 or 4
    const int b_row = tid >> 5;            // 0..7
    const int b_col = (tid & 31) << 2;     // 0..124

    const float* Ag = A + (size_t)(by * BM + a_row) * K + a_col;
    const float* Bg = B + (size_t)b_row * N + (size_t)bx * BN + b_col;

    float acc[TM][TN];
    #pragma unroll
    for (int i = 0; i < TM; i++)
        #pragma unroll
        for (int j = 0; j < TN; j++) acc[i][j] = 0.f;

    for (int k0 = 0; k0 < K; k0 += BK) {
        float4 av = *(const float4*)(Ag + k0);
        As[a_col + 0][a_row] = av.x;
        As[a_col + 1][a_row] = av.y;
        As[a_col + 2][a_row] = av.z;
        As[a_col + 3][a_row] = av.w;
        float4 bv = *(const float4*)(Bg + (size_t)k0 * N);
        *(float4*)&Bs[b_row][b_col] = bv;
        __syncthreads();

        #pragma unroll
        for (int kk = 0; kk < BK; kk++) {
            float ar[TM], br[TN];
            *(float4*)&ar[0] = *(const float4*)&As[kk][trow * TM];
            *(float4*)&ar[4] = *(const float4*)&As[kk][trow * TM + 4];
            *(float4*)&br[0] = *(const float4*)&Bs[kk][tcol * TN];
            *(float4*)&br[4] = *(const float4*)&Bs[kk][tcol * TN + 4];
            #pragma unroll
            for (int i = 0; i < TM; i++)
                #pragma unroll
                for (int j = 0; j < TN; j++)
                    acc[i][j] = fmaf(ar[i], br[j], acc[i][j]);
        }
        __syncthreads();
    }

    #pragma unroll
    for (int i = 0; i < TM; i++) {
        size_t row = (size_t)by * BM + trow * TM + i;
        #pragma unroll
        for (int j = 0; j < TN; j += 4) {
            int col = bx * BN + tcol * TN + j;
            float4 o;
            o.x = acc[i][j + 0] + bias[col + 0];
            o.y = acc[i][j + 1] + bias[col + 1];
            o.z = acc[i][j + 2] + bias[col + 2];
            o.w = acc[i][j + 3] + bias[col + 3];
            *(float4*)(C + row * N + col) = o;
        }
    }
}

// ---------------------------------------------------------------------------
// Fused flash-attention-style kernel, fp32, online softmax.
// qkv layout per token row (6144 floats): 16 heads x [q(128) | k(128) | v(128)]
// grid: (S/64, NH, BATCH), 256 threads. Each block: 64 query rows x dh=128.
// Output: g_attn[b, s, h*128 + d]  (i.e. (B,S,E) with heads re-interleaved)
// ---------------------------------------------------------------------------
#define TQ 64
#define TK 64
#define QK_PAD 129   // DH + 1, kills the stride-512 bank conflict
#define PS_PAD 65

// smem floats: Qs 64*129 + Ks 64*129 + Vs 64*128 + Ps 64*65 + 3*64
#define ATTN_SMEM_FLOATS (TQ*QK_PAD + TK*QK_PAD + TK*DH + TQ*PS_PAD + 3*TQ)
#define ATTN_SMEM_BYTES  (ATTN_SMEM_FLOATS * 4)

__global__ __launch_bounds__(256) void attn_kernel(
    const float* __restrict__ qkv, float* __restrict__ out)
{
    extern __shared__ float sm[];
    float* Qs  = sm;                       // [TQ][QK_PAD]
    float* Ks  = Qs + TQ * QK_PAD;         // [TK][QK_PAD]
    float* Vs  = Ks + TK * QK_PAD;         // [TK][DH]
    float* Ps  = Vs + TK * DH;             // [TQ][PS_PAD]
    float* m_s = Ps + TQ * PS_PAD;         // [TQ]
    float* l_s = m_s + TQ;                 // [TQ]
    float* fac = l_s + TQ;                 // [TQ]

    const int tid = threadIdx.x;
    const int qt = blockIdx.x, h = blockIdx.y, b = blockIdx.z;
    const int tx = tid & 15;   // O cols: tx*8..+7 ; S cols: tx*4..+3
    const int ty = tid >> 4;   // rows: ty*4..+3

    const size_t head_base = (size_t)b * S_LEN * (3 * EMB) + (size_t)h * (3 * DH);
    const float scale = 0.08838834764831845f;  // 1/sqrt(128)

    // Load Q tile, pre-scaled
    for (int i = tid; i < TQ * DH / 4; i += 256) {
        int r = i >> 5;              // 32 float4 per 128-wide row
        int c = (i & 31) << 2;
        const float4 v = *(const float4*)(qkv + head_base +
                            (size_t)(qt * TQ + r) * (3 * EMB) + c);
        float* q = Qs + r * QK_PAD + c;
        q[0] = v.x * scale; q[1] = v.y * scale;
        q[2] = v.z * scale; q[3] = v.w * scale;
    }
    if (tid < TQ) { m_s[tid] = -1e30f; l_s[tid] = 0.f; }

    float Oacc[4][8];
    #pragma unroll
    for (int i = 0; i < 4; i++)
        #pragma unroll
        for (int j = 0; j < 8; j++) Oacc[i][j] = 0.f;

    for (int kt = 0; kt < S_LEN / TK; kt++) {
        __syncthreads();  // Q-load done (kt==0); prev iter's Ks/Vs/Ps reads done

        // Load K and V tiles
        for (int i = tid; i < TK * DH / 4; i += 256) {
            int r = i >> 5;
            int c = (i & 31) << 2;
            size_t g = head_base + (size_t)(kt * TK + r) * (3 * EMB) + c;
            float4 kv = *(const float4*)(qkv + g + DH);
            float* kd = Ks + r * QK_PAD + c;
            kd[0] = kv.x; kd[1] = kv.y; kd[2] = kv.z; kd[3] = kv.w;
            float4 vv = *(const float4*)(qkv + g + 2 * DH);
            *(float4*)(Vs + r * DH + c) = vv;
        }
        __syncthreads();

        // S = Q @ K^T : each thread computes a 4x4 score tile
        {
            float acc[4][4];
            #pragma unroll
            for (int i = 0; i < 4; i++)
                #pragma unroll
                for (int j = 0; j < 4; j++) acc[i][j] = 0.f;

            const float* qr = Qs + (ty * 4) * QK_PAD;
            const float* kr = Ks + (tx * 4) * QK_PAD;
            #pragma unroll 4
            for (int k = 0; k < DH; k++) {
                float a0 = qr[0 * QK_PAD + k];
                float a1 = qr[1 * QK_PAD + k];
                float a2 = qr[2 * QK_PAD + k];
                float a3 = qr[3 * QK_PAD + k];
                float b0 = kr[0 * QK_PAD + k];
                float b1 = kr[1 * QK_PAD + k];
                float b2 = kr[2 * QK_PAD + k];
                float b3 = kr[3 * QK_PAD + k];
                acc[0][0] = fmaf(a0, b0, acc[0][0]);
                acc[0][1] = fmaf(a0, b1, acc[0][1]);
                acc[0][2] = fmaf(a0, b2, acc[0][2]);
                acc[0][3] = fmaf(a0, b3, acc[0][3]);
                acc[1][0] = fmaf(a1, b0, acc[1][0]);
                acc[1][1] = fmaf(a1, b1, acc[1][1]);
                acc[1][2] = fmaf(a1, b2, acc[1][2]);
                acc[1][3] = fmaf(a1, b3, acc[1][3]);
                acc[2][0] = fmaf(a2, b0, acc[2][0]);
                acc[2][1] = fmaf(a2, b1, acc[2][1]);
                acc[2][2] = fmaf(a2, b2, acc[2][2]);
                acc[2][3] = fmaf(a2, b3, acc[2][3]);
                acc[3][0] = fmaf(a3, b0, acc[3][0]);
                acc[3][1] = fmaf(a3, b1, acc[3][1]);
                acc[3][2] = fmaf(a3, b2, acc[3][2]);
                acc[3][3] = fmaf(a3, b3, acc[3][3]);
            }
            #pragma unroll
            for (int i = 0; i < 4; i++)
                #pragma unroll
                for (int j = 0; j < 4; j++)
                    Ps[(ty * 4 + i) * PS_PAD + tx * 4 + j] = acc[i][j];
        }
        __syncthreads();

        // Online softmax update: 4 threads per row
        {
            const int row = tid >> 2, sub = tid & 3;
            float* pr = Ps + row * PS_PAD + sub * 16;
            float mx = -1e30f;
            #pragma unroll
            for (int i = 0; i < 16; i++) mx = fmaxf(mx, pr[i]);
            mx = fmaxf(mx, __shfl_xor_sync(0xffffffffu, mx, 1));
            mx = fmaxf(mx, __shfl_xor_sync(0xffffffffu, mx, 2));
            const float m_old = m_s[row];
            const float m_new = fmaxf(m_old, mx);
            float s = 0.f;
            #pragma unroll
            for (int i = 0; i < 16; i++) {
                float p = __expf(pr[i] - m_new);
                pr[i] = p;
                s += p;
            }
            s += __shfl_xor_sync(0xffffffffu, s, 1);
            s += __shfl_xor_sync(0xffffffffu, s, 2);
            if (sub == 0) {
                float f = __expf(m_old - m_new);
                l_s[row] = l_s[row] * f + s;
                m_s[row] = m_new;
                fac[row] = f;
            }
        }
        __syncthreads();

        // O = O*fac + P @ V : each thread owns rows ty*4..+3, cols tx*8..+7
        #pragma unroll
        for (int i = 0; i < 4; i++) {
            const float f = fac[ty * 4 + i];
            #pragma unroll
            for (int j = 0; j < 8; j++) Oacc[i][j] *= f;
        }
        #pragma unroll 2
        for (int j = 0; j < TK; j++) {
            const float p0 = Ps[(ty * 4 + 0) * PS_PAD + j];
            const float p1 = Ps[(ty * 4 + 1) * PS_PAD + j];
            const float p2 = Ps[(ty * 4 + 2) * PS_PAD + j];
            const float p3 = Ps[(ty * 4 + 3) * PS_PAD + j];
            const float* vrow = Vs + j * DH + tx * 8;
            float4 v0 = *(const float4*)(vrow);
            float4 v1 = *(const float4*)(vrow + 4);
            const float vv[8] = {v0.x, v0.y, v0.z, v0.w, v1.x, v1.y, v1.z, v1.w};
            #pragma unroll
            for (int c = 0; c < 8; c++) {
                Oacc[0][c] = fmaf(p0, vv[c], Oacc[0][c]);
                Oacc[1][c] = fmaf(p1, vv[c], Oacc[1][c]);
                Oacc[2][c] = fmaf(p2, vv[c], Oacc[2][c]);
                Oacc[3][c] = fmaf(p3, vv[c], Oacc[3][c]);
            }
        }
    }

    // Normalize and write: out[b, s, h*128 + c]
    #pragma unroll
    for (int i = 0; i < 4; i++) {
        const int r = ty * 4 + i;
        const float inv = 1.f / l_s[r];
        size_t o = ((size_t)b * S_LEN + qt * TQ + r) * EMB + h * DH + tx * 8;
        float4 w0, w1;
        w0.x = Oacc[i][0] * inv; w0.y = Oacc[i][1] * inv;
        w0.z = Oacc[i][2] * inv; w0.w = Oacc[i][3] * inv;
        w1.x = Oacc[i][4] * inv; w1.y = Oacc[i][5] * inv;
        w1.z = Oacc[i][6] * inv; w1.w = Oacc[i][7] * inv;
        *(float4*)(out + o) = w0;
        *(float4*)(out + o + 4) = w1;
    }
}

// ---------------------------------------------------------------------------
extern "C" void kernel_launch(void* const* d_in, const int* in_sizes, int n_in,
                              void* d_out, int out_size)
{
    (void)in_sizes; (void)n_in; (void)out_size;
    const float* x    = (const float*)d_in[0];
    const float* Wqkv = (const float*)d_in[1];
    const float* bqkv = (const float*)d_in[2];
    const float* Wout = (const float*)d_in[3];
    const float* bout = (const float*)d_in[4];
    float* out = (float*)d_out;

    float *qkv = nullptr, *attn = nullptr;
    cudaGetSymbolAddress((void**)&qkv, g_qkv);
    cudaGetSymbolAddress((void**)&attn, g_attn);

    cudaFuncSetAttribute(attn_kernel,
                         cudaFuncAttributeMaxDynamicSharedMemorySize,
                         ATTN_SMEM_BYTES);

    const int M = BATCH * S_LEN;  // 4096

    // 1) qkv = x @ W_qkv + b_qkv   (4096 x 6144 x 2048)
    {
        dim3 grid((3 * EMB) / 128, M / 128);
        sgemm_bias_kernel<<<grid, 256>>>(M, 3 * EMB, EMB, x, Wqkv, bqkv, qkv);
    }

    // 2) fused multi-head attention
    {
        dim3 grid(S_LEN / TQ, NH, BATCH);
        attn_kernel<<<grid, 256, ATTN_SMEM_BYTES>>>(qkv, attn);
    }

    // 3) out = attn @ W_out + b_out   (4096 x 2048 x 2048)
    {
        dim3 grid(EMB / 128, M / 128);
        sgemm_bias_kernel<<<grid, 256>>>(M, EMB, EMB, attn, Wout, bout, out);
    }
}

// round 3
// speedup vs baseline: 1.6271x; 1.6271x over previous
#include <cuda_runtime.h>
#include <cuda_bf16.h>
#include <cstdint>

#define S_LEN 2048
#define EMB   2048
#define NH    16
#define DH    128
#define BATCH 2
#define MROWS (BATCH * S_LEN)   // 4096
#define GK    2048              // K for both projection GEMMs

// ---------------------------------------------------------------------------
// Device scratch (no cudaMalloc allowed)
// ---------------------------------------------------------------------------
__device__ float g_qkv[(size_t)MROWS * 3 * EMB];          // ~100.7 MB
__device__ float g_attn[(size_t)MROWS * EMB];             // ~33.6 MB
__device__ __nv_bfloat16 g_ah[(size_t)MROWS * GK];        // A hi (x, then attn)
__device__ __nv_bfloat16 g_al[(size_t)MROWS * GK];        // A lo
__device__ __nv_bfloat16 g_wqh[(size_t)(3 * EMB) * GK];   // W_qkv^T hi [6144,2048]
__device__ __nv_bfloat16 g_wql[(size_t)(3 * EMB) * GK];
__device__ __nv_bfloat16 g_woh[(size_t)EMB * GK];         // W_out^T hi [2048,2048]
__device__ __nv_bfloat16 g_wol[(size_t)EMB * GK];

// ---------------------------------------------------------------------------
// PTX helpers (plain sm_80+ instructions only; NO 'a'-suffix features)
// ---------------------------------------------------------------------------
__device__ __forceinline__ uint32_t smem_to_u32(const void* p) {
    uint32_t a;
    asm("{ .reg .u64 t; cvta.to.shared.u64 t, %1; cvt.u32.u64 %0, t; }"
        : "=r"(a) : "l"(p));
    return a;
}

__device__ __forceinline__ void cp_async16(uint32_t saddr, const void* gaddr) {
    asm volatile("cp.async.cg.shared.global [%0], [%1], 16;"
        :: "r"(saddr), "l"(gaddr) : "memory");
}
#define CP_COMMIT() asm volatile("cp.async.commit_group;" ::: "memory")
#define CP_WAIT(n)  asm volatile("cp.async.wait_group %0;" :: "n"(n) : "memory")

__device__ __forceinline__ void ldsm_x4(uint32_t* r, uint32_t addr) {
    asm volatile("ldmatrix.sync.aligned.m8n8.x4.shared.b16 {%0,%1,%2,%3}, [%4];"
        : "=r"(r[0]), "=r"(r[1]), "=r"(r[2]), "=r"(r[3]) : "r"(addr));
}

__device__ __forceinline__ void mma16816(float* d, const uint32_t* a,
                                         const uint32_t* b) {
    asm volatile(
        "mma.sync.aligned.m16n8k16.row.col.f32.bf16.bf16.f32 "
        "{%0,%1,%2,%3}, {%4,%5,%6,%7}, {%8,%9}, {%0,%1,%2,%3};"
        : "+f"(d[0]), "+f"(d[1]), "+f"(d[2]), "+f"(d[3])
        : "r"(a[0]), "r"(a[1]), "r"(a[2]), "r"(a[3]), "r"(b[0]), "r"(b[1]));
}

// ---------------------------------------------------------------------------
// Conversion kernels: fp32 -> bf16 hi/lo split
// ---------------------------------------------------------------------------
__global__ __launch_bounds__(256) void split_kernel(
    const float* __restrict__ in, __nv_bfloat16* __restrict__ hi,
    __nv_bfloat16* __restrict__ lo, int n)
{
    int i = blockIdx.x * blockDim.x + threadIdx.x;
    int stride = gridDim.x * blockDim.x;
    for (; i < n; i += stride) {
        float v = in[i];
        __nv_bfloat16 h = __float2bfloat16(v);
        hi[i] = h;
        lo[i] = __float2bfloat16(v - __bfloat162float(h));
    }
}

// W[K,N] row-major -> T[N,K] bf16 hi/lo
__global__ __launch_bounds__(256) void transpose_split_kernel(
    const float* __restrict__ W, __nv_bfloat16* __restrict__ Th,
    __nv_bfloat16* __restrict__ Tl, int K, int N)
{
    __shared__ float t[32][33];
    const int nb = blockIdx.x * 32;
    const int kb = blockIdx.y * 32;
    const int x = threadIdx.x, y = threadIdx.y;   // block (32,8)
    #pragma unroll
    for (int j = 0; j < 32; j += 8)
        t[y + j][x] = W[(size_t)(kb + y + j) * N + nb + x];
    __syncthreads();
    #pragma unroll
    for (int j = 0; j < 32; j += 8) {
        float v = t[x][y + j];                    // = W[kb+x][nb+y+j]
        __nv_bfloat16 h = __float2bfloat16(v);
        size_t o = (size_t)(nb + y + j) * K + kb + x;
        Th[o] = h;
        Tl[o] = __float2bfloat16(v - __bfloat162float(h));
    }
}

// ---------------------------------------------------------------------------
// HMMA (mma.sync bf16) GEMM with 3-term hi/lo split:
//   C[M,N] = Ah*Bh^T + Ah*Bl^T + Al*Bh^T + bias
// A*: [M, 2048] bf16 row-major. B*: [N, 2048] bf16 row-major (pre-transposed).
// Block tile 128x128, 8 warps (2x4), warp tile 64x32, K-chunk 64.
// SMEM: 4 tiles (Ah,Al,Bh,Bl) of 128x128B per stage, double-buffered (128 KB).
// XOR swizzle: 16B-unit index ^= (row & 7)  -> conflict-free ldmatrix.
// ---------------------------------------------------------------------------
#define GBK   64
#define NCHUNK (GK / GBK)       // 32
#define TBYTES 16384            // 128 rows x 128 B
#define STAGE  (4 * TBYTES)     // 64 KB
#define GEMM_SMEM (2 * STAGE)   // 128 KB

__global__ __launch_bounds__(256) void gemm_mma_kernel(
    int N,
    const __nv_bfloat16* __restrict__ Ah, const __nv_bfloat16* __restrict__ Al,
    const __nv_bfloat16* __restrict__ Bh, const __nv_bfloat16* __restrict__ Bl,
    const float* __restrict__ bias, float* __restrict__ C)
{
    extern __shared__ char gsm[];
    const uint32_t sb = smem_to_u32(gsm);
    const int tid = threadIdx.x;
    const int w = tid >> 5, l = tid & 31;
    const int warp_m = w >> 2, warp_n = w & 3;    // 2 x 4 warp grid
    const int bx = blockIdx.x, by = blockIdx.y;

    const __nv_bfloat16* srcs[4] = {
        Ah + (size_t)(by * 128) * GK, Al + (size_t)(by * 128) * GK,
        Bh + (size_t)(bx * 128) * GK, Bl + (size_t)(bx * 128) * GK };

    // Accumulators initialized with bias (c0,c1 at col n,n+1; c2,c3 same cols, row+8)
    float acc[4][4][4];
    #pragma unroll
    for (int nt = 0; nt < 4; nt++) {
        const int n = bx * 128 + warp_n * 32 + nt * 8 + ((l & 3) << 1);
        const float b0 = bias[n], b1 = bias[n + 1];
        #pragma unroll
        for (int mt = 0; mt < 4; mt++) {
            acc[mt][nt][0] = b0; acc[mt][nt][1] = b1;
            acc[mt][nt][2] = b0; acc[mt][nt][3] = b1;
        }
    }

    // ---- async load of one K-chunk into stage (kt&1) ----
    auto load_chunk = [&](int kt) {
        const uint32_t st = sb + (kt & 1) * STAGE;
        const size_t kofs = (size_t)kt * GBK;           // bf16 elements
        #pragma unroll
        for (int a = 0; a < 4; a++) {
            const char* g = (const char*)(srcs[a] + kofs);
            #pragma unroll
            for (int j = 0; j < 4; j++) {               // 1024 units / 256 thr
                const int u = tid + 256 * j;
                const int r = u >> 3;
                const int cu = u & 7;
                const uint32_t off = r * 128 + ((cu ^ (r & 7)) << 4);
                cp_async16(st + a * TBYTES + off,
                           g + (size_t)r * (GK * 2) + (cu << 4));
            }
        }
        CP_COMMIT();
    };

    load_chunk(0);

    for (int kt = 0; kt < NCHUNK; kt++) {
        if (kt + 1 < NCHUNK) { load_chunk(kt + 1); CP_WAIT(1); }
        else                 { CP_WAIT(0); }
        __syncthreads();

        const uint32_t st = sb + (kt & 1) * STAGE;
        const uint32_t sAh = st, sAl = st + TBYTES;
        const uint32_t sBh = st + 2 * TBYTES, sBl = st + 3 * TBYTES;

        #pragma unroll
        for (int kk = 0; kk < 4; kk++) {
            const int kb = kk * 32;    // byte col base of this k16 step

            uint32_t ah[4][4], al[4][4];
            #pragma unroll
            for (int mt = 0; mt < 4; mt++) {
                const int row = warp_m * 64 + mt * 16 + (l & 15);
                const int bc = kb + ((l >> 4) << 4);
                const uint32_t off = row * 128 + (bc ^ ((row & 7) << 4));
                ldsm_x4(ah[mt], sAh + off);
                ldsm_x4(al[mt], sAl + off);
            }

            // B: one x4 covers two n8 tiles (regs [b0,b1] tile0, [b0,b1] tile1)
            uint32_t bh[2][4], bl[2][4];
            #pragma unroll
            for (int np = 0; np < 2; np++) {
                const int g = l >> 3, idx = l & 7;
                const int row = warp_n * 32 + np * 16 + ((g >> 1) << 3) + idx;
                const int bc = kb + ((g & 1) << 4);
                const uint32_t off = row * 128 + (bc ^ ((row & 7) << 4));
                ldsm_x4(bh[np], sBh + off);
                ldsm_x4(bl[np], sBl + off);
            }

            #pragma unroll
            for (int mt = 0; mt < 4; mt++)
                #pragma unroll
                for (int nt = 0; nt < 4; nt++) {
                    const uint32_t* bhp = &bh[nt >> 1][(nt & 1) * 2];
                    const uint32_t* blp = &bl[nt >> 1][(nt & 1) * 2];
                    mma16816(acc[mt][nt], ah[mt], bhp);   // Ah*Bh
                    mma16816(acc[mt][nt], ah[mt], blp);   // Ah*Bl
                    mma16816(acc[mt][nt], al[mt], bhp);   // Al*Bh
                }
        }
        __syncthreads();   // before next iter's load overwrites buf (kt&1)^1... (kt)
    }

    // Epilogue: direct stores (fp32, 2 floats per store)
    #pragma unroll
    for (int mt = 0; mt < 4; mt++) {
        const int m = by * 128 + warp_m * 64 + mt * 16 + (l >> 2);
        float* c0 = C + (size_t)m * N + bx * 128 + warp_n * 32 + ((l & 3) << 1);
        #pragma unroll
        for (int nt = 0; nt < 4; nt++) {
            float2 v0 = make_float2(acc[mt][nt][0], acc[mt][nt][1]);
            float2 v1 = make_float2(acc[mt][nt][2], acc[mt][nt][3]);
            *(float2*)(c0 + nt * 8) = v0;
            *(float2*)(c0 + (size_t)8 * N + nt * 8) = v1;
        }
    }
}

// ---------------------------------------------------------------------------
// Fused flash-attention kernel (fp32, online softmax) — unchanged from R1.
// qkv row layout (6144 f32): 16 heads x [q(128) | k(128) | v(128)]
// ---------------------------------------------------------------------------
#define TQ 64
#define TK 64
#define QK_PAD 129
#define PS_PAD 65
#define ATTN_SMEM_FLOATS (TQ*QK_PAD + TK*QK_PAD + TK*DH + TQ*PS_PAD + 3*TQ)
#define ATTN_SMEM_BYTES  (ATTN_SMEM_FLOATS * 4)

__global__ __launch_bounds__(256) void attn_kernel(
    const float* __restrict__ qkv, float* __restrict__ out)
{
    extern __shared__ float sm[];
    float* Qs  = sm;
    float* Ks  = Qs + TQ * QK_PAD;
    float* Vs  = Ks + TK * QK_PAD;
    float* Ps  = Vs + TK * DH;
    float* m_s = Ps + TQ * PS_PAD;
    float* l_s = m_s + TQ;
    float* fac = l_s + TQ;

    const int tid = threadIdx.x;
    const int qt = blockIdx.x, h = blockIdx.y, b = blockIdx.z;
    const int tx = tid & 15;
    const int ty = tid >> 4;

    const size_t head_base = (size_t)b * S_LEN * (3 * EMB) + (size_t)h * (3 * DH);
    const float scale = 0.08838834764831845f;

    for (int i = tid; i < TQ * DH / 4; i += 256) {
        int r = i >> 5;
        int c = (i & 31) << 2;
        const float4 v = *(const float4*)(qkv + head_base +
                            (size_t)(qt * TQ + r) * (3 * EMB) + c);
        float* q = Qs + r * QK_PAD + c;
        q[0] = v.x * scale; q[1] = v.y * scale;
        q[2] = v.z * scale; q[3] = v.w * scale;
    }
    if (tid < TQ) { m_s[tid] = -1e30f; l_s[tid] = 0.f; }

    float Oacc[4][8];
    #pragma unroll
    for (int i = 0; i < 4; i++)
        #pragma unroll
        for (int j = 0; j < 8; j++) Oacc[i][j] = 0.f;

    for (int kt = 0; kt < S_LEN / TK; kt++) {
        __syncthreads();

        for (int i = tid; i < TK * DH / 4; i += 256) {
            int r = i >> 5;
            int c = (i & 31) << 2;
            size_t g = head_base + (size_t)(kt * TK + r) * (3 * EMB) + c;
            float4 kv = *(const float4*)(qkv + g + DH);
            float* kd = Ks + r * QK_PAD + c;
            kd[0] = kv.x; kd[1] = kv.y; kd[2] = kv.z; kd[3] = kv.w;
            float4 vv = *(const float4*)(qkv + g + 2 * DH);
            *(float4*)(Vs + r * DH + c) = vv;
        }
        __syncthreads();

        {
            float acc[4][4];
            #pragma unroll
            for (int i = 0; i < 4; i++)
                #pragma unroll
                for (int j = 0; j < 4; j++) acc[i][j] = 0.f;

            const float* qr = Qs + (ty * 4) * QK_PAD;
            const float* kr = Ks + (tx * 4) * QK_PAD;
            #pragma unroll 4
            for (int k = 0; k < DH; k++) {
                float a0 = qr[0 * QK_PAD + k];
                float a1 = qr[1 * QK_PAD + k];
                float a2 = qr[2 * QK_PAD + k];
                float a3 = qr[3 * QK_PAD + k];
                float b0 = kr[0 * QK_PAD + k];
                float b1 = kr[1 * QK_PAD + k];
                float b2 = kr[2 * QK_PAD + k];
                float b3 = kr[3 * QK_PAD + k];
                acc[0][0] = fmaf(a0, b0, acc[0][0]);
                acc[0][1] = fmaf(a0, b1, acc[0][1]);
                acc[0][2] = fmaf(a0, b2, acc[0][2]);
                acc[0][3] = fmaf(a0, b3, acc[0][3]);
                acc[1][0] = fmaf(a1, b0, acc[1][0]);
                acc[1][1] = fmaf(a1, b1, acc[1][1]);
                acc[1][2] = fmaf(a1, b2, acc[1][2]);
                acc[1][3] = fmaf(a1, b3, acc[1][3]);
                acc[2][0] = fmaf(a2, b0, acc[2][0]);
                acc[2][1] = fmaf(a2, b1, acc[2][1]);
                acc[2][2] = fmaf(a2, b2, acc[2][2]);
                acc[2][3] = fmaf(a2, b3, acc[2][3]);
                acc[3][0] = fmaf(a3, b0, acc[3][0]);
                acc[3][1] = fmaf(a3, b1, acc[3][1]);
                acc[3][2] = fmaf(a3, b2, acc[3][2]);
                acc[3][3] = fmaf(a3, b3, acc[3][3]);
            }
            #pragma unroll
            for (int i = 0; i < 4; i++)
                #pragma unroll
                for (int j = 0; j < 4; j++)
                    Ps[(ty * 4 + i) * PS_PAD + tx * 4 + j] = acc[i][j];
        }
        __syncthreads();

        {
            const int row = tid >> 2, sub = tid & 3;
            float* pr = Ps + row * PS_PAD + sub * 16;
            float mx = -1e30f;
            #pragma unroll
            for (int i = 0; i < 16; i++) mx = fmaxf(mx, pr[i]);
            mx = fmaxf(mx, __shfl_xor_sync(0xffffffffu, mx, 1));
            mx = fmaxf(mx, __shfl_xor_sync(0xffffffffu, mx, 2));
            const float m_old = m_s[row];
            const float m_new = fmaxf(m_old, mx);
            float s = 0.f;
            #pragma unroll
            for (int i = 0; i < 16; i++) {
                float p = __expf(pr[i] - m_new);
                pr[i] = p;
                s += p;
            }
            s += __shfl_xor_sync(0xffffffffu, s, 1);
            s += __shfl_xor_sync(0xffffffffu, s, 2);
            if (sub == 0) {
                float f = __expf(m_old - m_new);
                l_s[row] = l_s[row] * f + s;
                m_s[row] = m_new;
                fac[row] = f;
            }
        }
        __syncthreads();

        #pragma unroll
        for (int i = 0; i < 4; i++) {
            const float f = fac[ty * 4 + i];
            #pragma unroll
            for (int j = 0; j < 8; j++) Oacc[i][j] *= f;
        }
        #pragma unroll 2
        for (int j = 0; j < TK; j++) {
            const float p0 = Ps[(ty * 4 + 0) * PS_PAD + j];
            const float p1 = Ps[(ty * 4 + 1) * PS_PAD + j];
            const float p2 = Ps[(ty * 4 + 2) * PS_PAD + j];
            const float p3 = Ps[(ty * 4 + 3) * PS_PAD + j];
            const float* vrow = Vs + j * DH + tx * 8;
            float4 v0 = *(const float4*)(vrow);
            float4 v1 = *(const float4*)(vrow + 4);
            const float vv[8] = {v0.x, v0.y, v0.z, v0.w, v1.x, v1.y, v1.z, v1.w};
            #pragma unroll
            for (int c = 0; c < 8; c++) {
                Oacc[0][c] = fmaf(p0, vv[c], Oacc[0][c]);
                Oacc[1][c] = fmaf(p1, vv[c], Oacc[1][c]);
                Oacc[2][c] = fmaf(p2, vv[c], Oacc[2][c]);
                Oacc[3][c] = fmaf(p3, vv[c], Oacc[3][c]);
            }
        }
    }

    #pragma unroll
    for (int i = 0; i < 4; i++) {
        const int r = ty * 4 + i;
        const float inv = 1.f / l_s[r];
        size_t o = ((size_t)b * S_LEN + qt * TQ + r) * EMB + h * DH + tx * 8;
        float4 w0, w1;
        w0.x = Oacc[i][0] * inv; w0.y = Oacc[i][1] * inv;
        w0.z = Oacc[i][2] * inv; w0.w = Oacc[i][3] * inv;
        w1.x = Oacc[i][4] * inv; w1.y = Oacc[i][5] * inv;
        w1.z = Oacc[i][6] * inv; w1.w = Oacc[i][7] * inv;
        *(float4*)(out + o) = w0;
        *(float4*)(out + o + 4) = w1;
    }
}

// ---------------------------------------------------------------------------
extern "C" void kernel_launch(void* const* d_in, const int* in_sizes, int n_in,
                              void* d_out, int out_size)
{
    (void)in_sizes; (void)n_in; (void)out_size;
    const float* x    = (const float*)d_in[0];
    const float* Wqkv = (const float*)d_in[1];
    const float* bqkv = (const float*)d_in[2];
    const float* Wout = (const float*)d_in[3];
    const float* bout = (const float*)d_in[4];
    float* out = (float*)d_out;

    float *qkv = nullptr, *attn = nullptr;
    __nv_bfloat16 *ah, *al, *wqh, *wql, *woh, *wol;
    cudaGetSymbolAddress((void**)&qkv, g_qkv);
    cudaGetSymbolAddress((void**)&attn, g_attn);
    cudaGetSymbolAddress((void**)&ah, g_ah);
    cudaGetSymbolAddress((void**)&al, g_al);
    cudaGetSymbolAddress((void**)&wqh, g_wqh);
    cudaGetSymbolAddress((void**)&wql, g_wql);
    cudaGetSymbolAddress((void**)&woh, g_woh);
    cudaGetSymbolAddress((void**)&wol, g_wol);

    cudaFuncSetAttribute(attn_kernel,
                         cudaFuncAttributeMaxDynamicSharedMemorySize,
                         ATTN_SMEM_BYTES);
    cudaFuncSetAttribute(gemm_mma_kernel,
                         cudaFuncAttributeMaxDynamicSharedMemorySize,
                         GEMM_SMEM);

    // 0) fp32 -> bf16 hi/lo conversions
    split_kernel<<<2048, 256>>>(x, ah, al, MROWS * EMB);
    transpose_split_kernel<<<dim3((3 * EMB) / 32, GK / 32), dim3(32, 8)>>>(
        Wqkv, wqh, wql, GK, 3 * EMB);
    transpose_split_kernel<<<dim3(EMB / 32, GK / 32), dim3(32, 8)>>>(
        Wout, woh, wol, GK, EMB);

    // 1) qkv = x @ W_qkv + b_qkv  (HMMA, 4096 x 6144 x 2048)
    gemm_mma_kernel<<<dim3((3 * EMB) / 128, MROWS / 128), 256, GEMM_SMEM>>>(
        3 * EMB, ah, al, wqh, wql, bqkv, qkv);

    // 2) fused multi-head attention (fp32)
    attn_kernel<<<dim3(S_LEN / TQ, NH, BATCH), 256, ATTN_SMEM_BYTES>>>(qkv, attn);

    // 3) out = attn @ W_out + b_out  (HMMA, 4096 x 2048 x 2048)
    split_kernel<<<2048, 256>>>(attn, ah, al, MROWS * EMB);
    gemm_mma_kernel<<<dim3(EMB / 128, MROWS / 128), 256, GEMM_SMEM>>>(
        EMB, ah, al, woh, wol, bout, out);
}

// round 4
// speedup vs baseline: 3.3261x; 2.0442x over previous
#include <cuda_runtime.h>
#include <cuda_bf16.h>
#include <cstdint>

#define S_LEN 2048
#define EMB   2048
#define NH    16
#define DH    128
#define BATCH 2
#define MROWS (BATCH * S_LEN)   // 4096
#define GK    2048              // K for both projection GEMMs

// ---------------------------------------------------------------------------
// Device scratch (no cudaMalloc allowed)
// ---------------------------------------------------------------------------
__device__ float g_qkv[(size_t)MROWS * 3 * EMB];          // ~100.7 MB
__device__ float g_attn[(size_t)MROWS * EMB];             // ~33.6 MB
__device__ __nv_bfloat16 g_ah[(size_t)MROWS * GK];
__device__ __nv_bfloat16 g_al[(size_t)MROWS * GK];
__device__ __nv_bfloat16 g_wqh[(size_t)(3 * EMB) * GK];
__device__ __nv_bfloat16 g_wql[(size_t)(3 * EMB) * GK];
__device__ __nv_bfloat16 g_woh[(size_t)EMB * GK];
__device__ __nv_bfloat16 g_wol[(size_t)EMB * GK];
// per-head Q/K/V hi/lo, layout [B, H, S, DH]
#define QKV_ELEMS ((size_t)BATCH * NH * S_LEN * DH)
__device__ __nv_bfloat16 g_qh[QKV_ELEMS];
__device__ __nv_bfloat16 g_ql[QKV_ELEMS];
__device__ __nv_bfloat16 g_kh[QKV_ELEMS];
__device__ __nv_bfloat16 g_kl[QKV_ELEMS];
__device__ __nv_bfloat16 g_vh[QKV_ELEMS];
__device__ __nv_bfloat16 g_vl[QKV_ELEMS];

// ---------------------------------------------------------------------------
// PTX helpers (plain sm_80+ instructions only; NO 'a'-suffix features)
// ---------------------------------------------------------------------------
__device__ __forceinline__ uint32_t smem_to_u32(const void* p) {
    uint32_t a;
    asm("{ .reg .u64 t; cvta.to.shared.u64 t, %1; cvt.u32.u64 %0, t; }"
        : "=r"(a) : "l"(p));
    return a;
}

__device__ __forceinline__ void cp_async16(uint32_t saddr, const void* gaddr) {
    asm volatile("cp.async.cg.shared.global [%0], [%1], 16;"
        :: "r"(saddr), "l"(gaddr) : "memory");
}
#define CP_COMMIT() asm volatile("cp.async.commit_group;" ::: "memory")
#define CP_WAIT(n)  asm volatile("cp.async.wait_group %0;" :: "n"(n) : "memory")

__device__ __forceinline__ void ldsm_x4(uint32_t* r, uint32_t addr) {
    asm volatile("ldmatrix.sync.aligned.m8n8.x4.shared.b16 {%0,%1,%2,%3}, [%4];"
        : "=r"(r[0]), "=r"(r[1]), "=r"(r[2]), "=r"(r[3]) : "r"(addr));
}
__device__ __forceinline__ void ldsm_x4_t(uint32_t* r, uint32_t addr) {
    asm volatile("ldmatrix.sync.aligned.m8n8.x4.trans.shared.b16 {%0,%1,%2,%3}, [%4];"
        : "=r"(r[0]), "=r"(r[1]), "=r"(r[2]), "=r"(r[3]) : "r"(addr));
}

__device__ __forceinline__ void mma16816(float* d, const uint32_t* a,
                                         const uint32_t* b) {
    asm volatile(
        "mma.sync.aligned.m16n8k16.row.col.f32.bf16.bf16.f32 "
        "{%0,%1,%2,%3}, {%4,%5,%6,%7}, {%8,%9}, {%0,%1,%2,%3};"
        : "+f"(d[0]), "+f"(d[1]), "+f"(d[2]), "+f"(d[3])
        : "r"(a[0]), "r"(a[1]), "r"(a[2]), "r"(a[3]), "r"(b[0]), "r"(b[1]));
}

// Fast 2^t on FMA/ALU pipes only (no MUFU, no CVT). |rel err| < 3e-6.
__device__ __forceinline__ float exp2_fast(float t) {
    t = fmaxf(t, -126.0f);
    const float MAGIC = 12582912.0f;          // 2^23 + 2^22
    float z = t + MAGIC;
    int i = __float_as_int(z);                // low bits hold round(t)
    float r = z - MAGIC;
    float f = t - r;                          // f in [-0.5, 0.5]
    float p = 1.3333558146e-3f;
    p = fmaf(p, f, 9.6181291076e-3f);
    p = fmaf(p, f, 5.5504108664e-2f);
    p = fmaf(p, f, 2.4022650696e-1f);
    p = fmaf(p, f, 6.9314718056e-1f);
    p = fmaf(p, f, 1.0f);
    int eb = (i + (127 - 0x4B400000)) << 23;  // (n+127)<<23
    return p * __int_as_float(eb);
}

// ---------------------------------------------------------------------------
// Conversion kernels: fp32 -> bf16 hi/lo split
// ---------------------------------------------------------------------------
__global__ __launch_bounds__(256) void split_kernel(
    const float* __restrict__ in, __nv_bfloat16* __restrict__ hi,
    __nv_bfloat16* __restrict__ lo, int n)
{
    int i = blockIdx.x * blockDim.x + threadIdx.x;
    int stride = gridDim.x * blockDim.x;
    for (; i < n; i += stride) {
        float v = in[i];
        __nv_bfloat16 h = __float2bfloat16(v);
        hi[i] = h;
        lo[i] = __float2bfloat16(v - __bfloat162float(h));
    }
}

// W[K,N] row-major -> T[N,K] bf16 hi/lo
__global__ __launch_bounds__(256) void transpose_split_kernel(
    const float* __restrict__ W, __nv_bfloat16* __restrict__ Th,
    __nv_bfloat16* __restrict__ Tl, int K, int N)
{
    __shared__ float t[32][33];
    const int nb = blockIdx.x * 32;
    const int kb = blockIdx.y * 32;
    const int x = threadIdx.x, y = threadIdx.y;   // block (32,8)
    #pragma unroll
    for (int j = 0; j < 32; j += 8)
        t[y + j][x] = W[(size_t)(kb + y + j) * N + nb + x];
    __syncthreads();
    #pragma unroll
    for (int j = 0; j < 32; j += 8) {
        float v = t[x][y + j];
        __nv_bfloat16 h = __float2bfloat16(v);
        size_t o = (size_t)(nb + y + j) * K + kb + x;
        Th[o] = h;
        Tl[o] = __float2bfloat16(v - __bfloat162float(h));
    }
}

// qkv [B,S,3E] (per row: 16 heads x [q|k|v] of 128) -> per-head hi/lo arrays
// Q is pre-scaled by log2(e)/sqrt(dh) so softmax works in exp2 domain.
__global__ __launch_bounds__(256) void qkv_split_kernel(
    const float* __restrict__ qkv)
{
    const float qscale = 0.12751744f;  // 1.44269504 / sqrt(128)
    size_t i = (size_t)blockIdx.x * blockDim.x + threadIdx.x;
    size_t stride = (size_t)gridDim.x * blockDim.x;
    const size_t total = QKV_ELEMS;
    for (; i < total; i += stride) {
        int d = i & 127;
        int h = (i >> 7) & 15;
        int s = (i >> 11) & 2047;
        int b = (int)(i >> 22);
        const float* src = qkv + ((size_t)(b * S_LEN + s)) * (3 * EMB) + h * (3 * DH);
        size_t dst = (((size_t)(b * NH + h)) * S_LEN + s) * DH + d;
        float q = src[d] * qscale;
        float k = src[DH + d];
        float v = src[2 * DH + d];
        __nv_bfloat16 qh = __float2bfloat16(q);
        __nv_bfloat16 kh = __float2bfloat16(k);
        __nv_bfloat16 vh = __float2bfloat16(v);
        g_qh[dst] = qh; g_ql[dst] = __float2bfloat16(q - __bfloat162float(qh));
        g_kh[dst] = kh; g_kl[dst] = __float2bfloat16(k - __bfloat162float(kh));
        g_vh[dst] = vh; g_vl[dst] = __float2bfloat16(v - __bfloat162float(vh));
    }
}

// ---------------------------------------------------------------------------
// HMMA GEMM with 3-term hi/lo split (unchanged from R3)
// ---------------------------------------------------------------------------
#define GBK   64
#define NCHUNK (GK / GBK)
#define TBYTES 16384
#define STAGE  (4 * TBYTES)
#define GEMM_SMEM (2 * STAGE)

__global__ __launch_bounds__(256) void gemm_mma_kernel(
    int N,
    const __nv_bfloat16* __restrict__ Ah, const __nv_bfloat16* __restrict__ Al,
    const __nv_bfloat16* __restrict__ Bh, const __nv_bfloat16* __restrict__ Bl,
    const float* __restrict__ bias, float* __restrict__ C)
{
    extern __shared__ char gsm[];
    const uint32_t sb = smem_to_u32(gsm);
    const int tid = threadIdx.x;
    const int w = tid >> 5, l = tid & 31;
    const int warp_m = w >> 2, warp_n = w & 3;
    const int bx = blockIdx.x, by = blockIdx.y;

    const __nv_bfloat16* srcs[4] = {
        Ah + (size_t)(by * 128) * GK, Al + (size_t)(by * 128) * GK,
        Bh + (size_t)(bx * 128) * GK, Bl + (size_t)(bx * 128) * GK };

    float acc[4][4][4];
    #pragma unroll
    for (int nt = 0; nt < 4; nt++) {
        const int n = bx * 128 + warp_n * 32 + nt * 8 + ((l & 3) << 1);
        const float b0 = bias[n], b1 = bias[n + 1];
        #pragma unroll
        for (int mt = 0; mt < 4; mt++) {
            acc[mt][nt][0] = b0; acc[mt][nt][1] = b1;
            acc[mt][nt][2] = b0; acc[mt][nt][3] = b1;
        }
    }

    auto load_chunk = [&](int kt) {
        const uint32_t st = sb + (kt & 1) * STAGE;
        const size_t kofs = (size_t)kt * GBK;
        #pragma unroll
        for (int a = 0; a < 4; a++) {
            const char* g = (const char*)(srcs[a] + kofs);
            #pragma unroll
            for (int j = 0; j < 4; j++) {
                const int u = tid + 256 * j;
                const int r = u >> 3;
                const int cu = u & 7;
                const uint32_t off = r * 128 + ((cu ^ (r & 7)) << 4);
                cp_async16(st + a * TBYTES + off,
                           g + (size_t)r * (GK * 2) + (cu << 4));
            }
        }
        CP_COMMIT();
    };

    load_chunk(0);

    for (int kt = 0; kt < NCHUNK; kt++) {
        if (kt + 1 < NCHUNK) { load_chunk(kt + 1); CP_WAIT(1); }
        else                 { CP_WAIT(0); }
        __syncthreads();

        const uint32_t st = sb + (kt & 1) * STAGE;
        const uint32_t sAh = st, sAl = st + TBYTES;
        const uint32_t sBh = st + 2 * TBYTES, sBl = st + 3 * TBYTES;

        #pragma unroll
        for (int kk = 0; kk < 4; kk++) {
            const int kb = kk * 32;

            uint32_t ah[4][4], al[4][4];
            #pragma unroll
            for (int mt = 0; mt < 4; mt++) {
                const int row = warp_m * 64 + mt * 16 + (l & 15);
                const int bc = kb + ((l >> 4) << 4);
                const uint32_t off = row * 128 + (bc ^ ((row & 7) << 4));
                ldsm_x4(ah[mt], sAh + off);
                ldsm_x4(al[mt], sAl + off);
            }

            uint32_t bh[2][4], bl[2][4];
            #pragma unroll
            for (int np = 0; np < 2; np++) {
                const int g = l >> 3, idx = l & 7;
                const int row = warp_n * 32 + np * 16 + ((g >> 1) << 3) + idx;
                const int bc = kb + ((g & 1) << 4);
                const uint32_t off = row * 128 + (bc ^ ((row & 7) << 4));
                ldsm_x4(bh[np], sBh + off);
                ldsm_x4(bl[np], sBl + off);
            }

            #pragma unroll
            for (int mt = 0; mt < 4; mt++)
                #pragma unroll
                for (int nt = 0; nt < 4; nt++) {
                    const uint32_t* bhp = &bh[nt >> 1][(nt & 1) * 2];
                    const uint32_t* blp = &bl[nt >> 1][(nt & 1) * 2];
                    mma16816(acc[mt][nt], ah[mt], bhp);
                    mma16816(acc[mt][nt], ah[mt], blp);
                    mma16816(acc[mt][nt], al[mt], bhp);
                }
        }
        __syncthreads();
    }

    #pragma unroll
    for (int mt = 0; mt < 4; mt++) {
        const int m = by * 128 + warp_m * 64 + mt * 16 + (l >> 2);
        float* c0 = C + (size_t)m * N + bx * 128 + warp_n * 32 + ((l & 3) << 1);
        #pragma unroll
        for (int nt = 0; nt < 4; nt++) {
            float2 v0 = make_float2(acc[mt][nt][0], acc[mt][nt][1]);
            float2 v1 = make_float2(acc[mt][nt][2], acc[mt][nt][3]);
            *(float2*)(c0 + nt * 8) = v0;
            *(float2*)(c0 + (size_t)8 * N + nt * 8) = v1;
        }
    }
}

// ---------------------------------------------------------------------------
// Tensor-core flash attention (bf16 hi/lo 3-term, online softmax in exp2 domain)
// Block: one (b, h, 128-row Q tile). 256 threads (8 warps). K-tiles of 32.
// ---------------------------------------------------------------------------
#define ATQ 128
#define AKT 32
#define ANT (S_LEN / AKT)      // 64 tiles

// smem byte offsets
#define SM_QH   0
#define SM_QL   32768
#define SM_KV   65536                 // 2 stages x 32768 (Kh|Kl|Vh|Vl x 8KB)
#define SM_S    131072                // scores fp32 [128][36]
#define SM_PH   (131072 + 18432)      // P hi bf16 [128][40]
#define SM_PL   (SM_PH + 10240)
#define SM_M    (SM_PL + 10240)
#define SM_L    (SM_M + 512)
#define SM_FAC  (SM_L + 512)
#define ATTN_SMEM (SM_FAC + 512)      // 171520 bytes

// swizzled offset for 256-byte-row tiles (cu = 16B unit index, 0..15)
#define SWZ(row, cu) ((row) * 256 + ((((cu) ^ ((row) & 7))) << 4))

__global__ __launch_bounds__(256) void attn_mma_kernel(
    const __nv_bfloat16* __restrict__ qh, const __nv_bfloat16* __restrict__ ql,
    const __nv_bfloat16* __restrict__ kh, const __nv_bfloat16* __restrict__ kl,
    const __nv_bfloat16* __restrict__ vh, const __nv_bfloat16* __restrict__ vl,
    float* __restrict__ out)
{
    extern __shared__ char gsm[];
    const uint32_t sb = smem_to_u32(gsm);
    float* Ms  = (float*)(gsm + SM_M);
    float* Ls  = (float*)(gsm + SM_L);
    float* Fs  = (float*)(gsm + SM_FAC);

    const int tid = threadIdx.x;
    const int w = tid >> 5, l = tid & 31;
    const int qt = blockIdx.x, h = blockIdx.y, b = blockIdx.z;

    const size_t head = ((size_t)(b * NH + h)) * S_LEN * DH;
    const __nv_bfloat16* Qh_g = qh + head + (size_t)qt * ATQ * DH;
    const __nv_bfloat16* Ql_g = ql + head + (size_t)qt * ATQ * DH;

    // ---- prologue: load Q (both tiles) + KV(0) as group 0; KV(1) as group 1
    auto load_kv = [&](int t) {
        const uint32_t st = sb + SM_KV + (t & 1) * 32768;
        const size_t base = head + (size_t)t * AKT * DH;
        const __nv_bfloat16* srcs[4] = {kh + base, kl + base, vh + base, vl + base};
        #pragma unroll
        for (int a = 0; a < 4; a++) {
            #pragma unroll
            for (int j = 0; j < 2; j++) {
                const int u = tid + 256 * j;       // 512 16B units per tile
                const int row = u >> 4, cu = u & 15;
                cp_async16(st + a * 8192 + SWZ(row, cu),
                           (const char*)srcs[a] + (size_t)row * 256 + cu * 16);
            }
        }
        CP_COMMIT();
    };

    #pragma unroll
    for (int j = 0; j < 8; j++) {
        const int u = tid + 256 * j;               // 2048 units per Q tile
        const int row = u >> 4, cu = u & 15;
        cp_async16(sb + SM_QH + SWZ(row, cu),
                   (const char*)Qh_g + (size_t)row * 256 + cu * 16);
        cp_async16(sb + SM_QL + SWZ(row, cu),
                   (const char*)Ql_g + (size_t)row * 256 + cu * 16);
    }
    load_kv(0);          // commits group containing Q + KV0
    load_kv(1);

    if (tid < ATQ) { Ms[tid] = -1e9f; Ls[tid] = 0.f; }

    float O[4][4][4];
    #pragma unroll
    for (int mt = 0; mt < 4; mt++)
        #pragma unroll
        for (int nt = 0; nt < 4; nt++)
            #pragma unroll
            for (int c = 0; c < 4; c++) O[mt][nt][c] = 0.f;

    // warp roles
    const int qk_wm = w >> 1, qk_wn = w & 1;       // 4x2 over (128, 32)
    const int pv_wm = w >> 2, pv_wn = w & 3;       // 2x4 over (128, 128)

    for (int t = 0; t < ANT; t++) {
        if (t < ANT - 2) { CP_WAIT(1); } else { CP_WAIT(0); }
        __syncthreads();

        const uint32_t stg = sb + SM_KV + (t & 1) * 32768;

        // ---- QK: S(128x32) = Q * K^T, 3 terms --------------------------
        {
            float sacc[2][2][4];
            #pragma unroll
            for (int mt = 0; mt < 2; mt++)
                #pragma unroll
                for (int nt = 0; nt < 2; nt++)
                    #pragma unroll
                    for (int c = 0; c < 4; c++) sacc[mt][nt][c] = 0.f;

            #pragma unroll
            for (int kk = 0; kk < 8; kk++) {
                uint32_t qhf[2][4], qlf[2][4];
                #pragma unroll
                for (int mt = 0; mt < 2; mt++) {
                    const int row = qk_wm * 32 + mt * 16 + (l & 15);
                    const int cu = kk * 2 + (l >> 4);
                    const uint32_t off = SWZ(row, cu);
                    ldsm_x4(qhf[mt], sb + SM_QH + off);
                    ldsm_x4(qlf[mt], sb + SM_QL + off);
                }
                const int g = l >> 3, idx = l & 7;
                const int krow = qk_wn * 16 + ((g >> 1) << 3) + idx;
                const int bcu = kk * 2 + (g & 1);
                const uint32_t offb = SWZ(krow, bcu);
                uint32_t khf[4], klf[4];
                ldsm_x4(khf, stg + offb);            // Kh at stage+0
                ldsm_x4(klf, stg + 8192 + offb);     // Kl
                #pragma unroll
                for (int mt = 0; mt < 2; mt++)
                    #pragma unroll
                    for (int nt = 0; nt < 2; nt++) {
                        mma16816(sacc[mt][nt], qhf[mt], &khf[nt * 2]);
                        mma16816(sacc[mt][nt], qhf[mt], &klf[nt * 2]);
                        mma16816(sacc[mt][nt], qlf[mt], &khf[nt * 2]);
                    }
            }
            float* S = (float*)(gsm + SM_S);
            #pragma unroll
            for (int mt = 0; mt < 2; mt++) {
                const int row = qk_wm * 32 + mt * 16 + (l >> 2);
                #pragma unroll
                for (int nt = 0; nt < 2; nt++) {
                    const int col = qk_wn * 16 + nt * 8 + ((l & 3) << 1);
                    S[row * 36 + col]       = sacc[mt][nt][0];
                    S[row * 36 + col + 1]   = sacc[mt][nt][1];
                    S[(row + 8) * 36 + col]     = sacc[mt][nt][2];
                    S[(row + 8) * 36 + col + 1] = sacc[mt][nt][3];
                }
            }
        }
        __syncthreads();

        // ---- online softmax (exp2 domain), write P hi/lo ----------------
        {
            const int row = tid >> 1, sub = tid & 1;
            const float* Sp = (float*)(gsm + SM_S) + row * 36 + sub * 16;
            float v[16];
            #pragma unroll
            for (int j = 0; j < 16; j += 4) {
                float4 x = *(const float4*)(Sp + j);
                v[j] = x.x; v[j+1] = x.y; v[j+2] = x.z; v[j+3] = x.w;
            }
            float mx = v[0];
            #pragma unroll
            for (int j = 1; j < 16; j++) mx = fmaxf(mx, v[j]);
            mx = fmaxf(mx, __shfl_xor_sync(0xffffffffu, mx, 1));
            const float m_old = Ms[row];
            const float m_new = fmaxf(m_old, mx);
            __nv_bfloat16* Ph = (__nv_bfloat16*)(gsm + SM_PH) + row * 40 + sub * 16;
            __nv_bfloat16* Pl = (__nv_bfloat16*)(gsm + SM_PL) + row * 40 + sub * 16;
            float sum = 0.f;
            #pragma unroll
            for (int j = 0; j < 16; j += 2) {
                float p0 = exp2_fast(v[j]     - m_new);
                float p1 = exp2_fast(v[j + 1] - m_new);
                sum += p0 + p1;
                __nv_bfloat162 h2;
                h2.x = __float2bfloat16(p0);
                h2.y = __float2bfloat16(p1);
                __nv_bfloat162 l2;
                l2.x = __float2bfloat16(p0 - __bfloat162float(h2.x));
                l2.y = __float2bfloat16(p1 - __bfloat162float(h2.y));
                *(__nv_bfloat162*)(Ph + j) = h2;
                *(__nv_bfloat162*)(Pl + j) = l2;
            }
            sum += __shfl_xor_sync(0xffffffffu, sum, 1);
            if (sub == 0) {
                const float f = exp2_fast(m_old - m_new);
                Ls[row] = Ls[row] * f + sum;
                Ms[row] = m_new;
                Fs[row] = f;
            }
        }
        __syncthreads();

        // ---- PV: O = O*fac + P * V, 3 terms ------------------------------
        {
            #pragma unroll
            for (int mt = 0; mt < 4; mt++) {
                const int r0 = pv_wm * 64 + mt * 16 + (l >> 2);
                const float f0 = Fs[r0], f1 = Fs[r0 + 8];
                #pragma unroll
                for (int nt = 0; nt < 4; nt++) {
                    O[mt][nt][0] *= f0; O[mt][nt][1] *= f0;
                    O[mt][nt][2] *= f1; O[mt][nt][3] *= f1;
                }
            }
            const uint32_t sVh = stg + 16384, sVl = stg + 24576;
            #pragma unroll
            for (int kk = 0; kk < 2; kk++) {
                uint32_t pah[4][4], pal[4][4];
                #pragma unroll
                for (int mt = 0; mt < 4; mt++) {
                    const int row = pv_wm * 64 + mt * 16 + (l & 15);
                    const uint32_t ao = row * 80 + kk * 32 + ((l >> 4) << 4);
                    ldsm_x4(pah[mt], sb + SM_PH + ao);
                    ldsm_x4(pal[mt], sb + SM_PL + ao);
                }
                uint32_t vbh[2][4], vbl[2][4];
                #pragma unroll
                for (int np = 0; np < 2; np++) {
                    const int mat = l >> 3, idx = l & 7;
                    const int key = kk * 16 + ((mat & 1) << 3) + idx;
                    const int cu = pv_wn * 4 + np * 2 + (mat >> 1);
                    const uint32_t off = SWZ(key, cu);
                    ldsm_x4_t(vbh[np], sVh + off);
                    ldsm_x4_t(vbl[np], sVl + off);
                }
                #pragma unroll
                for (int mt = 0; mt < 4; mt++)
                    #pragma unroll
                    for (int nt = 0; nt < 4; nt++) {
                        const uint32_t* bh = &vbh[nt >> 1][(nt & 1) * 2];
                        const uint32_t* bl = &vbl[nt >> 1][(nt & 1) * 2];
                        mma16816(O[mt][nt], pah[mt], bh);
                        mma16816(O[mt][nt], pah[mt], bl);
                        mma16816(O[mt][nt], pal[mt], bh);
                    }
            }
        }
        __syncthreads();

        if (t + 2 < ANT) load_kv(t + 2);
    }

    // ---- epilogue: normalize by 1/l, store to out[b, s, h*128 + d] -------
    #pragma unroll
    for (int mt = 0; mt < 4; mt++) {
        const int r0 = pv_wm * 64 + mt * 16 + (l >> 2);
        const float inv0 = 1.f / Ls[r0];
        const float inv1 = 1.f / Ls[r0 + 8];
        const size_t s0 = (size_t)(b * S_LEN + qt * ATQ + r0) * EMB + h * DH;
        #pragma unroll
        for (int nt = 0; nt < 4; nt++) {
            const int col = pv_wn * 32 + nt * 8 + ((l & 3) << 1);
            *(float2*)(out + s0 + col) =
                make_float2(O[mt][nt][0] * inv0, O[mt][nt][1] * inv0);
            *(float2*)(out + s0 + (size_t)8 * EMB + col) =
                make_float2(O[mt][nt][2] * inv1, O[mt][nt][3] * inv1);
        }
    }
}

// ---------------------------------------------------------------------------
extern "C" void kernel_launch(void* const* d_in, const int* in_sizes, int n_in,
                              void* d_out, int out_size)
{
    (void)in_sizes; (void)n_in; (void)out_size;
    const float* x    = (const float*)d_in[0];
    const float* Wqkv = (const float*)d_in[1];
    const float* bqkv = (const float*)d_in[2];
    const float* Wout = (const float*)d_in[3];
    const float* bout = (const float*)d_in[4];
    float* out = (float*)d_out;

    float *qkv = nullptr, *attn = nullptr;
    __nv_bfloat16 *ah, *al, *wqh, *wql, *woh, *wol;
    __nv_bfloat16 *qhp, *qlp, *khp, *klp, *vhp, *vlp;
    cudaGetSymbolAddress((void**)&qkv, g_qkv);
    cudaGetSymbolAddress((void**)&attn, g_attn);
    cudaGetSymbolAddress((void**)&ah, g_ah);
    cudaGetSymbolAddress((void**)&al, g_al);
    cudaGetSymbolAddress((void**)&wqh, g_wqh);
    cudaGetSymbolAddress((void**)&wql, g_wql);
    cudaGetSymbolAddress((void**)&woh, g_woh);
    cudaGetSymbolAddress((void**)&wol, g_wol);
    cudaGetSymbolAddress((void**)&qhp, g_qh);
    cudaGetSymbolAddress((void**)&qlp, g_ql);
    cudaGetSymbolAddress((void**)&khp, g_kh);
    cudaGetSymbolAddress((void**)&klp, g_kl);
    cudaGetSymbolAddress((void**)&vhp, g_vh);
    cudaGetSymbolAddress((void**)&vlp, g_vl);

    cudaFuncSetAttribute(gemm_mma_kernel,
                         cudaFuncAttributeMaxDynamicSharedMemorySize, GEMM_SMEM);
    cudaFuncSetAttribute(attn_mma_kernel,
                         cudaFuncAttributeMaxDynamicSharedMemorySize, ATTN_SMEM);

    // 0) conversions
    split_kernel<<<2048, 256>>>(x, ah, al, MROWS * EMB);
    transpose_split_kernel<<<dim3((3 * EMB) / 32, GK / 32), dim3(32, 8)>>>(
        Wqkv, wqh, wql, GK, 3 * EMB);
    transpose_split_kernel<<<dim3(EMB / 32, GK / 32), dim3(32, 8)>>>(
        Wout, woh, wol, GK, EMB);

    // 1) qkv = x @ W_qkv + b_qkv
    gemm_mma_kernel<<<dim3((3 * EMB) / 128, MROWS / 128), 256, GEMM_SMEM>>>(
        3 * EMB, ah, al, wqh, wql, bqkv, qkv);

    // 2) per-head hi/lo split (Q pre-scaled into exp2 domain)
    qkv_split_kernel<<<2048, 256>>>(qkv);

    // 3) tensor-core attention
    attn_mma_kernel<<<dim3(S_LEN / ATQ, NH, BATCH), 256, ATTN_SMEM>>>(
        qhp, qlp, khp, klp, vhp, vlp, attn);

    // 4) out = attn @ W_out + b_out
    split_kernel<<<2048, 256>>>(attn, ah, al, MROWS * EMB);
    gemm_mma_kernel<<<dim3(EMB / 128, MROWS / 128), 256, GEMM_SMEM>>>(
        EMB, ah, al, woh, wol, bout, out);
}

// round 5
// speedup vs baseline: 3.3350x; 1.0027x over previous
#include <cuda_runtime.h>
#include <cuda_bf16.h>
#include <cstdint>

#define S_LEN 2048
#define EMB   2048
#define NH    16
#define DH    128
#define BATCH 2
#define MROWS (BATCH * S_LEN)   // 4096
#define GK    2048              // K for both projection GEMMs

// ---------------------------------------------------------------------------
// Device scratch (no cudaMalloc allowed)
// ---------------------------------------------------------------------------
__device__ __nv_bfloat16 g_ah[(size_t)MROWS * GK];        // A hi (x, then attn-out)
__device__ __nv_bfloat16 g_al[(size_t)MROWS * GK];        // A lo
__device__ __nv_bfloat16 g_wqh[(size_t)(3 * EMB) * GK];
__device__ __nv_bfloat16 g_wql[(size_t)(3 * EMB) * GK];
__device__ __nv_bfloat16 g_woh[(size_t)EMB * GK];
__device__ __nv_bfloat16 g_wol[(size_t)EMB * GK];
// per-head Q/K/V hi/lo, layout [B, H, S, DH]
#define QKV_ELEMS ((size_t)BATCH * NH * S_LEN * DH)
__device__ __nv_bfloat16 g_qh[QKV_ELEMS];
__device__ __nv_bfloat16 g_ql[QKV_ELEMS];
__device__ __nv_bfloat16 g_kh[QKV_ELEMS];
__device__ __nv_bfloat16 g_kl[QKV_ELEMS];
__device__ __nv_bfloat16 g_vh[QKV_ELEMS];
__device__ __nv_bfloat16 g_vl[QKV_ELEMS];

// ---------------------------------------------------------------------------
// PTX helpers (plain sm_80+ instructions only; NO 'a'-suffix features)
// ---------------------------------------------------------------------------
__device__ __forceinline__ uint32_t smem_to_u32(const void* p) {
    uint32_t a;
    asm("{ .reg .u64 t; cvta.to.shared.u64 t, %1; cvt.u32.u64 %0, t; }"
        : "=r"(a) : "l"(p));
    return a;
}

__device__ __forceinline__ void cp_async16(uint32_t saddr, const void* gaddr) {
    asm volatile("cp.async.cg.shared.global [%0], [%1], 16;"
        :: "r"(saddr), "l"(gaddr) : "memory");
}
#define CP_COMMIT() asm volatile("cp.async.commit_group;" ::: "memory")
#define CP_WAIT(n)  asm volatile("cp.async.wait_group %0;" :: "n"(n) : "memory")

__device__ __forceinline__ void ldsm_x4(uint32_t* r, uint32_t addr) {
    asm volatile("ldmatrix.sync.aligned.m8n8.x4.shared.b16 {%0,%1,%2,%3}, [%4];"
        : "=r"(r[0]), "=r"(r[1]), "=r"(r[2]), "=r"(r[3]) : "r"(addr));
}
__device__ __forceinline__ void ldsm_x4_t(uint32_t* r, uint32_t addr) {
    asm volatile("ldmatrix.sync.aligned.m8n8.x4.trans.shared.b16 {%0,%1,%2,%3}, [%4];"
        : "=r"(r[0]), "=r"(r[1]), "=r"(r[2]), "=r"(r[3]) : "r"(addr));
}

__device__ __forceinline__ void mma16816(float* d, const uint32_t* a,
                                         const uint32_t* b) {
    asm volatile(
        "mma.sync.aligned.m16n8k16.row.col.f32.bf16.bf16.f32 "
        "{%0,%1,%2,%3}, {%4,%5,%6,%7}, {%8,%9}, {%0,%1,%2,%3};"
        : "+f"(d[0]), "+f"(d[1]), "+f"(d[2]), "+f"(d[3])
        : "r"(a[0]), "r"(a[1]), "r"(a[2]), "r"(a[3]), "r"(b[0]), "r"(b[1]));
}

// Fast 2^t on FMA/ALU pipes only (no MUFU, no CVT). |rel err| < 3e-6.
__device__ __forceinline__ float exp2_fast(float t) {
    t = fmaxf(t, -126.0f);
    const float MAGIC = 12582912.0f;          // 2^23 + 2^22
    float z = t + MAGIC;
    int i = __float_as_int(z);
    float r = z - MAGIC;
    float f = t - r;                          // f in [-0.5, 0.5]
    float p = 1.3333558146e-3f;
    p = fmaf(p, f, 9.6181291076e-3f);
    p = fmaf(p, f, 5.5504108664e-2f);
    p = fmaf(p, f, 2.4022650696e-1f);
    p = fmaf(p, f, 6.9314718056e-1f);
    p = fmaf(p, f, 1.0f);
    int eb = (i + (127 - 0x4B400000)) << 23;
    return p * __int_as_float(eb);
}

__device__ __forceinline__ __nv_bfloat162 split_hi(float v0, float v1, __nv_bfloat162& lo) {
    __nv_bfloat162 h;
    h.x = __float2bfloat16(v0);
    h.y = __float2bfloat16(v1);
    lo.x = __float2bfloat16(v0 - __bfloat162float(h.x));
    lo.y = __float2bfloat16(v1 - __bfloat162float(h.y));
    return h;
}

// ---------------------------------------------------------------------------
// Conversion kernels
// ---------------------------------------------------------------------------
__global__ __launch_bounds__(256) void split_kernel(
    const float* __restrict__ in, __nv_bfloat16* __restrict__ hi,
    __nv_bfloat16* __restrict__ lo, int n)
{
    int i = blockIdx.x * blockDim.x + threadIdx.x;
    int stride = gridDim.x * blockDim.x;
    for (; i < n; i += stride) {
        float v = in[i];
        __nv_bfloat16 h = __float2bfloat16(v);
        hi[i] = h;
        lo[i] = __float2bfloat16(v - __bfloat162float(h));
    }
}

// W[K,N] row-major -> T[N,K] bf16 hi/lo
__global__ __launch_bounds__(256) void transpose_split_kernel(
    const float* __restrict__ W, __nv_bfloat16* __restrict__ Th,
    __nv_bfloat16* __restrict__ Tl, int K, int N)
{
    __shared__ float t[32][33];
    const int nb = blockIdx.x * 32;
    const int kb = blockIdx.y * 32;
    const int x = threadIdx.x, y = threadIdx.y;   // block (32,8)
    #pragma unroll
    for (int j = 0; j < 32; j += 8)
        t[y + j][x] = W[(size_t)(kb + y + j) * N + nb + x];
    __syncthreads();
    #pragma unroll
    for (int j = 0; j < 32; j += 8) {
        float v = t[x][y + j];
        __nv_bfloat16 h = __float2bfloat16(v);
        size_t o = (size_t)(nb + y + j) * K + kb + x;
        Th[o] = h;
        Tl[o] = __float2bfloat16(v - __bfloat162float(h));
    }
}

// ---------------------------------------------------------------------------
// Shared HMMA mainloop (3-term hi/lo). Block tile 128x128, 8 warps, K-chunk 64.
// Computes acc[4][4][4] for this block; caller provides epilogue.
// ---------------------------------------------------------------------------
#define GBK   64
#define NCHUNK (GK / GBK)
#define TBYTES 16384
#define STAGE  (4 * TBYTES)
#define GEMM_SMEM (2 * STAGE)

template <typename Epilogue>
__device__ __forceinline__ void gemm_mainloop(
    char* gsm,
    const __nv_bfloat16* __restrict__ Ah, const __nv_bfloat16* __restrict__ Al,
    const __nv_bfloat16* __restrict__ Bh, const __nv_bfloat16* __restrict__ Bl,
    const float* __restrict__ bias, int bx, int by, Epilogue epi)
{
    const uint32_t sb = smem_to_u32(gsm);
    const int tid = threadIdx.x;
    const int w = tid >> 5, l = tid & 31;
    const int warp_m = w >> 2, warp_n = w & 3;

    const __nv_bfloat16* srcs[4] = {
        Ah + (size_t)(by * 128) * GK, Al + (size_t)(by * 128) * GK,
        Bh + (size_t)(bx * 128) * GK, Bl + (size_t)(bx * 128) * GK };

    float acc[4][4][4];
    #pragma unroll
    for (int nt = 0; nt < 4; nt++) {
        const int n = bx * 128 + warp_n * 32 + nt * 8 + ((l & 3) << 1);
        const float b0 = bias[n], b1 = bias[n + 1];
        #pragma unroll
        for (int mt = 0; mt < 4; mt++) {
            acc[mt][nt][0] = b0; acc[mt][nt][1] = b1;
            acc[mt][nt][2] = b0; acc[mt][nt][3] = b1;
        }
    }

    auto load_chunk = [&](int kt) {
        const uint32_t st = sb + (kt & 1) * STAGE;
        const size_t kofs = (size_t)kt * GBK;
        #pragma unroll
        for (int a = 0; a < 4; a++) {
            const char* g = (const char*)(srcs[a] + kofs);
            #pragma unroll
            for (int j = 0; j < 4; j++) {
                const int u = tid + 256 * j;
                const int r = u >> 3;
                const int cu = u & 7;
                const uint32_t off = r * 128 + ((cu ^ (r & 7)) << 4);
                cp_async16(st + a * TBYTES + off,
                           g + (size_t)r * (GK * 2) + (cu << 4));
            }
        }
        CP_COMMIT();
    };

    load_chunk(0);

    for (int kt = 0; kt < NCHUNK; kt++) {
        if (kt + 1 < NCHUNK) { load_chunk(kt + 1); CP_WAIT(1); }
        else                 { CP_WAIT(0); }
        __syncthreads();

        const uint32_t st = sb + (kt & 1) * STAGE;
        const uint32_t sAh = st, sAl = st + TBYTES;
        const uint32_t sBh = st + 2 * TBYTES, sBl = st + 3 * TBYTES;

        #pragma unroll
        for (int kk = 0; kk < 4; kk++) {
            const int kb = kk * 32;

            uint32_t ah[4][4], al[4][4];
            #pragma unroll
            for (int mt = 0; mt < 4; mt++) {
                const int row = warp_m * 64 + mt * 16 + (l & 15);
                const int bc = kb + ((l >> 4) << 4);
                const uint32_t off = row * 128 + (bc ^ ((row & 7) << 4));
                ldsm_x4(ah[mt], sAh + off);
                ldsm_x4(al[mt], sAl + off);
            }

            uint32_t bh[2][4], bl[2][4];
            #pragma unroll
            for (int np = 0; np < 2; np++) {
                const int g = l >> 3, idx = l & 7;
                const int row = warp_n * 32 + np * 16 + ((g >> 1) << 3) + idx;
                const int bc = kb + ((g & 1) << 4);
                const uint32_t off = row * 128 + (bc ^ ((row & 7) << 4));
                ldsm_x4(bh[np], sBh + off);
                ldsm_x4(bl[np], sBl + off);
            }

            #pragma unroll
            for (int mt = 0; mt < 4; mt++)
                #pragma unroll
                for (int nt = 0; nt < 4; nt++) {
                    const uint32_t* bhp = &bh[nt >> 1][(nt & 1) * 2];
                    const uint32_t* blp = &bl[nt >> 1][(nt & 1) * 2];
                    mma16816(acc[mt][nt], ah[mt], bhp);
                    mma16816(acc[mt][nt], ah[mt], blp);
                    mma16816(acc[mt][nt], al[mt], bhp);
                }
        }
        __syncthreads();
    }

    epi(acc, warp_m, warp_n, l);
}

// GEMM2: plain fp32 output C = A*B^T + bias
__global__ __launch_bounds__(256) void gemm_mma_kernel(
    int N,
    const __nv_bfloat16* __restrict__ Ah, const __nv_bfloat16* __restrict__ Al,
    const __nv_bfloat16* __restrict__ Bh, const __nv_bfloat16* __restrict__ Bl,
    const float* __restrict__ bias, float* __restrict__ C)
{
    extern __shared__ char gsm[];
    const int bx = blockIdx.x, by = blockIdx.y;
    gemm_mainloop(gsm, Ah, Al, Bh, Bl, bias, bx, by,
        [&](float acc[4][4][4], int warp_m, int warp_n, int l) {
            #pragma unroll
            for (int mt = 0; mt < 4; mt++) {
                const int m = by * 128 + warp_m * 64 + mt * 16 + (l >> 2);
                float* c0 = C + (size_t)m * N + bx * 128 + warp_n * 32 + ((l & 3) << 1);
                #pragma unroll
                for (int nt = 0; nt < 4; nt++) {
                    *(float2*)(c0 + nt * 8) =
                        make_float2(acc[mt][nt][0], acc[mt][nt][1]);
                    *(float2*)(c0 + (size_t)8 * N + nt * 8) =
                        make_float2(acc[mt][nt][2], acc[mt][nt][3]);
                }
            }
        });
}

// GEMM1 fused: writes per-head Q/K/V hi/lo bf16 directly (no fp32 qkv).
// Each 128-col tile bx lies wholly in one region: region = bx%3 (q/k/v), head = bx/3.
// Q gets the log2(e)/sqrt(dh) scale (applied after bias, matching reference).
__global__ __launch_bounds__(256) void gemm_qkv_kernel(
    const __nv_bfloat16* __restrict__ Ah, const __nv_bfloat16* __restrict__ Al,
    const __nv_bfloat16* __restrict__ Bh, const __nv_bfloat16* __restrict__ Bl,
    const float* __restrict__ bias)
{
    extern __shared__ char gsm[];
    const int bx = blockIdx.x, by = blockIdx.y;
    const int region = bx % 3;        // 0=q, 1=k, 2=v
    const int head   = bx / 3;
    __nv_bfloat16* H = (region == 0) ? g_qh : (region == 1) ? g_kh : g_vh;
    __nv_bfloat16* L = (region == 0) ? g_ql : (region == 1) ? g_kl : g_vl;
    const float scl = (region == 0) ? 0.12751744f : 1.0f;  // log2(e)/sqrt(128)

    gemm_mainloop(gsm, Ah, Al, Bh, Bl, bias, bx, by,
        [&](float acc[4][4][4], int warp_m, int warp_n, int l) {
            #pragma unroll
            for (int mt = 0; mt < 4; mt++) {
                const int m = by * 128 + warp_m * 64 + mt * 16 + (l >> 2);
                const int b = m >> 11, s = m & (S_LEN - 1);
                const size_t base =
                    (((size_t)(b * NH + head)) * S_LEN + s) * DH;
                #pragma unroll
                for (int nt = 0; nt < 4; nt++) {
                    const int d = warp_n * 32 + nt * 8 + ((l & 3) << 1);
                    __nv_bfloat162 lo0, lo1;
                    __nv_bfloat162 h0 = split_hi(acc[mt][nt][0] * scl,
                                                 acc[mt][nt][1] * scl, lo0);
                    __nv_bfloat162 h1 = split_hi(acc[mt][nt][2] * scl,
                                                 acc[mt][nt][3] * scl, lo1);
                    *(__nv_bfloat162*)(H + base + d) = h0;
                    *(__nv_bfloat162*)(L + base + d) = lo0;
                    *(__nv_bfloat162*)(H + base + (size_t)8 * DH + d) = h1;
                    *(__nv_bfloat162*)(L + base + (size_t)8 * DH + d) = lo1;
                }
            }
        });
}

// ---------------------------------------------------------------------------
// Tensor-core flash attention (bf16 hi/lo 3-term, online softmax in exp2 domain)
// Epilogue writes GEMM2's A operand (hi/lo bf16) directly.
// ---------------------------------------------------------------------------
#define ATQ 128
#define AKT 32
#define ANT (S_LEN / AKT)

#define SM_QH   0
#define SM_QL   32768
#define SM_KV   65536
#define SM_S    131072
#define SM_PH   (131072 + 18432)
#define SM_PL   (SM_PH + 10240)
#define SM_M    (SM_PL + 10240)
#define SM_L    (SM_M + 512)
#define SM_FAC  (SM_L + 512)
#define ATTN_SMEM (SM_FAC + 512)

#define SWZ(row, cu) ((row) * 256 + ((((cu) ^ ((row) & 7))) << 4))

__global__ __launch_bounds__(256) void attn_mma_kernel(
    const __nv_bfloat16* __restrict__ qh, const __nv_bfloat16* __restrict__ ql,
    const __nv_bfloat16* __restrict__ kh, const __nv_bfloat16* __restrict__ kl,
    const __nv_bfloat16* __restrict__ vh, const __nv_bfloat16* __restrict__ vl,
    __nv_bfloat16* __restrict__ outH, __nv_bfloat16* __restrict__ outL)
{
    extern __shared__ char gsm[];
    const uint32_t sb = smem_to_u32(gsm);
    float* Ms  = (float*)(gsm + SM_M);
    float* Ls  = (float*)(gsm + SM_L);
    float* Fs  = (float*)(gsm + SM_FAC);

    const int tid = threadIdx.x;
    const int w = tid >> 5, l = tid & 31;
    const int qt = blockIdx.x, h = blockIdx.y, b = blockIdx.z;

    const size_t head = ((size_t)(b * NH + h)) * S_LEN * DH;
    const __nv_bfloat16* Qh_g = qh + head + (size_t)qt * ATQ * DH;
    const __nv_bfloat16* Ql_g = ql + head + (size_t)qt * ATQ * DH;

    auto load_kv = [&](int t) {
        const uint32_t st = sb + SM_KV + (t & 1) * 32768;
        const size_t base = head + (size_t)t * AKT * DH;
        const __nv_bfloat16* srcs[4] = {kh + base, kl + base, vh + base, vl + base};
        #pragma unroll
        for (int a = 0; a < 4; a++) {
            #pragma unroll
            for (int j = 0; j < 2; j++) {
                const int u = tid + 256 * j;
                const int row = u >> 4, cu = u & 15;
                cp_async16(st + a * 8192 + SWZ(row, cu),
                           (const char*)srcs[a] + (size_t)row * 256 + cu * 16);
            }
        }
        CP_COMMIT();
    };

    #pragma unroll
    for (int j = 0; j < 8; j++) {
        const int u = tid + 256 * j;
        const int row = u >> 4, cu = u & 15;
        cp_async16(sb + SM_QH + SWZ(row, cu),
                   (const char*)Qh_g + (size_t)row * 256 + cu * 16);
        cp_async16(sb + SM_QL + SWZ(row, cu),
                   (const char*)Ql_g + (size_t)row * 256 + cu * 16);
    }
    load_kv(0);
    load_kv(1);

    if (tid < ATQ) { Ms[tid] = -1e9f; Ls[tid] = 0.f; }

    float O[4][4][4];
    #pragma unroll
    for (int mt = 0; mt < 4; mt++)
        #pragma unroll
        for (int nt = 0; nt < 4; nt++)
            #pragma unroll
            for (int c = 0; c < 4; c++) O[mt][nt][c] = 0.f;

    const int qk_wm = w >> 1, qk_wn = w & 1;
    const int pv_wm = w >> 2, pv_wn = w & 3;

    for (int t = 0; t < ANT; t++) {
        if (t < ANT - 2) { CP_WAIT(1); } else { CP_WAIT(0); }
        __syncthreads();

        const uint32_t stg = sb + SM_KV + (t & 1) * 32768;

        // ---- QK ----------------------------------------------------------
        {
            float sacc[2][2][4];
            #pragma unroll
            for (int mt = 0; mt < 2; mt++)
                #pragma unroll
                for (int nt = 0; nt < 2; nt++)
                    #pragma unroll
                    for (int c = 0; c < 4; c++) sacc[mt][nt][c] = 0.f;

            #pragma unroll
            for (int kk = 0; kk < 8; kk++) {
                uint32_t qhf[2][4], qlf[2][4];
                #pragma unroll
                for (int mt = 0; mt < 2; mt++) {
                    const int row = qk_wm * 32 + mt * 16 + (l & 15);
                    const int cu = kk * 2 + (l >> 4);
                    const uint32_t off = SWZ(row, cu);
                    ldsm_x4(qhf[mt], sb + SM_QH + off);
                    ldsm_x4(qlf[mt], sb + SM_QL + off);
                }
                const int g = l >> 3, idx = l & 7;
                const int krow = qk_wn * 16 + ((g >> 1) << 3) + idx;
                const int bcu = kk * 2 + (g & 1);
                const uint32_t offb = SWZ(krow, bcu);
                uint32_t khf[4], klf[4];
                ldsm_x4(khf, stg + offb);
                ldsm_x4(klf, stg + 8192 + offb);
                #pragma unroll
                for (int mt = 0; mt < 2; mt++)
                    #pragma unroll
                    for (int nt = 0; nt < 2; nt++) {
                        mma16816(sacc[mt][nt], qhf[mt], &khf[nt * 2]);
                        mma16816(sacc[mt][nt], qhf[mt], &klf[nt * 2]);
                        mma16816(sacc[mt][nt], qlf[mt], &khf[nt * 2]);
                    }
            }
            float* S = (float*)(gsm + SM_S);
            #pragma unroll
            for (int mt = 0; mt < 2; mt++) {
                const int row = qk_wm * 32 + mt * 16 + (l >> 2);
                #pragma unroll
                for (int nt = 0; nt < 2; nt++) {
                    const int col = qk_wn * 16 + nt * 8 + ((l & 3) << 1);
                    S[row * 36 + col]       = sacc[mt][nt][0];
                    S[row * 36 + col + 1]   = sacc[mt][nt][1];
                    S[(row + 8) * 36 + col]     = sacc[mt][nt][2];
                    S[(row + 8) * 36 + col + 1] = sacc[mt][nt][3];
                }
            }
        }
        __syncthreads();

        // ---- online softmax ----------------------------------------------
        {
            const int row = tid >> 1, sub = tid & 1;
            const float* Sp = (float*)(gsm + SM_S) + row * 36 + sub * 16;
            float v[16];
            #pragma unroll
            for (int j = 0; j < 16; j += 4) {
                float4 x = *(const float4*)(Sp + j);
                v[j] = x.x; v[j+1] = x.y; v[j+2] = x.z; v[j+3] = x.w;
            }
            float mx = v[0];
            #pragma unroll
            for (int j = 1; j < 16; j++) mx = fmaxf(mx, v[j]);
            mx = fmaxf(mx, __shfl_xor_sync(0xffffffffu, mx, 1));
            const float m_old = Ms[row];
            const float m_new = fmaxf(m_old, mx);
            __nv_bfloat16* Ph = (__nv_bfloat16*)(gsm + SM_PH) + row * 40 + sub * 16;
            __nv_bfloat16* Pl = (__nv_bfloat16*)(gsm + SM_PL) + row * 40 + sub * 16;
            float sum = 0.f;
            #pragma unroll
            for (int j = 0; j < 16; j += 2) {
                float p0 = exp2_fast(v[j]     - m_new);
                float p1 = exp2_fast(v[j + 1] - m_new);
                sum += p0 + p1;
                __nv_bfloat162 l2;
                __nv_bfloat162 h2 = split_hi(p0, p1, l2);
                *(__nv_bfloat162*)(Ph + j) = h2;
                *(__nv_bfloat162*)(Pl + j) = l2;
            }
            sum += __shfl_xor_sync(0xffffffffu, sum, 1);
            if (sub == 0) {
                const float f = exp2_fast(m_old - m_new);
                Ls[row] = Ls[row] * f + sum;
                Ms[row] = m_new;
                Fs[row] = f;
            }
        }
        __syncthreads();

        // ---- PV ------------------------------------------------------------
        {
            #pragma unroll
            for (int mt = 0; mt < 4; mt++) {
                const int r0 = pv_wm * 64 + mt * 16 + (l >> 2);
                const float f0 = Fs[r0], f1 = Fs[r0 + 8];
                #pragma unroll
                for (int nt = 0; nt < 4; nt++) {
                    O[mt][nt][0] *= f0; O[mt][nt][1] *= f0;
                    O[mt][nt][2] *= f1; O[mt][nt][3] *= f1;
                }
            }
            const uint32_t sVh = stg + 16384, sVl = stg + 24576;
            #pragma unroll
            for (int kk = 0; kk < 2; kk++) {
                uint32_t pah[4][4], pal[4][4];
                #pragma unroll
                for (int mt = 0; mt < 4; mt++) {
                    const int row = pv_wm * 64 + mt * 16 + (l & 15);
                    const uint32_t ao = row * 80 + kk * 32 + ((l >> 4) << 4);
                    ldsm_x4(pah[mt], sb + SM_PH + ao);
                    ldsm_x4(pal[mt], sb + SM_PL + ao);
                }
                uint32_t vbh[2][4], vbl[2][4];
                #pragma unroll
                for (int np = 0; np < 2; np++) {
                    const int mat = l >> 3, idx = l & 7;
                    const int key = kk * 16 + ((mat & 1) << 3) + idx;
                    const int cu = pv_wn * 4 + np * 2 + (mat >> 1);
                    const uint32_t off = SWZ(key, cu);
                    ldsm_x4_t(vbh[np], sVh + off);
                    ldsm_x4_t(vbl[np], sVl + off);
                }
                #pragma unroll
                for (int mt = 0; mt < 4; mt++)
                    #pragma unroll
                    for (int nt = 0; nt < 4; nt++) {
                        const uint32_t* bhp = &vbh[nt >> 1][(nt & 1) * 2];
                        const uint32_t* blp = &vbl[nt >> 1][(nt & 1) * 2];
                        mma16816(O[mt][nt], pah[mt], bhp);
                        mma16816(O[mt][nt], pah[mt], blp);
                        mma16816(O[mt][nt], pal[mt], bhp);
                    }
            }
        }
        __syncthreads();

        if (t + 2 < ANT) load_kv(t + 2);
    }

    // ---- epilogue: normalize, split hi/lo, write GEMM2's A operand --------
    #pragma unroll
    for (int mt = 0; mt < 4; mt++) {
        const int r0 = pv_wm * 64 + mt * 16 + (l >> 2);
        const float inv0 = 1.f / Ls[r0];
        const float inv1 = 1.f / Ls[r0 + 8];
        const size_t s0 = (size_t)(b * S_LEN + qt * ATQ + r0) * EMB + h * DH;
        #pragma unroll
        for (int nt = 0; nt < 4; nt++) {
            const int col = pv_wn * 32 + nt * 8 + ((l & 3) << 1);
            __nv_bfloat162 lo0, lo1;
            __nv_bfloat162 h0 = split_hi(O[mt][nt][0] * inv0,
                                         O[mt][nt][1] * inv0, lo0);
            __nv_bfloat162 h1 = split_hi(O[mt][nt][2] * inv1,
                                         O[mt][nt][3] * inv1, lo1);
            *(__nv_bfloat162*)(outH + s0 + col) = h0;
            *(__nv_bfloat162*)(outL + s0 + col) = lo0;
            *(__nv_bfloat162*)(outH + s0 + (size_t)8 * EMB + col) = h1;
            *(__nv_bfloat162*)(outL + s0 + (size_t)8 * EMB + col) = lo1;
        }
    }
}

// ---------------------------------------------------------------------------
extern "C" void kernel_launch(void* const* d_in, const int* in_sizes, int n_in,
                              void* d_out, int out_size)
{
    (void)in_sizes; (void)n_in; (void)out_size;
    const float* x    = (const float*)d_in[0];
    const float* Wqkv = (const float*)d_in[1];
    const float* bqkv = (const float*)d_in[2];
    const float* Wout = (const float*)d_in[3];
    const float* bout = (const float*)d_in[4];
    float* out = (float*)d_out;

    __nv_bfloat16 *ah, *al, *wqh, *wql, *woh, *wol;
    __nv_bfloat16 *qhp, *qlp, *khp, *klp, *vhp, *vlp;
    cudaGetSymbolAddress((void**)&ah, g_ah);
    cudaGetSymbolAddress((void**)&al, g_al);
    cudaGetSymbolAddress((void**)&wqh, g_wqh);
    cudaGetSymbolAddress((void**)&wql, g_wql);
    cudaGetSymbolAddress((void**)&woh, g_woh);
    cudaGetSymbolAddress((void**)&wol, g_wol);
    cudaGetSymbolAddress((void**)&qhp, g_qh);
    cudaGetSymbolAddress((void**)&qlp, g_ql);
    cudaGetSymbolAddress((void**)&khp, g_kh);
    cudaGetSymbolAddress((void**)&klp, g_kl);
    cudaGetSymbolAddress((void**)&vhp, g_vh);
    cudaGetSymbolAddress((void**)&vlp, g_vl);

    cudaFuncSetAttribute(gemm_mma_kernel,
                         cudaFuncAttributeMaxDynamicSharedMemorySize, GEMM_SMEM);
    cudaFuncSetAttribute(gemm_qkv_kernel,
                         cudaFuncAttributeMaxDynamicSharedMemorySize, GEMM_SMEM);
    cudaFuncSetAttribute(attn_mma_kernel,
                         cudaFuncAttributeMaxDynamicSharedMemorySize, ATTN_SMEM);

    // 0) conversions (inputs only)
    split_kernel<<<2048, 256>>>(x, ah, al, MROWS * EMB);
    transpose_split_kernel<<<dim3((3 * EMB) / 32, GK / 32), dim3(32, 8)>>>(
        Wqkv, wqh, wql, GK, 3 * EMB);
    transpose_split_kernel<<<dim3(EMB / 32, GK / 32), dim3(32, 8)>>>(
        Wout, woh, wol, GK, EMB);

    // 1) qkv projection fused with per-head hi/lo split (Q pre-scaled)
    gemm_qkv_kernel<<<dim3((3 * EMB) / 128, MROWS / 128), 256, GEMM_SMEM>>>(
        ah, al, wqh, wql, bqkv);

    // 2) tensor-core attention; writes GEMM2's A (hi/lo) directly
    attn_mma_kernel<<<dim3(S_LEN / ATQ, NH, BATCH), 256, ATTN_SMEM>>>(
        qhp, qlp, khp, klp, vhp, vlp, ah, al);

    // 3) out = attn @ W_out + b_out
    gemm_mma_kernel<<<dim3(EMB / 128, MROWS / 128), 256, GEMM_SMEM>>>(
        EMB, ah, al, woh, wol, bout, out);
}

// round 6
// speedup vs baseline: 3.5079x; 1.0518x over previous
#include <cuda_runtime.h>
#include <cuda_bf16.h>
#include <cstdint>

#define S_LEN 2048
#define EMB   2048
#define NH    16
#define DH    128
#define BATCH 2
#define MROWS (BATCH * S_LEN)   // 4096
#define GK    2048              // K for both projection GEMMs

// ---------------------------------------------------------------------------
// Device scratch (no cudaMalloc allowed)
// ---------------------------------------------------------------------------
__device__ __nv_bfloat16 g_ah[(size_t)MROWS * GK];        // A hi (x, then attn-out)
__device__ __nv_bfloat16 g_al[(size_t)MROWS * GK];        // A lo
__device__ __nv_bfloat16 g_wqh[(size_t)(3 * EMB) * GK];
__device__ __nv_bfloat16 g_wql[(size_t)(3 * EMB) * GK];
__device__ __nv_bfloat16 g_woh[(size_t)EMB * GK];
__device__ __nv_bfloat16 g_wol[(size_t)EMB * GK];
// per-head Q/K/V hi/lo, layout [B, H, S, DH]
#define QKV_ELEMS ((size_t)BATCH * NH * S_LEN * DH)
__device__ __nv_bfloat16 g_qh[QKV_ELEMS];
__device__ __nv_bfloat16 g_ql[QKV_ELEMS];
__device__ __nv_bfloat16 g_kh[QKV_ELEMS];
__device__ __nv_bfloat16 g_kl[QKV_ELEMS];
__device__ __nv_bfloat16 g_vh[QKV_ELEMS];
__device__ __nv_bfloat16 g_vl[QKV_ELEMS];

// ---------------------------------------------------------------------------
// PTX helpers (plain sm_80+ instructions only)
// ---------------------------------------------------------------------------
__device__ __forceinline__ uint32_t smem_to_u32(const void* p) {
    uint32_t a;
    asm("{ .reg .u64 t; cvta.to.shared.u64 t, %1; cvt.u32.u64 %0, t; }"
        : "=r"(a) : "l"(p));
    return a;
}

__device__ __forceinline__ void cp_async16(uint32_t saddr, const void* gaddr) {
    asm volatile("cp.async.cg.shared.global [%0], [%1], 16;"
        :: "r"(saddr), "l"(gaddr) : "memory");
}
#define CP_COMMIT() asm volatile("cp.async.commit_group;" ::: "memory")
#define CP_WAIT(n)  asm volatile("cp.async.wait_group %0;" :: "n"(n) : "memory")

__device__ __forceinline__ void ldsm_x4(uint32_t* r, uint32_t addr) {
    asm volatile("ldmatrix.sync.aligned.m8n8.x4.shared.b16 {%0,%1,%2,%3}, [%4];"
        : "=r"(r[0]), "=r"(r[1]), "=r"(r[2]), "=r"(r[3]) : "r"(addr));
}
__device__ __forceinline__ void ldsm_x4_t(uint32_t* r, uint32_t addr) {
    asm volatile("ldmatrix.sync.aligned.m8n8.x4.trans.shared.b16 {%0,%1,%2,%3}, [%4];"
        : "=r"(r[0]), "=r"(r[1]), "=r"(r[2]), "=r"(r[3]) : "r"(addr));
}

__device__ __forceinline__ void mma16816(float* d, const uint32_t* a,
                                         const uint32_t* b) {
    asm volatile(
        "mma.sync.aligned.m16n8k16.row.col.f32.bf16.bf16.f32 "
        "{%0,%1,%2,%3}, {%4,%5,%6,%7}, {%8,%9}, {%0,%1,%2,%3};"
        : "+f"(d[0]), "+f"(d[1]), "+f"(d[2]), "+f"(d[3])
        : "r"(a[0]), "r"(a[1]), "r"(a[2]), "r"(a[3]), "r"(b[0]), "r"(b[1]));
}

// Fast 2^t on FMA/ALU pipes only (no MUFU, no CVT). |rel err| < 3e-6.
__device__ __forceinline__ float exp2_fast(float t) {
    t = fmaxf(t, -126.0f);
    const float MAGIC = 12582912.0f;          // 2^23 + 2^22
    float z = t + MAGIC;
    int i = __float_as_int(z);
    float r = z - MAGIC;
    float f = t - r;                          // f in [-0.5, 0.5]
    float p = 1.3333558146e-3f;
    p = fmaf(p, f, 9.6181291076e-3f);
    p = fmaf(p, f, 5.5504108664e-2f);
    p = fmaf(p, f, 2.4022650696e-1f);
    p = fmaf(p, f, 6.9314718056e-1f);
    p = fmaf(p, f, 1.0f);
    int eb = (i + (127 - 0x4B400000)) << 23;
    return p * __int_as_float(eb);
}

__device__ __forceinline__ __nv_bfloat162 split_hi(float v0, float v1, __nv_bfloat162& lo) {
    __nv_bfloat162 h;
    h.x = __float2bfloat16(v0);
    h.y = __float2bfloat16(v1);
    lo.x = __float2bfloat16(v0 - __bfloat162float(h.x));
    lo.y = __float2bfloat16(v1 - __bfloat162float(h.y));
    return h;
}
__device__ __forceinline__ uint32_t b2u(__nv_bfloat162 v) {
    return *(uint32_t*)&v;
}

// ---------------------------------------------------------------------------
// Conversion kernels
// ---------------------------------------------------------------------------
__global__ __launch_bounds__(256) void split_kernel(
    const float* __restrict__ in, __nv_bfloat16* __restrict__ hi,
    __nv_bfloat16* __restrict__ lo, int n)
{
    int i = blockIdx.x * blockDim.x + threadIdx.x;
    int stride = gridDim.x * blockDim.x;
    for (; i < n; i += stride) {
        float v = in[i];
        __nv_bfloat16 h = __float2bfloat16(v);
        hi[i] = h;
        lo[i] = __float2bfloat16(v - __bfloat162float(h));
    }
}

__global__ __launch_bounds__(256) void transpose_split_kernel(
    const float* __restrict__ W, __nv_bfloat16* __restrict__ Th,
    __nv_bfloat16* __restrict__ Tl, int K, int N)
{
    __shared__ float t[32][33];
    const int nb = blockIdx.x * 32;
    const int kb = blockIdx.y * 32;
    const int x = threadIdx.x, y = threadIdx.y;   // block (32,8)
    #pragma unroll
    for (int j = 0; j < 32; j += 8)
        t[y + j][x] = W[(size_t)(kb + y + j) * N + nb + x];
    __syncthreads();
    #pragma unroll
    for (int j = 0; j < 32; j += 8) {
        float v = t[x][y + j];
        __nv_bfloat16 h = __float2bfloat16(v);
        size_t o = (size_t)(nb + y + j) * K + kb + x;
        Th[o] = h;
        Tl[o] = __float2bfloat16(v - __bfloat162float(h));
    }
}

// ---------------------------------------------------------------------------
// Shared HMMA mainloop (3-term hi/lo). Block tile 128x128, 8 warps, K-chunk 64.
// 3-stage cp.async pipeline, ONE __syncthreads per K-chunk.
// ---------------------------------------------------------------------------
#define GBK   64
#define NCHUNK (GK / GBK)
#define TBYTES 16384
#define STAGE  (4 * TBYTES)          // 64 KB
#define GEMM_SMEM (3 * STAGE)        // 192 KB

template <typename Epilogue>
__device__ __forceinline__ void gemm_mainloop(
    char* gsm,
    const __nv_bfloat16* __restrict__ Ah, const __nv_bfloat16* __restrict__ Al,
    const __nv_bfloat16* __restrict__ Bh, const __nv_bfloat16* __restrict__ Bl,
    const float* __restrict__ bias, int bx, int by, Epilogue epi)
{
    const uint32_t sb = smem_to_u32(gsm);
    const int tid = threadIdx.x;
    const int w = tid >> 5, l = tid & 31;
    const int warp_m = w >> 2, warp_n = w & 3;

    const __nv_bfloat16* srcs[4] = {
        Ah + (size_t)(by * 128) * GK, Al + (size_t)(by * 128) * GK,
        Bh + (size_t)(bx * 128) * GK, Bl + (size_t)(bx * 128) * GK };

    float acc[4][4][4];
    #pragma unroll
    for (int nt = 0; nt < 4; nt++) {
        const int n = bx * 128 + warp_n * 32 + nt * 8 + ((l & 3) << 1);
        const float b0 = bias[n], b1 = bias[n + 1];
        #pragma unroll
        for (int mt = 0; mt < 4; mt++) {
            acc[mt][nt][0] = b0; acc[mt][nt][1] = b1;
            acc[mt][nt][2] = b0; acc[mt][nt][3] = b1;
        }
    }

    auto load_chunk = [&](int kt) {
        const uint32_t st = sb + (kt % 3) * STAGE;
        const size_t kofs = (size_t)kt * GBK;
        #pragma unroll
        for (int a = 0; a < 4; a++) {
            const char* g = (const char*)(srcs[a] + kofs);
            #pragma unroll
            for (int j = 0; j < 4; j++) {
                const int u = tid + 256 * j;
                const int r = u >> 3;
                const int cu = u & 7;
                const uint32_t off = r * 128 + ((cu ^ (r & 7)) << 4);
                cp_async16(st + a * TBYTES + off,
                           g + (size_t)r * (GK * 2) + (cu << 4));
            }
        }
        CP_COMMIT();
    };

    load_chunk(0);
    load_chunk(1);

    for (int kt = 0; kt < NCHUNK; kt++) {
        if (kt + 1 < NCHUNK) { CP_WAIT(1); } else { CP_WAIT(0); }
        __syncthreads();
        if (kt + 2 < NCHUNK) load_chunk(kt + 2);

        const uint32_t st = sb + (kt % 3) * STAGE;
        const uint32_t sAh = st, sAl = st + TBYTES;
        const uint32_t sBh = st + 2 * TBYTES, sBl = st + 3 * TBYTES;

        #pragma unroll
        for (int kk = 0; kk < 4; kk++) {
            const int kb = kk * 32;

            uint32_t ah[4][4], al[4][4];
            #pragma unroll
            for (int mt = 0; mt < 4; mt++) {
                const int row = warp_m * 64 + mt * 16 + (l & 15);
                const int bc = kb + ((l >> 4) << 4);
                const uint32_t off = row * 128 + (bc ^ ((row & 7) << 4));
                ldsm_x4(ah[mt], sAh + off);
                ldsm_x4(al[mt], sAl + off);
            }

            uint32_t bh[2][4], bl[2][4];
            #pragma unroll
            for (int np = 0; np < 2; np++) {
                const int g = l >> 3, idx = l & 7;
                const int row = warp_n * 32 + np * 16 + ((g >> 1) << 3) + idx;
                const int bc = kb + ((g & 1) << 4);
                const uint32_t off = row * 128 + (bc ^ ((row & 7) << 4));
                ldsm_x4(bh[np], sBh + off);
                ldsm_x4(bl[np], sBl + off);
            }

            #pragma unroll
            for (int mt = 0; mt < 4; mt++)
                #pragma unroll
                for (int nt = 0; nt < 4; nt++) {
                    const uint32_t* bhp = &bh[nt >> 1][(nt & 1) * 2];
                    const uint32_t* blp = &bl[nt >> 1][(nt & 1) * 2];
                    mma16816(acc[mt][nt], ah[mt], bhp);
                    mma16816(acc[mt][nt], ah[mt], blp);
                    mma16816(acc[mt][nt], al[mt], bhp);
                }
        }
    }

    epi(acc, warp_m, warp_n, l);
}

// GEMM2: plain fp32 output C = A*B^T + bias
__global__ __launch_bounds__(256) void gemm_mma_kernel(
    int N,
    const __nv_bfloat16* __restrict__ Ah, const __nv_bfloat16* __restrict__ Al,
    const __nv_bfloat16* __restrict__ Bh, const __nv_bfloat16* __restrict__ Bl,
    const float* __restrict__ bias, float* __restrict__ C)
{
    extern __shared__ char gsm[];
    const int bx = blockIdx.x, by = blockIdx.y;
    gemm_mainloop(gsm, Ah, Al, Bh, Bl, bias, bx, by,
        [&](float acc[4][4][4], int warp_m, int warp_n, int l) {
            #pragma unroll
            for (int mt = 0; mt < 4; mt++) {
                const int m = by * 128 + warp_m * 64 + mt * 16 + (l >> 2);
                float* c0 = C + (size_t)m * N + bx * 128 + warp_n * 32 + ((l & 3) << 1);
                #pragma unroll
                for (int nt = 0; nt < 4; nt++) {
                    *(float2*)(c0 + nt * 8) =
                        make_float2(acc[mt][nt][0], acc[mt][nt][1]);
                    *(float2*)(c0 + (size_t)8 * N + nt * 8) =
                        make_float2(acc[mt][nt][2], acc[mt][nt][3]);
                }
            }
        });
}

// GEMM1 fused: writes per-head Q/K/V hi/lo bf16 directly.
__global__ __launch_bounds__(256) void gemm_qkv_kernel(
    const __nv_bfloat16* __restrict__ Ah, const __nv_bfloat16* __restrict__ Al,
    const __nv_bfloat16* __restrict__ Bh, const __nv_bfloat16* __restrict__ Bl,
    const float* __restrict__ bias)
{
    extern __shared__ char gsm[];
    const int bx = blockIdx.x, by = blockIdx.y;
    const int region = bx % 3;        // 0=q, 1=k, 2=v
    const int head   = bx / 3;
    __nv_bfloat16* H = (region == 0) ? g_qh : (region == 1) ? g_kh : g_vh;
    __nv_bfloat16* L = (region == 0) ? g_ql : (region == 1) ? g_kl : g_vl;
    const float scl = (region == 0) ? 0.12751744f : 1.0f;  // log2(e)/sqrt(128)

    gemm_mainloop(gsm, Ah, Al, Bh, Bl, bias, bx, by,
        [&](float acc[4][4][4], int warp_m, int warp_n, int l) {
            #pragma unroll
            for (int mt = 0; mt < 4; mt++) {
                const int m = by * 128 + warp_m * 64 + mt * 16 + (l >> 2);
                const int b = m >> 11, s = m & (S_LEN - 1);
                const size_t base =
                    (((size_t)(b * NH + head)) * S_LEN + s) * DH;
                #pragma unroll
                for (int nt = 0; nt < 4; nt++) {
                    const int d = warp_n * 32 + nt * 8 + ((l & 3) << 1);
                    __nv_bfloat162 lo0, lo1;
                    __nv_bfloat162 h0 = split_hi(acc[mt][nt][0] * scl,
                                                 acc[mt][nt][1] * scl, lo0);
                    __nv_bfloat162 h1 = split_hi(acc[mt][nt][2] * scl,
                                                 acc[mt][nt][3] * scl, lo1);
                    *(__nv_bfloat162*)(H + base + d) = h0;
                    *(__nv_bfloat162*)(L + base + d) = lo0;
                    *(__nv_bfloat162*)(H + base + (size_t)8 * DH + d) = h1;
                    *(__nv_bfloat162*)(L + base + (size_t)8 * DH + d) = lo1;
                }
            }
        });
}

// ---------------------------------------------------------------------------
// FA2-style tensor-core attention: register-resident softmax, P never in smem.
// 8 warps; each warp owns 16 Q rows (QK 16x32, PV 16x128). One sync per tile.
// 3-stage KV pipeline. Epilogue writes GEMM2's A (hi/lo bf16) directly.
// ---------------------------------------------------------------------------
#define ATQ 128
#define AKT 32
#define ANT (S_LEN / AKT)

#define ASM_QH 0
#define ASM_QL 32768
#define ASM_KV 65536                  // 3 stages x 32768 (Kh|Kl|Vh|Vl x 8KB)
#define ATTN_SMEM (65536 + 3 * 32768) // 163840

#define SWZ(row, cu) ((row) * 256 + ((((cu) ^ ((row) & 7))) << 4))

__global__ __launch_bounds__(256) void attn_mma_kernel(
    const __nv_bfloat16* __restrict__ qh, const __nv_bfloat16* __restrict__ ql,
    const __nv_bfloat16* __restrict__ kh, const __nv_bfloat16* __restrict__ kl,
    const __nv_bfloat16* __restrict__ vh, const __nv_bfloat16* __restrict__ vl,
    __nv_bfloat16* __restrict__ outH, __nv_bfloat16* __restrict__ outL)
{
    extern __shared__ char gsm[];
    const uint32_t sb = smem_to_u32(gsm);
    const int tid = threadIdx.x;
    const int w = tid >> 5, l = tid & 31;
    const int qt = blockIdx.x, h = blockIdx.y, b = blockIdx.z;

    const size_t head = ((size_t)(b * NH + h)) * S_LEN * DH;
    const __nv_bfloat16* Qh_g = qh + head + (size_t)qt * ATQ * DH;
    const __nv_bfloat16* Ql_g = ql + head + (size_t)qt * ATQ * DH;

    auto load_kv = [&](int t) {
        const uint32_t st = sb + ASM_KV + (t % 3) * 32768;
        const size_t base = head + (size_t)t * AKT * DH;
        const __nv_bfloat16* srcs[4] = {kh + base, kl + base, vh + base, vl + base};
        #pragma unroll
        for (int a = 0; a < 4; a++) {
            #pragma unroll
            for (int j = 0; j < 2; j++) {
                const int u = tid + 256 * j;
                const int row = u >> 4, cu = u & 15;
                cp_async16(st + a * 8192 + SWZ(row, cu),
                           (const char*)srcs[a] + (size_t)row * 256 + cu * 16);
            }
        }
        CP_COMMIT();
    };

    // Q loads are committed together with KV(0) as group 0.
    #pragma unroll
    for (int j = 0; j < 8; j++) {
        const int u = tid + 256 * j;
        const int row = u >> 4, cu = u & 15;
        cp_async16(sb + ASM_QH + SWZ(row, cu),
                   (const char*)Qh_g + (size_t)row * 256 + cu * 16);
        cp_async16(sb + ASM_QL + SWZ(row, cu),
                   (const char*)Ql_g + (size_t)row * 256 + cu * 16);
    }
    load_kv(0);
    load_kv(1);

    float m0 = -1e9f, m1 = -1e9f, ls0 = 0.f, ls1 = 0.f;
    float O[16][4];
    #pragma unroll
    for (int nt = 0; nt < 16; nt++)
        #pragma unroll
        for (int c = 0; c < 4; c++) O[nt][c] = 0.f;

    for (int t = 0; t < ANT; t++) {
        if (t + 1 < ANT) { CP_WAIT(1); } else { CP_WAIT(0); }
        __syncthreads();
        if (t + 2 < ANT) load_kv(t + 2);

        const uint32_t stg = sb + ASM_KV + (t % 3) * 32768;

        // ---- QK: sacc[nt][4], warp tile 16x32 -----------------------------
        float sacc[4][4];
        #pragma unroll
        for (int nt = 0; nt < 4; nt++)
            #pragma unroll
            for (int c = 0; c < 4; c++) sacc[nt][c] = 0.f;

        #pragma unroll
        for (int kk = 0; kk < 8; kk++) {
            uint32_t qhf[4], qlf[4];
            {
                const int row = w * 16 + (l & 15);
                const int cu = kk * 2 + (l >> 4);
                const uint32_t off = SWZ(row, cu);
                ldsm_x4(qhf, sb + ASM_QH + off);
                ldsm_x4(qlf, sb + ASM_QL + off);
            }
            uint32_t khf[2][4], klf[2][4];
            #pragma unroll
            for (int np = 0; np < 2; np++) {
                const int g = l >> 3, idx = l & 7;
                const int krow = np * 16 + ((g >> 1) << 3) + idx;
                const int bcu = kk * 2 + (g & 1);
                const uint32_t off = SWZ(krow, bcu);
                ldsm_x4(khf[np], stg + off);
                ldsm_x4(klf[np], stg + 8192 + off);
            }
            #pragma unroll
            for (int nt = 0; nt < 4; nt++) {
                const uint32_t* bhp = &khf[nt >> 1][(nt & 1) * 2];
                const uint32_t* blp = &klf[nt >> 1][(nt & 1) * 2];
                mma16816(sacc[nt], qhf, bhp);
                mma16816(sacc[nt], qhf, blp);
                mma16816(sacc[nt], qlf, bhp);
            }
        }

        // ---- softmax in registers (rows r=l>>2 and r+8, quad-reduced) -----
        float mx0 = sacc[0][0], mx1 = sacc[0][2];
        #pragma unroll
        for (int nt = 0; nt < 4; nt++) {
            mx0 = fmaxf(mx0, fmaxf(sacc[nt][0], sacc[nt][1]));
            mx1 = fmaxf(mx1, fmaxf(sacc[nt][2], sacc[nt][3]));
        }
        mx0 = fmaxf(mx0, __shfl_xor_sync(0xffffffffu, mx0, 1));
        mx0 = fmaxf(mx0, __shfl_xor_sync(0xffffffffu, mx0, 2));
        mx1 = fmaxf(mx1, __shfl_xor_sync(0xffffffffu, mx1, 1));
        mx1 = fmaxf(mx1, __shfl_xor_sync(0xffffffffu, mx1, 2));
        const float mn0 = fmaxf(m0, mx0);
        const float mn1 = fmaxf(m1, mx1);

        uint32_t ph[2][4], pl[2][4];
        float s0 = 0.f, s1 = 0.f;
        #pragma unroll
        for (int nt = 0; nt < 4; nt++) {
            const float p0 = exp2_fast(sacc[nt][0] - mn0);
            const float p1 = exp2_fast(sacc[nt][1] - mn0);
            const float p2 = exp2_fast(sacc[nt][2] - mn1);
            const float p3 = exp2_fast(sacc[nt][3] - mn1);
            s0 += p0 + p1;
            s1 += p2 + p3;
            __nv_bfloat162 lo01, lo23;
            const __nv_bfloat162 h01 = split_hi(p0, p1, lo01);
            const __nv_bfloat162 h23 = split_hi(p2, p3, lo23);
            const int kk = nt >> 1, base = (nt & 1) * 2;
            ph[kk][base]     = b2u(h01);
            ph[kk][base + 1] = b2u(h23);
            pl[kk][base]     = b2u(lo01);
            pl[kk][base + 1] = b2u(lo23);
        }
        s0 += __shfl_xor_sync(0xffffffffu, s0, 1);
        s0 += __shfl_xor_sync(0xffffffffu, s0, 2);
        s1 += __shfl_xor_sync(0xffffffffu, s1, 1);
        s1 += __shfl_xor_sync(0xffffffffu, s1, 2);
        const float f0 = exp2_fast(m0 - mn0);
        const float f1 = exp2_fast(m1 - mn1);
        ls0 = ls0 * f0 + s0;
        ls1 = ls1 * f1 + s1;
        m0 = mn0; m1 = mn1;

        #pragma unroll
        for (int nt = 0; nt < 16; nt++) {
            O[nt][0] *= f0; O[nt][1] *= f0;
            O[nt][2] *= f1; O[nt][3] *= f1;
        }

        // ---- PV: warp tile 16x128, P from registers -----------------------
        const uint32_t sVh = stg + 16384, sVl = stg + 24576;
        #pragma unroll
        for (int kk = 0; kk < 2; kk++) {
            #pragma unroll
            for (int np = 0; np < 8; np++) {
                uint32_t vbh[4], vbl[4];
                const int mat = l >> 3, idx = l & 7;
                const int key = kk * 16 + ((mat & 1) << 3) + idx;
                const int cu = np * 2 + (mat >> 1);
                const uint32_t off = SWZ(key, cu);
                ldsm_x4_t(vbh, sVh + off);
                ldsm_x4_t(vbl, sVl + off);
                #pragma unroll
                for (int half = 0; half < 2; half++) {
                    const int nt = np * 2 + half;
                    mma16816(O[nt], ph[kk], &vbh[half * 2]);
                    mma16816(O[nt], ph[kk], &vbl[half * 2]);
                    mma16816(O[nt], pl[kk], &vbh[half * 2]);
                }
            }
        }
    }

    // ---- epilogue: normalize, split hi/lo, write GEMM2's A ---------------
    const float inv0 = 1.f / ls0;
    const float inv1 = 1.f / ls1;
    const int row0 = qt * ATQ + w * 16 + (l >> 2);
    const size_t s0o = (size_t)(b * S_LEN + row0) * EMB + h * DH;
    #pragma unroll
    for (int nt = 0; nt < 16; nt++) {
        const int col = nt * 8 + ((l & 3) << 1);
        __nv_bfloat162 lo0, lo1;
        const __nv_bfloat162 h0 = split_hi(O[nt][0] * inv0, O[nt][1] * inv0, lo0);
        const __nv_bfloat162 h1 = split_hi(O[nt][2] * inv1, O[nt][3] * inv1, lo1);
        *(__nv_bfloat162*)(outH + s0o + col) = h0;
        *(__nv_bfloat162*)(outL + s0o + col) = lo0;
        *(__nv_bfloat162*)(outH + s0o + (size_t)8 * EMB + col) = h1;
        *(__nv_bfloat162*)(outL + s0o + (size_t)8 * EMB + col) = lo1;
    }
}

// ---------------------------------------------------------------------------
extern "C" void kernel_launch(void* const* d_in, const int* in_sizes, int n_in,
                              void* d_out, int out_size)
{
    (void)in_sizes; (void)n_in; (void)out_size;
    const float* x    = (const float*)d_in[0];
    const float* Wqkv = (const float*)d_in[1];
    const float* bqkv = (const float*)d_in[2];
    const float* Wout = (const float*)d_in[3];
    const float* bout = (const float*)d_in[4];
    float* out = (float*)d_out;

    __nv_bfloat16 *ah, *al, *wqh, *wql, *woh, *wol;
    __nv_bfloat16 *qhp, *qlp, *khp, *klp, *vhp, *vlp;
    cudaGetSymbolAddress((void**)&ah, g_ah);
    cudaGetSymbolAddress((void**)&al, g_al);
    cudaGetSymbolAddress((void**)&wqh, g_wqh);
    cudaGetSymbolAddress((void**)&wql, g_wql);
    cudaGetSymbolAddress((void**)&woh, g_woh);
    cudaGetSymbolAddress((void**)&wol, g_wol);
    cudaGetSymbolAddress((void**)&qhp, g_qh);
    cudaGetSymbolAddress((void**)&qlp, g_ql);
    cudaGetSymbolAddress((void**)&khp, g_kh);
    cudaGetSymbolAddress((void**)&klp, g_kl);
    cudaGetSymbolAddress((void**)&vhp, g_vh);
    cudaGetSymbolAddress((void**)&vlp, g_vl);

    cudaFuncSetAttribute(gemm_mma_kernel,
                         cudaFuncAttributeMaxDynamicSharedMemorySize, GEMM_SMEM);
    cudaFuncSetAttribute(gemm_qkv_kernel,
                         cudaFuncAttributeMaxDynamicSharedMemorySize, GEMM_SMEM);
    cudaFuncSetAttribute(attn_mma_kernel,
                         cudaFuncAttributeMaxDynamicSharedMemorySize, ATTN_SMEM);

    // 0) conversions (inputs only)
    split_kernel<<<2048, 256>>>(x, ah, al, MROWS * EMB);
    transpose_split_kernel<<<dim3((3 * EMB) / 32, GK / 32), dim3(32, 8)>>>(
        Wqkv, wqh, wql, GK, 3 * EMB);
    transpose_split_kernel<<<dim3(EMB / 32, GK / 32), dim3(32, 8)>>>(
        Wout, woh, wol, GK, EMB);

    // 1) qkv projection fused with per-head hi/lo split (Q pre-scaled)
    gemm_qkv_kernel<<<dim3((3 * EMB) / 128, MROWS / 128), 256, GEMM_SMEM>>>(
        ah, al, wqh, wql, bqkv);

    // 2) FA2-style tensor-core attention; writes GEMM2's A (hi/lo) directly
    attn_mma_kernel<<<dim3(S_LEN / ATQ, NH, BATCH), 256, ATTN_SMEM>>>(
        qhp, qlp, khp, klp, vhp, vlp, ah, al);

    // 3) out = attn @ W_out + b_out
    gemm_mma_kernel<<<dim3(EMB / 128, MROWS / 128), 256, GEMM_SMEM>>>(
        EMB, ah, al, woh, wol, bout, out);
}

// round 7
// speedup vs baseline: 3.5285x; 1.0059x over previous
#include <cuda_runtime.h>
#include <cuda_bf16.h>
#include <cstdint>

#define S_LEN 2048
#define EMB   2048
#define NH    16
#define DH    128
#define BATCH 2
#define MROWS (BATCH * S_LEN)   // 4096
#define GK    2048              // K for both projection GEMMs

// ---------------------------------------------------------------------------
// Device scratch (no cudaMalloc allowed)
// ---------------------------------------------------------------------------
__device__ __nv_bfloat16 g_ah[(size_t)MROWS * GK];        // A hi (x, then attn-out)
__device__ __nv_bfloat16 g_al[(size_t)MROWS * GK];        // A lo
__device__ __nv_bfloat16 g_wqh[(size_t)(3 * EMB) * GK];
__device__ __nv_bfloat16 g_wql[(size_t)(3 * EMB) * GK];
__device__ __nv_bfloat16 g_woh[(size_t)EMB * GK];
__device__ __nv_bfloat16 g_wol[(size_t)EMB * GK];
// per-head Q/K/V hi/lo, layout [B, H, S, DH]
#define QKV_ELEMS ((size_t)BATCH * NH * S_LEN * DH)
__device__ __nv_bfloat16 g_qh[QKV_ELEMS];
__device__ __nv_bfloat16 g_ql[QKV_ELEMS];
__device__ __nv_bfloat16 g_kh[QKV_ELEMS];
__device__ __nv_bfloat16 g_kl[QKV_ELEMS];
__device__ __nv_bfloat16 g_vh[QKV_ELEMS];
__device__ __nv_bfloat16 g_vl[QKV_ELEMS];

// ---------------------------------------------------------------------------
// PTX helpers (plain sm_80+ instructions only)
// ---------------------------------------------------------------------------
__device__ __forceinline__ uint32_t smem_to_u32(const void* p) {
    uint32_t a;
    asm("{ .reg .u64 t; cvta.to.shared.u64 t, %1; cvt.u32.u64 %0, t; }"
        : "=r"(a) : "l"(p));
    return a;
}

__device__ __forceinline__ void cp_async16(uint32_t saddr, const void* gaddr) {
    asm volatile("cp.async.cg.shared.global [%0], [%1], 16;"
        :: "r"(saddr), "l"(gaddr) : "memory");
}
#define CP_COMMIT() asm volatile("cp.async.commit_group;" ::: "memory")
#define CP_WAIT(n)  asm volatile("cp.async.wait_group %0;" :: "n"(n) : "memory")

__device__ __forceinline__ void ldsm_x4(uint32_t* r, uint32_t addr) {
    asm volatile("ldmatrix.sync.aligned.m8n8.x4.shared.b16 {%0,%1,%2,%3}, [%4];"
        : "=r"(r[0]), "=r"(r[1]), "=r"(r[2]), "=r"(r[3]) : "r"(addr));
}
__device__ __forceinline__ void ldsm_x4_t(uint32_t* r, uint32_t addr) {
    asm volatile("ldmatrix.sync.aligned.m8n8.x4.trans.shared.b16 {%0,%1,%2,%3}, [%4];"
        : "=r"(r[0]), "=r"(r[1]), "=r"(r[2]), "=r"(r[3]) : "r"(addr));
}

__device__ __forceinline__ void mma16816(float* d, const uint32_t* a,
                                         const uint32_t* b) {
    asm volatile(
        "mma.sync.aligned.m16n8k16.row.col.f32.bf16.bf16.f32 "
        "{%0,%1,%2,%3}, {%4,%5,%6,%7}, {%8,%9}, {%0,%1,%2,%3};"
        : "+f"(d[0]), "+f"(d[1]), "+f"(d[2]), "+f"(d[3])
        : "r"(a[0]), "r"(a[1]), "r"(a[2]), "r"(a[3]), "r"(b[0]), "r"(b[1]));
}

// Fast 2^t on FMA/ALU pipes only (no MUFU, no CVT). |rel err| < 3e-6.
__device__ __forceinline__ float exp2_fast(float t) {
    t = fmaxf(t, -126.0f);
    const float MAGIC = 12582912.0f;          // 2^23 + 2^22
    float z = t + MAGIC;
    int i = __float_as_int(z);
    float r = z - MAGIC;
    float f = t - r;                          // f in [-0.5, 0.5]
    float p = 1.3333558146e-3f;
    p = fmaf(p, f, 9.6181291076e-3f);
    p = fmaf(p, f, 5.5504108664e-2f);
    p = fmaf(p, f, 2.4022650696e-1f);
    p = fmaf(p, f, 6.9314718056e-1f);
    p = fmaf(p, f, 1.0f);
    int eb = (i + (127 - 0x4B400000)) << 23;
    return p * __int_as_float(eb);
}

__device__ __forceinline__ __nv_bfloat162 split_hi(float v0, float v1, __nv_bfloat162& lo) {
    __nv_bfloat162 h;
    h.x = __float2bfloat16(v0);
    h.y = __float2bfloat16(v1);
    lo.x = __float2bfloat16(v0 - __bfloat162float(h.x));
    lo.y = __float2bfloat16(v1 - __bfloat162float(h.y));
    return h;
}
__device__ __forceinline__ uint32_t b2u(__nv_bfloat162 v) {
    return *(uint32_t*)&v;
}

// ---------------------------------------------------------------------------
// Conversion kernels
// ---------------------------------------------------------------------------
__global__ __launch_bounds__(256) void split_kernel(
    const float* __restrict__ in, __nv_bfloat16* __restrict__ hi,
    __nv_bfloat16* __restrict__ lo, int n)
{
    int i = blockIdx.x * blockDim.x + threadIdx.x;
    int stride = gridDim.x * blockDim.x;
    for (; i < n; i += stride) {
        float v = in[i];
        __nv_bfloat16 h = __float2bfloat16(v);
        hi[i] = h;
        lo[i] = __float2bfloat16(v - __bfloat162float(h));
    }
}

__global__ __launch_bounds__(256) void transpose_split_kernel(
    const float* __restrict__ W, __nv_bfloat16* __restrict__ Th,
    __nv_bfloat16* __restrict__ Tl, int K, int N)
{
    __shared__ float t[32][33];
    const int nb = blockIdx.x * 32;
    const int kb = blockIdx.y * 32;
    const int x = threadIdx.x, y = threadIdx.y;   // block (32,8)
    #pragma unroll
    for (int j = 0; j < 32; j += 8)
        t[y + j][x] = W[(size_t)(kb + y + j) * N + nb + x];
    __syncthreads();
    #pragma unroll
    for (int j = 0; j < 32; j += 8) {
        float v = t[x][y + j];
        __nv_bfloat16 h = __float2bfloat16(v);
        size_t o = (size_t)(nb + y + j) * K + kb + x;
        Th[o] = h;
        Tl[o] = __float2bfloat16(v - __bfloat162float(h));
    }
}

// ---------------------------------------------------------------------------
// Shared HMMA mainloop (3-term hi/lo). Block tile 256x128, 16 warps (512 thr),
// warp tile 64x32, K-chunk 64. 2-stage cp.async pipeline, ONE sync per chunk.
// ---------------------------------------------------------------------------
#define GBK   64
#define NCHUNK (GK / GBK)            // 32
#define ATB   32768                  // A array bytes/stage (256 rows x 128B)
#define BTB   16384                  // B array bytes/stage (128 rows x 128B)
#define STAGE (2 * ATB + 2 * BTB)    // 98304
#define GEMM_SMEM (2 * STAGE)        // 196608

template <typename Epilogue>
__device__ __forceinline__ void gemm_mainloop(
    char* gsm,
    const __nv_bfloat16* __restrict__ Ah, const __nv_bfloat16* __restrict__ Al,
    const __nv_bfloat16* __restrict__ Bh, const __nv_bfloat16* __restrict__ Bl,
    const float* __restrict__ bias, int bx, int by, Epilogue epi)
{
    const uint32_t sb = smem_to_u32(gsm);
    const int tid = threadIdx.x;
    const int w = tid >> 5, l = tid & 31;
    const int warp_m = w >> 2, warp_n = w & 3;   // 4 x 4 warp grid

    const __nv_bfloat16* gAh = Ah + (size_t)(by * 256) * GK;
    const __nv_bfloat16* gAl = Al + (size_t)(by * 256) * GK;
    const __nv_bfloat16* gBh = Bh + (size_t)(bx * 128) * GK;
    const __nv_bfloat16* gBl = Bl + (size_t)(bx * 128) * GK;

    float acc[4][4][4];
    #pragma unroll
    for (int nt = 0; nt < 4; nt++) {
        const int n = bx * 128 + warp_n * 32 + nt * 8 + ((l & 3) << 1);
        const float b0 = bias[n], b1 = bias[n + 1];
        #pragma unroll
        for (int mt = 0; mt < 4; mt++) {
            acc[mt][nt][0] = b0; acc[mt][nt][1] = b1;
            acc[mt][nt][2] = b0; acc[mt][nt][3] = b1;
        }
    }

    auto load_chunk = [&](int kt) {
        const uint32_t st = sb + (kt & 1) * STAGE;
        const size_t kofs = (size_t)kt * GBK;
        // A hi/lo: 256 rows x 8 units each
        {
            const char* gh = (const char*)(gAh + kofs);
            const char* gl = (const char*)(gAl + kofs);
            #pragma unroll
            for (int j = 0; j < 4; j++) {
                const int u = tid + 512 * j;      // 2048 units
                const int r = u >> 3;
                const int cu = u & 7;
                const uint32_t off = r * 128 + ((cu ^ (r & 7)) << 4);
                const size_t go = (size_t)r * (GK * 2) + (cu << 4);
                cp_async16(st + off, gh + go);
                cp_async16(st + ATB + off, gl + go);
            }
        }
        // B hi/lo: 128 rows x 8 units each
        {
            const char* gh = (const char*)(gBh + kofs);
            const char* gl = (const char*)(gBl + kofs);
            #pragma unroll
            for (int j = 0; j < 2; j++) {
                const int u = tid + 512 * j;      // 1024 units
                const int r = u >> 3;
                const int cu = u & 7;
                const uint32_t off = r * 128 + ((cu ^ (r & 7)) << 4);
                const size_t go = (size_t)r * (GK * 2) + (cu << 4);
                cp_async16(st + 2 * ATB + off, gh + go);
                cp_async16(st + 2 * ATB + BTB + off, gl + go);
            }
        }
        CP_COMMIT();
    };

    load_chunk(0);

    for (int kt = 0; kt < NCHUNK; kt++) {
        CP_WAIT(0);                 // chunk kt resident (kt+1 not yet issued)
        __syncthreads();            // all warps done reading buffer (kt+1)&1
        if (kt + 1 < NCHUNK) load_chunk(kt + 1);

        const uint32_t st = sb + (kt & 1) * STAGE;
        const uint32_t sAh = st, sAl = st + ATB;
        const uint32_t sBh = st + 2 * ATB, sBl = st + 2 * ATB + BTB;

        #pragma unroll
        for (int kk = 0; kk < 4; kk++) {
            const int kb = kk * 32;

            uint32_t ah[4][4], al[4][4];
            #pragma unroll
            for (int mt = 0; mt < 4; mt++) {
                const int row = warp_m * 64 + mt * 16 + (l & 15);
                const int bc = kb + ((l >> 4) << 4);
                const uint32_t off = row * 128 + (bc ^ ((row & 7) << 4));
                ldsm_x4(ah[mt], sAh + off);
                ldsm_x4(al[mt], sAl + off);
            }

            uint32_t bh[2][4], bl[2][4];
            #pragma unroll
            for (int np = 0; np < 2; np++) {
                const int g = l >> 3, idx = l & 7;
                const int row = warp_n * 32 + np * 16 + ((g >> 1) << 3) + idx;
                const int bc = kb + ((g & 1) << 4);
                const uint32_t off = row * 128 + (bc ^ ((row & 7) << 4));
                ldsm_x4(bh[np], sBh + off);
                ldsm_x4(bl[np], sBl + off);
            }

            #pragma unroll
            for (int mt = 0; mt < 4; mt++)
                #pragma unroll
                for (int nt = 0; nt < 4; nt++) {
                    const uint32_t* bhp = &bh[nt >> 1][(nt & 1) * 2];
                    const uint32_t* blp = &bl[nt >> 1][(nt & 1) * 2];
                    mma16816(acc[mt][nt], ah[mt], bhp);
                    mma16816(acc[mt][nt], ah[mt], blp);
                    mma16816(acc[mt][nt], al[mt], bhp);
                }
        }
    }

    epi(acc, warp_m, warp_n, l);
}

// GEMM2: plain fp32 output C = A*B^T + bias
__global__ __launch_bounds__(512, 1) void gemm_mma_kernel(
    int N,
    const __nv_bfloat16* __restrict__ Ah, const __nv_bfloat16* __restrict__ Al,
    const __nv_bfloat16* __restrict__ Bh, const __nv_bfloat16* __restrict__ Bl,
    const float* __restrict__ bias, float* __restrict__ C)
{
    extern __shared__ char gsm[];
    const int bx = blockIdx.x, by = blockIdx.y;
    gemm_mainloop(gsm, Ah, Al, Bh, Bl, bias, bx, by,
        [&](float acc[4][4][4], int warp_m, int warp_n, int l) {
            #pragma unroll
            for (int mt = 0; mt < 4; mt++) {
                const int m = by * 256 + warp_m * 64 + mt * 16 + (l >> 2);
                float* c0 = C + (size_t)m * N + bx * 128 + warp_n * 32 + ((l & 3) << 1);
                #pragma unroll
                for (int nt = 0; nt < 4; nt++) {
                    *(float2*)(c0 + nt * 8) =
                        make_float2(acc[mt][nt][0], acc[mt][nt][1]);
                    *(float2*)(c0 + (size_t)8 * N + nt * 8) =
                        make_float2(acc[mt][nt][2], acc[mt][nt][3]);
                }
            }
        });
}

// GEMM1 fused: writes per-head Q/K/V hi/lo bf16 directly.
__global__ __launch_bounds__(512, 1) void gemm_qkv_kernel(
    const __nv_bfloat16* __restrict__ Ah, const __nv_bfloat16* __restrict__ Al,
    const __nv_bfloat16* __restrict__ Bh, const __nv_bfloat16* __restrict__ Bl,
    const float* __restrict__ bias)
{
    extern __shared__ char gsm[];
    const int bx = blockIdx.x, by = blockIdx.y;
    const int region = bx % 3;        // 0=q, 1=k, 2=v
    const int head   = bx / 3;
    __nv_bfloat16* H = (region == 0) ? g_qh : (region == 1) ? g_kh : g_vh;
    __nv_bfloat16* L = (region == 0) ? g_ql : (region == 1) ? g_kl : g_vl;
    const float scl = (region == 0) ? 0.12751744f : 1.0f;  // log2(e)/sqrt(128)

    gemm_mainloop(gsm, Ah, Al, Bh, Bl, bias, bx, by,
        [&](float acc[4][4][4], int warp_m, int warp_n, int l) {
            #pragma unroll
            for (int mt = 0; mt < 4; mt++) {
                const int m = by * 256 + warp_m * 64 + mt * 16 + (l >> 2);
                const int b = m >> 11, s = m & (S_LEN - 1);
                const size_t base =
                    (((size_t)(b * NH + head)) * S_LEN + s) * DH;
                #pragma unroll
                for (int nt = 0; nt < 4; nt++) {
                    const int d = warp_n * 32 + nt * 8 + ((l & 3) << 1);
                    __nv_bfloat162 lo0, lo1;
                    __nv_bfloat162 h0 = split_hi(acc[mt][nt][0] * scl,
                                                 acc[mt][nt][1] * scl, lo0);
                    __nv_bfloat162 h1 = split_hi(acc[mt][nt][2] * scl,
                                                 acc[mt][nt][3] * scl, lo1);
                    *(__nv_bfloat162*)(H + base + d) = h0;
                    *(__nv_bfloat162*)(L + base + d) = lo0;
                    *(__nv_bfloat162*)(H + base + (size_t)8 * DH + d) = h1;
                    *(__nv_bfloat162*)(L + base + (size_t)8 * DH + d) = lo1;
                }
            }
        });
}

// ---------------------------------------------------------------------------
// FA2-style tensor-core attention (unchanged from R6)
// ---------------------------------------------------------------------------
#define ATQ 128
#define AKT 32
#define ANT (S_LEN / AKT)

#define ASM_QH 0
#define ASM_QL 32768
#define ASM_KV 65536                  // 3 stages x 32768 (Kh|Kl|Vh|Vl x 8KB)
#define ATTN_SMEM (65536 + 3 * 32768) // 163840

#define SWZ(row, cu) ((row) * 256 + ((((cu) ^ ((row) & 7))) << 4))

__global__ __launch_bounds__(256) void attn_mma_kernel(
    const __nv_bfloat16* __restrict__ qh, const __nv_bfloat16* __restrict__ ql,
    const __nv_bfloat16* __restrict__ kh, const __nv_bfloat16* __restrict__ kl,
    const __nv_bfloat16* __restrict__ vh, const __nv_bfloat16* __restrict__ vl,
    __nv_bfloat16* __restrict__ outH, __nv_bfloat16* __restrict__ outL)
{
    extern __shared__ char gsm[];
    const uint32_t sb = smem_to_u32(gsm);
    const int tid = threadIdx.x;
    const int w = tid >> 5, l = tid & 31;
    const int qt = blockIdx.x, h = blockIdx.y, b = blockIdx.z;

    const size_t head = ((size_t)(b * NH + h)) * S_LEN * DH;
    const __nv_bfloat16* Qh_g = qh + head + (size_t)qt * ATQ * DH;
    const __nv_bfloat16* Ql_g = ql + head + (size_t)qt * ATQ * DH;

    auto load_kv = [&](int t) {
        const uint32_t st = sb + ASM_KV + (t % 3) * 32768;
        const size_t base = head + (size_t)t * AKT * DH;
        const __nv_bfloat16* srcs[4] = {kh + base, kl + base, vh + base, vl + base};
        #pragma unroll
        for (int a = 0; a < 4; a++) {
            #pragma unroll
            for (int j = 0; j < 2; j++) {
                const int u = tid + 256 * j;
                const int row = u >> 4, cu = u & 15;
                cp_async16(st + a * 8192 + SWZ(row, cu),
                           (const char*)srcs[a] + (size_t)row * 256 + cu * 16);
            }
        }
        CP_COMMIT();
    };

    #pragma unroll
    for (int j = 0; j < 8; j++) {
        const int u = tid + 256 * j;
        const int row = u >> 4, cu = u & 15;
        cp_async16(sb + ASM_QH + SWZ(row, cu),
                   (const char*)Qh_g + (size_t)row * 256 + cu * 16);
        cp_async16(sb + ASM_QL + SWZ(row, cu),
                   (const char*)Ql_g + (size_t)row * 256 + cu * 16);
    }
    load_kv(0);
    load_kv(1);

    float m0 = -1e9f, m1 = -1e9f, ls0 = 0.f, ls1 = 0.f;
    float O[16][4];
    #pragma unroll
    for (int nt = 0; nt < 16; nt++)
        #pragma unroll
        for (int c = 0; c < 4; c++) O[nt][c] = 0.f;

    for (int t = 0; t < ANT; t++) {
        if (t + 1 < ANT) { CP_WAIT(1); } else { CP_WAIT(0); }
        __syncthreads();
        if (t + 2 < ANT) load_kv(t + 2);

        const uint32_t stg = sb + ASM_KV + (t % 3) * 32768;

        // ---- QK: sacc[nt][4], warp tile 16x32 -----------------------------
        float sacc[4][4];
        #pragma unroll
        for (int nt = 0; nt < 4; nt++)
            #pragma unroll
            for (int c = 0; c < 4; c++) sacc[nt][c] = 0.f;

        #pragma unroll
        for (int kk = 0; kk < 8; kk++) {
            uint32_t qhf[4], qlf[4];
            {
                const int row = w * 16 + (l & 15);
                const int cu = kk * 2 + (l >> 4);
                const uint32_t off = SWZ(row, cu);
                ldsm_x4(qhf, sb + ASM_QH + off);
                ldsm_x4(qlf, sb + ASM_QL + off);
            }
            uint32_t khf[2][4], klf[2][4];
            #pragma unroll
            for (int np = 0; np < 2; np++) {
                const int g = l >> 3, idx = l & 7;
                const int krow = np * 16 + ((g >> 1) << 3) + idx;
                const int bcu = kk * 2 + (g & 1);
                const uint32_t off = SWZ(krow, bcu);
                ldsm_x4(khf[np], stg + off);
                ldsm_x4(klf[np], stg + 8192 + off);
            }
            #pragma unroll
            for (int nt = 0; nt < 4; nt++) {
                const uint32_t* bhp = &khf[nt >> 1][(nt & 1) * 2];
                const uint32_t* blp = &klf[nt >> 1][(nt & 1) * 2];
                mma16816(sacc[nt], qhf, bhp);
                mma16816(sacc[nt], qhf, blp);
                mma16816(sacc[nt], qlf, bhp);
            }
        }

        // ---- softmax in registers -----------------------------------------
        float mx0 = sacc[0][0], mx1 = sacc[0][2];
        #pragma unroll
        for (int nt = 0; nt < 4; nt++) {
            mx0 = fmaxf(mx0, fmaxf(sacc[nt][0], sacc[nt][1]));
            mx1 = fmaxf(mx1, fmaxf(sacc[nt][2], sacc[nt][3]));
        }
        mx0 = fmaxf(mx0, __shfl_xor_sync(0xffffffffu, mx0, 1));
        mx0 = fmaxf(mx0, __shfl_xor_sync(0xffffffffu, mx0, 2));
        mx1 = fmaxf(mx1, __shfl_xor_sync(0xffffffffu, mx1, 1));
        mx1 = fmaxf(mx1, __shfl_xor_sync(0xffffffffu, mx1, 2));
        const float mn0 = fmaxf(m0, mx0);
        const float mn1 = fmaxf(m1, mx1);

        uint32_t ph[2][4], pl[2][4];
        float s0 = 0.f, s1 = 0.f;
        #pragma unroll
        for (int nt = 0; nt < 4; nt++) {
            const float p0 = exp2_fast(sacc[nt][0] - mn0);
            const float p1 = exp2_fast(sacc[nt][1] - mn0);
            const float p2 = exp2_fast(sacc[nt][2] - mn1);
            const float p3 = exp2_fast(sacc[nt][3] - mn1);
            s0 += p0 + p1;
            s1 += p2 + p3;
            __nv_bfloat162 lo01, lo23;
            const __nv_bfloat162 h01 = split_hi(p0, p1, lo01);
            const __nv_bfloat162 h23 = split_hi(p2, p3, lo23);
            const int kk = nt >> 1, base = (nt & 1) * 2;
            ph[kk][base]     = b2u(h01);
            ph[kk][base + 1] = b2u(h23);
            pl[kk][base]     = b2u(lo01);
            pl[kk][base + 1] = b2u(lo23);
        }
        s0 += __shfl_xor_sync(0xffffffffu, s0, 1);
        s0 += __shfl_xor_sync(0xffffffffu, s0, 2);
        s1 += __shfl_xor_sync(0xffffffffu, s1, 1);
        s1 += __shfl_xor_sync(0xffffffffu, s1, 2);
        const float f0 = exp2_fast(m0 - mn0);
        const float f1 = exp2_fast(m1 - mn1);
        ls0 = ls0 * f0 + s0;
        ls1 = ls1 * f1 + s1;
        m0 = mn0; m1 = mn1;

        #pragma unroll
        for (int nt = 0; nt < 16; nt++) {
            O[nt][0] *= f0; O[nt][1] *= f0;
            O[nt][2] *= f1; O[nt][3] *= f1;
        }

        // ---- PV: warp tile 16x128, P from registers -----------------------
        const uint32_t sVh = stg + 16384, sVl = stg + 24576;
        #pragma unroll
        for (int kk = 0; kk < 2; kk++) {
            #pragma unroll
            for (int np = 0; np < 8; np++) {
                uint32_t vbh[4], vbl[4];
                const int mat = l >> 3, idx = l & 7;
                const int key = kk * 16 + ((mat & 1) << 3) + idx;
                const int cu = np * 2 + (mat >> 1);
                const uint32_t off = SWZ(key, cu);
                ldsm_x4_t(vbh, sVh + off);
                ldsm_x4_t(vbl, sVl + off);
                #pragma unroll
                for (int half = 0; half < 2; half++) {
                    const int nt = np * 2 + half;
                    mma16816(O[nt], ph[kk], &vbh[half * 2]);
                    mma16816(O[nt], ph[kk], &vbl[half * 2]);
                    mma16816(O[nt], pl[kk], &vbh[half * 2]);
                }
            }
        }
    }

    // ---- epilogue: normalize, split hi/lo, write GEMM2's A ---------------
    const float inv0 = 1.f / ls0;
    const float inv1 = 1.f / ls1;
    const int row0 = qt * ATQ + w * 16 + (l >> 2);
    const size_t s0o = (size_t)(b * S_LEN + row0) * EMB + h * DH;
    #pragma unroll
    for (int nt = 0; nt < 16; nt++) {
        const int col = nt * 8 + ((l & 3) << 1);
        __nv_bfloat162 lo0, lo1;
        const __nv_bfloat162 h0 = split_hi(O[nt][0] * inv0, O[nt][1] * inv0, lo0);
        const __nv_bfloat162 h1 = split_hi(O[nt][2] * inv1, O[nt][3] * inv1, lo1);
        *(__nv_bfloat162*)(outH + s0o + col) = h0;
        *(__nv_bfloat162*)(outL + s0o + col) = lo0;
        *(__nv_bfloat162*)(outH + s0o + (size_t)8 * EMB + col) = h1;
        *(__nv_bfloat162*)(outL + s0o + (size_t)8 * EMB + col) = lo1;
    }
}

// ---------------------------------------------------------------------------
extern "C" void kernel_launch(void* const* d_in, const int* in_sizes, int n_in,
                              void* d_out, int out_size)
{
    (void)in_sizes; (void)n_in; (void)out_size;
    const float* x    = (const float*)d_in[0];
    const float* Wqkv = (const float*)d_in[1];
    const float* bqkv = (const float*)d_in[2];
    const float* Wout = (const float*)d_in[3];
    const float* bout = (const float*)d_in[4];
    float* out = (float*)d_out;

    __nv_bfloat16 *ah, *al, *wqh, *wql, *woh, *wol;
    __nv_bfloat16 *qhp, *qlp, *khp, *klp, *vhp, *vlp;
    cudaGetSymbolAddress((void**)&ah, g_ah);
    cudaGetSymbolAddress((void**)&al, g_al);
    cudaGetSymbolAddress((void**)&wqh, g_wqh);
    cudaGetSymbolAddress((void**)&wql, g_wql);
    cudaGetSymbolAddress((void**)&woh, g_woh);
    cudaGetSymbolAddress((void**)&wol, g_wol);
    cudaGetSymbolAddress((void**)&qhp, g_qh);
    cudaGetSymbolAddress((void**)&qlp, g_ql);
    cudaGetSymbolAddress((void**)&khp, g_kh);
    cudaGetSymbolAddress((void**)&klp, g_kl);
    cudaGetSymbolAddress((void**)&vhp, g_vh);
    cudaGetSymbolAddress((void**)&vlp, g_vl);

    cudaFuncSetAttribute(gemm_mma_kernel,
                         cudaFuncAttributeMaxDynamicSharedMemorySize, GEMM_SMEM);
    cudaFuncSetAttribute(gemm_qkv_kernel,
                         cudaFuncAttributeMaxDynamicSharedMemorySize, GEMM_SMEM);
    cudaFuncSetAttribute(attn_mma_kernel,
                         cudaFuncAttributeMaxDynamicSharedMemorySize, ATTN_SMEM);

    // 0) conversions (inputs only)
    split_kernel<<<2048, 256>>>(x, ah, al, MROWS * EMB);
    transpose_split_kernel<<<dim3((3 * EMB) / 32, GK / 32), dim3(32, 8)>>>(
        Wqkv, wqh, wql, GK, 3 * EMB);
    transpose_split_kernel<<<dim3(EMB / 32, GK / 32), dim3(32, 8)>>>(
        Wout, woh, wol, GK, EMB);

    // 1) qkv projection fused with per-head hi/lo split (Q pre-scaled)
    gemm_qkv_kernel<<<dim3((3 * EMB) / 128, MROWS / 256), 512, GEMM_SMEM>>>(
        ah, al, wqh, wql, bqkv);

    // 2) FA2-style tensor-core attention; writes GEMM2's A (hi/lo) directly
    attn_mma_kernel<<<dim3(S_LEN / ATQ, NH, BATCH), 256, ATTN_SMEM>>>(
        qhp, qlp, khp, klp, vhp, vlp, ah, al);

    // 3) out = attn @ W_out + b_out
    gemm_mma_kernel<<<dim3(EMB / 128, MROWS / 256), 512, GEMM_SMEM>>>(
        EMB, ah, al, woh, wol, bout, out);
}

// round 8
// speedup vs baseline: 3.5577x; 1.0083x over previous
#include <cuda_runtime.h>
#include <cuda_bf16.h>
#include <cstdint>

#define S_LEN 2048
#define EMB   2048
#define NH    16
#define DH    128
#define BATCH 2
#define MROWS (BATCH * S_LEN)   // 4096
#define GK    2048              // K for both projection GEMMs

// ---------------------------------------------------------------------------
// Device scratch (no cudaMalloc allowed)
// ---------------------------------------------------------------------------
__device__ __nv_bfloat16 g_ah[(size_t)MROWS * GK];        // A hi (x, then attn-out)
__device__ __nv_bfloat16 g_al[(size_t)MROWS * GK];        // A lo
__device__ __nv_bfloat16 g_wqh[(size_t)(3 * EMB) * GK];
__device__ __nv_bfloat16 g_wql[(size_t)(3 * EMB) * GK];
__device__ __nv_bfloat16 g_woh[(size_t)EMB * GK];
__device__ __nv_bfloat16 g_wol[(size_t)EMB * GK];
// per-head Q/K/V hi/lo, layout [B, H, S, DH]
#define QKV_ELEMS ((size_t)BATCH * NH * S_LEN * DH)
__device__ __nv_bfloat16 g_qh[QKV_ELEMS];
__device__ __nv_bfloat16 g_ql[QKV_ELEMS];
__device__ __nv_bfloat16 g_kh[QKV_ELEMS];
__device__ __nv_bfloat16 g_kl[QKV_ELEMS];
__device__ __nv_bfloat16 g_vh[QKV_ELEMS];
__device__ __nv_bfloat16 g_vl[QKV_ELEMS];

// ---------------------------------------------------------------------------
// PTX helpers (plain sm_80+ instructions only)
// ---------------------------------------------------------------------------
__device__ __forceinline__ uint32_t smem_to_u32(const void* p) {
    uint32_t a;
    asm("{ .reg .u64 t; cvta.to.shared.u64 t, %1; cvt.u32.u64 %0, t; }"
        : "=r"(a) : "l"(p));
    return a;
}

__device__ __forceinline__ void cp_async16(uint32_t saddr, const void* gaddr) {
    asm volatile("cp.async.cg.shared.global [%0], [%1], 16;"
        :: "r"(saddr), "l"(gaddr) : "memory");
}
#define CP_COMMIT() asm volatile("cp.async.commit_group;" ::: "memory")
#define CP_WAIT(n)  asm volatile("cp.async.wait_group %0;" :: "n"(n) : "memory")

__device__ __forceinline__ void ldsm_x4(uint32_t* r, uint32_t addr) {
    asm volatile("ldmatrix.sync.aligned.m8n8.x4.shared.b16 {%0,%1,%2,%3}, [%4];"
        : "=r"(r[0]), "=r"(r[1]), "=r"(r[2]), "=r"(r[3]) : "r"(addr));
}
__device__ __forceinline__ void ldsm_x4_t(uint32_t* r, uint32_t addr) {
    asm volatile("ldmatrix.sync.aligned.m8n8.x4.trans.shared.b16 {%0,%1,%2,%3}, [%4];"
        : "=r"(r[0]), "=r"(r[1]), "=r"(r[2]), "=r"(r[3]) : "r"(addr));
}

__device__ __forceinline__ void mma16816(float* d, const uint32_t* a,
                                         const uint32_t* b) {
    asm volatile(
        "mma.sync.aligned.m16n8k16.row.col.f32.bf16.bf16.f32 "
        "{%0,%1,%2,%3}, {%4,%5,%6,%7}, {%8,%9}, {%0,%1,%2,%3};"
        : "+f"(d[0]), "+f"(d[1]), "+f"(d[2]), "+f"(d[3])
        : "r"(a[0]), "r"(a[1]), "r"(a[2]), "r"(a[3]), "r"(b[0]), "r"(b[1]));
}

// Fast 2^t on FMA/ALU pipes only (no MUFU, no CVT). |rel err| < 3e-6.
__device__ __forceinline__ float exp2_fast(float t) {
    t = fmaxf(t, -126.0f);
    const float MAGIC = 12582912.0f;          // 2^23 + 2^22
    float z = t + MAGIC;
    int i = __float_as_int(z);
    float r = z - MAGIC;
    float f = t - r;                          // f in [-0.5, 0.5]
    float p = 1.3333558146e-3f;
    p = fmaf(p, f, 9.6181291076e-3f);
    p = fmaf(p, f, 5.5504108664e-2f);
    p = fmaf(p, f, 2.4022650696e-1f);
    p = fmaf(p, f, 6.9314718056e-1f);
    p = fmaf(p, f, 1.0f);
    int eb = (i + (127 - 0x4B400000)) << 23;
    return p * __int_as_float(eb);
}

__device__ __forceinline__ __nv_bfloat162 split_hi(float v0, float v1, __nv_bfloat162& lo) {
    __nv_bfloat162 h;
    h.x = __float2bfloat16(v0);
    h.y = __float2bfloat16(v1);
    lo.x = __float2bfloat16(v0 - __bfloat162float(h.x));
    lo.y = __float2bfloat16(v1 - __bfloat162float(h.y));
    return h;
}
__device__ __forceinline__ uint32_t b2u(__nv_bfloat162 v) {
    return *(uint32_t*)&v;
}

// ---------------------------------------------------------------------------
// Conversion kernels
// ---------------------------------------------------------------------------
__global__ __launch_bounds__(256) void split_kernel(
    const float* __restrict__ in, __nv_bfloat16* __restrict__ hi,
    __nv_bfloat16* __restrict__ lo, int n)
{
    int i = blockIdx.x * blockDim.x + threadIdx.x;
    int stride = gridDim.x * blockDim.x;
    for (; i < n; i += stride) {
        float v = in[i];
        __nv_bfloat16 h = __float2bfloat16(v);
        hi[i] = h;
        lo[i] = __float2bfloat16(v - __bfloat162float(h));
    }
}

__global__ __launch_bounds__(256) void transpose_split_kernel(
    const float* __restrict__ W, __nv_bfloat16* __restrict__ Th,
    __nv_bfloat16* __restrict__ Tl, int K, int N)
{
    __shared__ float t[32][33];
    const int nb = blockIdx.x * 32;
    const int kb = blockIdx.y * 32;
    const int x = threadIdx.x, y = threadIdx.y;   // block (32,8)
    #pragma unroll
    for (int j = 0; j < 32; j += 8)
        t[y + j][x] = W[(size_t)(kb + y + j) * N + nb + x];
    __syncthreads();
    #pragma unroll
    for (int j = 0; j < 32; j += 8) {
        float v = t[x][y + j];
        __nv_bfloat16 h = __float2bfloat16(v);
        size_t o = (size_t)(nb + y + j) * K + kb + x;
        Th[o] = h;
        Tl[o] = __float2bfloat16(v - __bfloat162float(h));
    }
}

// ---------------------------------------------------------------------------
// HMMA mainloop, R3 geometry (empirically best: 71.4% tensor):
// block tile 128x128, 8 warps (2x4), warp tile 64x32, K-chunk 64,
// 2-stage double buffer, 2 syncs per chunk.
// ---------------------------------------------------------------------------
#define GBK   64
#define NCHUNK (GK / GBK)
#define TBYTES 16384
#define STAGE  (4 * TBYTES)          // 64 KB
#define GEMM_SMEM (2 * STAGE)        // 128 KB

template <typename Epilogue>
__device__ __forceinline__ void gemm_mainloop(
    char* gsm,
    const __nv_bfloat16* __restrict__ Ah, const __nv_bfloat16* __restrict__ Al,
    const __nv_bfloat16* __restrict__ Bh, const __nv_bfloat16* __restrict__ Bl,
    const float* __restrict__ bias, int bx, int by, Epilogue epi)
{
    const uint32_t sb = smem_to_u32(gsm);
    const int tid = threadIdx.x;
    const int w = tid >> 5, l = tid & 31;
    const int warp_m = w >> 2, warp_n = w & 3;

    const __nv_bfloat16* srcs[4] = {
        Ah + (size_t)(by * 128) * GK, Al + (size_t)(by * 128) * GK,
        Bh + (size_t)(bx * 128) * GK, Bl + (size_t)(bx * 128) * GK };

    float acc[4][4][4];
    #pragma unroll
    for (int nt = 0; nt < 4; nt++) {
        const int n = bx * 128 + warp_n * 32 + nt * 8 + ((l & 3) << 1);
        const float b0 = bias[n], b1 = bias[n + 1];
        #pragma unroll
        for (int mt = 0; mt < 4; mt++) {
            acc[mt][nt][0] = b0; acc[mt][nt][1] = b1;
            acc[mt][nt][2] = b0; acc[mt][nt][3] = b1;
        }
    }

    auto load_chunk = [&](int kt) {
        const uint32_t st = sb + (kt & 1) * STAGE;
        const size_t kofs = (size_t)kt * GBK;
        #pragma unroll
        for (int a = 0; a < 4; a++) {
            const char* g = (const char*)(srcs[a] + kofs);
            #pragma unroll
            for (int j = 0; j < 4; j++) {
                const int u = tid + 256 * j;
                const int r = u >> 3;
                const int cu = u & 7;
                const uint32_t off = r * 128 + ((cu ^ (r & 7)) << 4);
                cp_async16(st + a * TBYTES + off,
                           g + (size_t)r * (GK * 2) + (cu << 4));
            }
        }
        CP_COMMIT();
    };

    load_chunk(0);

    for (int kt = 0; kt < NCHUNK; kt++) {
        if (kt + 1 < NCHUNK) { load_chunk(kt + 1); CP_WAIT(1); }
        else                 { CP_WAIT(0); }
        __syncthreads();

        const uint32_t st = sb + (kt & 1) * STAGE;
        const uint32_t sAh = st, sAl = st + TBYTES;
        const uint32_t sBh = st + 2 * TBYTES, sBl = st + 3 * TBYTES;

        #pragma unroll
        for (int kk = 0; kk < 4; kk++) {
            const int kb = kk * 32;

            uint32_t ah[4][4], al[4][4];
            #pragma unroll
            for (int mt = 0; mt < 4; mt++) {
                const int row = warp_m * 64 + mt * 16 + (l & 15);
                const int bc = kb + ((l >> 4) << 4);
                const uint32_t off = row * 128 + (bc ^ ((row & 7) << 4));
                ldsm_x4(ah[mt], sAh + off);
                ldsm_x4(al[mt], sAl + off);
            }

            uint32_t bh[2][4], bl[2][4];
            #pragma unroll
            for (int np = 0; np < 2; np++) {
                const int g = l >> 3, idx = l & 7;
                const int row = warp_n * 32 + np * 16 + ((g >> 1) << 3) + idx;
                const int bc = kb + ((g & 1) << 4);
                const uint32_t off = row * 128 + (bc ^ ((row & 7) << 4));
                ldsm_x4(bh[np], sBh + off);
                ldsm_x4(bl[np], sBl + off);
            }

            #pragma unroll
            for (int mt = 0; mt < 4; mt++)
                #pragma unroll
                for (int nt = 0; nt < 4; nt++) {
                    const uint32_t* bhp = &bh[nt >> 1][(nt & 1) * 2];
                    const uint32_t* blp = &bl[nt >> 1][(nt & 1) * 2];
                    mma16816(acc[mt][nt], ah[mt], bhp);
                    mma16816(acc[mt][nt], ah[mt], blp);
                    mma16816(acc[mt][nt], al[mt], bhp);
                }
        }
        __syncthreads();
    }

    epi(acc, warp_m, warp_n, l);
}

// GEMM2: plain fp32 output C = A*B^T + bias
__global__ __launch_bounds__(256) void gemm_mma_kernel(
    int N,
    const __nv_bfloat16* __restrict__ Ah, const __nv_bfloat16* __restrict__ Al,
    const __nv_bfloat16* __restrict__ Bh, const __nv_bfloat16* __restrict__ Bl,
    const float* __restrict__ bias, float* __restrict__ C)
{
    extern __shared__ char gsm[];
    const int bx = blockIdx.x, by = blockIdx.y;
    gemm_mainloop(gsm, Ah, Al, Bh, Bl, bias, bx, by,
        [&](float acc[4][4][4], int warp_m, int warp_n, int l) {
            #pragma unroll
            for (int mt = 0; mt < 4; mt++) {
                const int m = by * 128 + warp_m * 64 + mt * 16 + (l >> 2);
                float* c0 = C + (size_t)m * N + bx * 128 + warp_n * 32 + ((l & 3) << 1);
                #pragma unroll
                for (int nt = 0; nt < 4; nt++) {
                    *(float2*)(c0 + nt * 8) =
                        make_float2(acc[mt][nt][0], acc[mt][nt][1]);
                    *(float2*)(c0 + (size_t)8 * N + nt * 8) =
                        make_float2(acc[mt][nt][2], acc[mt][nt][3]);
                }
            }
        });
}

// GEMM1 fused: writes per-head Q/K/V hi/lo bf16 directly.
__global__ __launch_bounds__(256) void gemm_qkv_kernel(
    const __nv_bfloat16* __restrict__ Ah, const __nv_bfloat16* __restrict__ Al,
    const __nv_bfloat16* __restrict__ Bh, const __nv_bfloat16* __restrict__ Bl,
    const float* __restrict__ bias)
{
    extern __shared__ char gsm[];
    const int bx = blockIdx.x, by = blockIdx.y;
    const int region = bx % 3;        // 0=q, 1=k, 2=v
    const int head   = bx / 3;
    __nv_bfloat16* H = (region == 0) ? g_qh : (region == 1) ? g_kh : g_vh;
    __nv_bfloat16* L = (region == 0) ? g_ql : (region == 1) ? g_kl : g_vl;
    const float scl = (region == 0) ? 0.12751744f : 1.0f;  // log2(e)/sqrt(128)

    gemm_mainloop(gsm, Ah, Al, Bh, Bl, bias, bx, by,
        [&](float acc[4][4][4], int warp_m, int warp_n, int l) {
            #pragma unroll
            for (int mt = 0; mt < 4; mt++) {
                const int m = by * 128 + warp_m * 64 + mt * 16 + (l >> 2);
                const int b = m >> 11, s = m & (S_LEN - 1);
                const size_t base =
                    (((size_t)(b * NH + head)) * S_LEN + s) * DH;
                #pragma unroll
                for (int nt = 0; nt < 4; nt++) {
                    const int d = warp_n * 32 + nt * 8 + ((l & 3) << 1);
                    __nv_bfloat162 lo0, lo1;
                    __nv_bfloat162 h0 = split_hi(acc[mt][nt][0] * scl,
                                                 acc[mt][nt][1] * scl, lo0);
                    __nv_bfloat162 h1 = split_hi(acc[mt][nt][2] * scl,
                                                 acc[mt][nt][3] * scl, lo1);
                    *(__nv_bfloat162*)(H + base + d) = h0;
                    *(__nv_bfloat162*)(L + base + d) = lo0;
                    *(__nv_bfloat162*)(H + base + (size_t)8 * DH + d) = h1;
                    *(__nv_bfloat162*)(L + base + (size_t)8 * DH + d) = lo1;
                }
            }
        });
}

// ---------------------------------------------------------------------------
// FA2-style tensor-core attention, Q fragments cached in registers.
// 8 warps; each warp owns 16 Q rows (QK 16x32, PV 16x128). One sync per tile.
// 3-stage KV pipeline. Epilogue writes GEMM2's A (hi/lo bf16) directly.
// ---------------------------------------------------------------------------
#define ATQ 128
#define AKT 32
#define ANT (S_LEN / AKT)

#define ASM_QH 0
#define ASM_QL 32768
#define ASM_KV 65536                  // 3 stages x 32768 (Kh|Kl|Vh|Vl x 8KB)
#define ATTN_SMEM (65536 + 3 * 32768) // 163840

#define SWZ(row, cu) ((row) * 256 + ((((cu) ^ ((row) & 7))) << 4))

__global__ __launch_bounds__(256) void attn_mma_kernel(
    const __nv_bfloat16* __restrict__ qh, const __nv_bfloat16* __restrict__ ql,
    const __nv_bfloat16* __restrict__ kh, const __nv_bfloat16* __restrict__ kl,
    const __nv_bfloat16* __restrict__ vh, const __nv_bfloat16* __restrict__ vl,
    __nv_bfloat16* __restrict__ outH, __nv_bfloat16* __restrict__ outL)
{
    extern __shared__ char gsm[];
    const uint32_t sb = smem_to_u32(gsm);
    const int tid = threadIdx.x;
    const int w = tid >> 5, l = tid & 31;
    const int qt = blockIdx.x, h = blockIdx.y, b = blockIdx.z;

    const size_t head = ((size_t)(b * NH + h)) * S_LEN * DH;
    const __nv_bfloat16* Qh_g = qh + head + (size_t)qt * ATQ * DH;
    const __nv_bfloat16* Ql_g = ql + head + (size_t)qt * ATQ * DH;

    auto load_kv = [&](int t) {
        const uint32_t st = sb + ASM_KV + (t % 3) * 32768;
        const size_t base = head + (size_t)t * AKT * DH;
        const __nv_bfloat16* srcs[4] = {kh + base, kl + base, vh + base, vl + base};
        #pragma unroll
        for (int a = 0; a < 4; a++) {
            #pragma unroll
            for (int j = 0; j < 2; j++) {
                const int u = tid + 256 * j;
                const int row = u >> 4, cu = u & 15;
                cp_async16(st + a * 8192 + SWZ(row, cu),
                           (const char*)srcs[a] + (size_t)row * 256 + cu * 16);
            }
        }
        CP_COMMIT();
    };

    // Q loads committed together with KV(0) as group 0.
    #pragma unroll
    for (int j = 0; j < 8; j++) {
        const int u = tid + 256 * j;
        const int row = u >> 4, cu = u & 15;
        cp_async16(sb + ASM_QH + SWZ(row, cu),
                   (const char*)Qh_g + (size_t)row * 256 + cu * 16);
        cp_async16(sb + ASM_QL + SWZ(row, cu),
                   (const char*)Ql_g + (size_t)row * 256 + cu * 16);
    }
    load_kv(0);
    load_kv(1);

    // Wait for group 0 (Q + KV0), then cache ALL Q fragments in registers.
    CP_WAIT(1);
    __syncthreads();
    uint32_t qhf[8][4], qlf[8][4];
    #pragma unroll
    for (int kk = 0; kk < 8; kk++) {
        const int row = w * 16 + (l & 15);
        const int cu = kk * 2 + (l >> 4);
        const uint32_t off = SWZ(row, cu);
        ldsm_x4(qhf[kk], sb + ASM_QH + off);
        ldsm_x4(qlf[kk], sb + ASM_QL + off);
    }

    float m0 = -1e9f, m1 = -1e9f, ls0 = 0.f, ls1 = 0.f;
    float O[16][4];
    #pragma unroll
    for (int nt = 0; nt < 16; nt++)
        #pragma unroll
        for (int c = 0; c < 4; c++) O[nt][c] = 0.f;

    for (int t = 0; t < ANT; t++) {
        if (t > 0) {
            if (t + 1 < ANT) { CP_WAIT(1); } else { CP_WAIT(0); }
            __syncthreads();
        }
        if (t + 2 < ANT) load_kv(t + 2);

        const uint32_t stg = sb + ASM_KV + (t % 3) * 32768;

        // ---- QK: sacc[nt][4], warp tile 16x32, Q from registers ------------
        float sacc[4][4];
        #pragma unroll
        for (int nt = 0; nt < 4; nt++)
            #pragma unroll
            for (int c = 0; c < 4; c++) sacc[nt][c] = 0.f;

        #pragma unroll
        for (int kk = 0; kk < 8; kk++) {
            uint32_t khf[2][4], klf[2][4];
            #pragma unroll
            for (int np = 0; np < 2; np++) {
                const int g = l >> 3, idx = l & 7;
                const int krow = np * 16 + ((g >> 1) << 3) + idx;
                const int bcu = kk * 2 + (g & 1);
                const uint32_t off = SWZ(krow, bcu);
                ldsm_x4(khf[np], stg + off);
                ldsm_x4(klf[np], stg + 8192 + off);
            }
            #pragma unroll
            for (int nt = 0; nt < 4; nt++) {
                const uint32_t* bhp = &khf[nt >> 1][(nt & 1) * 2];
                const uint32_t* blp = &klf[nt >> 1][(nt & 1) * 2];
                mma16816(sacc[nt], qhf[kk], bhp);
                mma16816(sacc[nt], qhf[kk], blp);
                mma16816(sacc[nt], qlf[kk], bhp);
            }
        }

        // ---- softmax in registers ------------------------------------------
        float mx0 = sacc[0][0], mx1 = sacc[0][2];
        #pragma unroll
        for (int nt = 0; nt < 4; nt++) {
            mx0 = fmaxf(mx0, fmaxf(sacc[nt][0], sacc[nt][1]));
            mx1 = fmaxf(mx1, fmaxf(sacc[nt][2], sacc[nt][3]));
        }
        mx0 = fmaxf(mx0, __shfl_xor_sync(0xffffffffu, mx0, 1));
        mx0 = fmaxf(mx0, __shfl_xor_sync(0xffffffffu, mx0, 2));
        mx1 = fmaxf(mx1, __shfl_xor_sync(0xffffffffu, mx1, 1));
        mx1 = fmaxf(mx1, __shfl_xor_sync(0xffffffffu, mx1, 2));
        const float mn0 = fmaxf(m0, mx0);
        const float mn1 = fmaxf(m1, mx1);

        uint32_t ph[2][4], pl[2][4];
        float s0 = 0.f, s1 = 0.f;
        #pragma unroll
        for (int nt = 0; nt < 4; nt++) {
            const float p0 = exp2_fast(sacc[nt][0] - mn0);
            const float p1 = exp2_fast(sacc[nt][1] - mn0);
            const float p2 = exp2_fast(sacc[nt][2] - mn1);
            const float p3 = exp2_fast(sacc[nt][3] - mn1);
            s0 += p0 + p1;
            s1 += p2 + p3;
            __nv_bfloat162 lo01, lo23;
            const __nv_bfloat162 h01 = split_hi(p0, p1, lo01);
            const __nv_bfloat162 h23 = split_hi(p2, p3, lo23);
            const int kk = nt >> 1, base = (nt & 1) * 2;
            ph[kk][base]     = b2u(h01);
            ph[kk][base + 1] = b2u(h23);
            pl[kk][base]     = b2u(lo01);
            pl[kk][base + 1] = b2u(lo23);
        }
        s0 += __shfl_xor_sync(0xffffffffu, s0, 1);
        s0 += __shfl_xor_sync(0xffffffffu, s0, 2);
        s1 += __shfl_xor_sync(0xffffffffu, s1, 1);
        s1 += __shfl_xor_sync(0xffffffffu, s1, 2);
        const float f0 = exp2_fast(m0 - mn0);
        const float f1 = exp2_fast(m1 - mn1);
        ls0 = ls0 * f0 + s0;
        ls1 = ls1 * f1 + s1;
        m0 = mn0; m1 = mn1;

        #pragma unroll
        for (int nt = 0; nt < 16; nt++) {
            O[nt][0] *= f0; O[nt][1] *= f0;
            O[nt][2] *= f1; O[nt][3] *= f1;
        }

        // ---- PV: warp tile 16x128, P from registers ------------------------
        const uint32_t sVh = stg + 16384, sVl = stg + 24576;
        #pragma unroll
        for (int kk = 0; kk < 2; kk++) {
            #pragma unroll
            for (int np = 0; np < 8; np++) {
                uint32_t vbh[4], vbl[4];
                const int mat = l >> 3, idx = l & 7;
                const int key = kk * 16 + ((mat & 1) << 3) + idx;
                const int cu = np * 2 + (mat >> 1);
                const uint32_t off = SWZ(key, cu);
                ldsm_x4_t(vbh, sVh + off);
                ldsm_x4_t(vbl, sVl + off);
                #pragma unroll
                for (int half = 0; half < 2; half++) {
                    const int nt = np * 2 + half;
                    mma16816(O[nt], ph[kk], &vbh[half * 2]);
                    mma16816(O[nt], ph[kk], &vbl[half * 2]);
                    mma16816(O[nt], pl[kk], &vbh[half * 2]);
                }
            }
        }
    }

    // ---- epilogue: normalize, split hi/lo, write GEMM2's A -----------------
    const float inv0 = 1.f / ls0;
    const float inv1 = 1.f / ls1;
    const int row0 = qt * ATQ + w * 16 + (l >> 2);
    const size_t s0o = (size_t)(b * S_LEN + row0) * EMB + h * DH;
    #pragma unroll
    for (int nt = 0; nt < 16; nt++) {
        const int col = nt * 8 + ((l & 3) << 1);
        __nv_bfloat162 lo0, lo1;
        const __nv_bfloat162 h0 = split_hi(O[nt][0] * inv0, O[nt][1] * inv0, lo0);
        const __nv_bfloat162 h1 = split_hi(O[nt][2] * inv1, O[nt][3] * inv1, lo1);
        *(__nv_bfloat162*)(outH + s0o + col) = h0;
        *(__nv_bfloat162*)(outL + s0o + col) = lo0;
        *(__nv_bfloat162*)(outH + s0o + (size_t)8 * EMB + col) = h1;
        *(__nv_bfloat162*)(outL + s0o + (size_t)8 * EMB + col) = lo1;
    }
}

// ---------------------------------------------------------------------------
extern "C" void kernel_launch(void* const* d_in, const int* in_sizes, int n_in,
                              void* d_out, int out_size)
{
    (void)in_sizes; (void)n_in; (void)out_size;
    const float* x    = (const float*)d_in[0];
    const float* Wqkv = (const float*)d_in[1];
    const float* bqkv = (const float*)d_in[2];
    const float* Wout = (const float*)d_in[3];
    const float* bout = (const float*)d_in[4];
    float* out = (float*)d_out;

    __nv_bfloat16 *ah, *al, *wqh, *wql, *woh, *wol;
    __nv_bfloat16 *qhp, *qlp, *khp, *klp, *vhp, *vlp;
    cudaGetSymbolAddress((void**)&ah, g_ah);
    cudaGetSymbolAddress((void**)&al, g_al);
    cudaGetSymbolAddress((void**)&wqh, g_wqh);
    cudaGetSymbolAddress((void**)&wql, g_wql);
    cudaGetSymbolAddress((void**)&woh, g_woh);
    cudaGetSymbolAddress((void**)&wol, g_wol);
    cudaGetSymbolAddress((void**)&qhp, g_qh);
    cudaGetSymbolAddress((void**)&qlp, g_ql);
    cudaGetSymbolAddress((void**)&khp, g_kh);
    cudaGetSymbolAddress((void**)&klp, g_kl);
    cudaGetSymbolAddress((void**)&vhp, g_vh);
    cudaGetSymbolAddress((void**)&vlp, g_vl);

    cudaFuncSetAttribute(gemm_mma_kernel,
                         cudaFuncAttributeMaxDynamicSharedMemorySize, GEMM_SMEM);
    cudaFuncSetAttribute(gemm_qkv_kernel,
                         cudaFuncAttributeMaxDynamicSharedMemorySize, GEMM_SMEM);
    cudaFuncSetAttribute(attn_mma_kernel,
                         cudaFuncAttributeMaxDynamicSharedMemorySize, ATTN_SMEM);

    // 0) conversions (inputs only)
    split_kernel<<<2048, 256>>>(x, ah, al, MROWS * EMB);
    transpose_split_kernel<<<dim3((3 * EMB) / 32, GK / 32), dim3(32, 8)>>>(
        Wqkv, wqh, wql, GK, 3 * EMB);
    transpose_split_kernel<<<dim3(EMB / 32, GK / 32), dim3(32, 8)>>>(
        Wout, woh, wol, GK, EMB);

    // 1) qkv projection fused with per-head hi/lo split (Q pre-scaled)
    gemm_qkv_kernel<<<dim3((3 * EMB) / 128, MROWS / 128), 256, GEMM_SMEM>>>(
        ah, al, wqh, wql, bqkv);

    // 2) FA2-style tensor-core attention; writes GEMM2's A (hi/lo) directly
    attn_mma_kernel<<<dim3(S_LEN / ATQ, NH, BATCH), 256, ATTN_SMEM>>>(
        qhp, qlp, khp, klp, vhp, vlp, ah, al);

    // 3) out = attn @ W_out + b_out
    gemm_mma_kernel<<<dim3(EMB / 128, MROWS / 128), 256, GEMM_SMEM>>>(
        EMB, ah, al, woh, wol, bout, out);
}

// round 9
// speedup vs baseline: 4.2540x; 1.1957x over previous
#include <cuda_runtime.h>
#include <cuda_bf16.h>
#include <cuda_fp16.h>
#include <cstdint>

#define S_LEN 2048
#define EMB   2048
#define NH    16
#define DH    128
#define BATCH 2
#define MROWS (BATCH * S_LEN)   // 4096
#define GK    2048              // K for both projection GEMMs

#define LO_SCALE 2048.0f        // 2^11: keeps W-lo residuals in fp16 normal range
#define LO_INV   (1.0f / 2048.0f)

// ---------------------------------------------------------------------------
// Device scratch (no cudaMalloc allowed)
// ---------------------------------------------------------------------------
__device__ __half g_a16[(size_t)MROWS * GK];              // A operand (x, then attn-out), fp16
__device__ __half g_wqh[(size_t)(3 * EMB) * GK];          // W_qkv^T hi fp16
__device__ __half g_wql[(size_t)(3 * EMB) * GK];          // W_qkv^T lo*2^11 fp16
__device__ __half g_woh[(size_t)EMB * GK];
__device__ __half g_wol[(size_t)EMB * GK];
// per-head Q/K/V hi/lo (bf16, 3-term attention unchanged), layout [B, H, S, DH]
#define QKV_ELEMS ((size_t)BATCH * NH * S_LEN * DH)
__device__ __nv_bfloat16 g_qh[QKV_ELEMS];
__device__ __nv_bfloat16 g_ql[QKV_ELEMS];
__device__ __nv_bfloat16 g_kh[QKV_ELEMS];
__device__ __nv_bfloat16 g_kl[QKV_ELEMS];
__device__ __nv_bfloat16 g_vh[QKV_ELEMS];
__device__ __nv_bfloat16 g_vl[QKV_ELEMS];

// ---------------------------------------------------------------------------
// PTX helpers (plain sm_80+ instructions only)
// ---------------------------------------------------------------------------
__device__ __forceinline__ uint32_t smem_to_u32(const void* p) {
    uint32_t a;
    asm("{ .reg .u64 t; cvta.to.shared.u64 t, %1; cvt.u32.u64 %0, t; }"
        : "=r"(a) : "l"(p));
    return a;
}

__device__ __forceinline__ void cp_async16(uint32_t saddr, const void* gaddr) {
    asm volatile("cp.async.cg.shared.global [%0], [%1], 16;"
        :: "r"(saddr), "l"(gaddr) : "memory");
}
#define CP_COMMIT() asm volatile("cp.async.commit_group;" ::: "memory")
#define CP_WAIT(n)  asm volatile("cp.async.wait_group %0;" :: "n"(n) : "memory")

__device__ __forceinline__ void ldsm_x4(uint32_t* r, uint32_t addr) {
    asm volatile("ldmatrix.sync.aligned.m8n8.x4.shared.b16 {%0,%1,%2,%3}, [%4];"
        : "=r"(r[0]), "=r"(r[1]), "=r"(r[2]), "=r"(r[3]) : "r"(addr));
}
__device__ __forceinline__ void ldsm_x4_t(uint32_t* r, uint32_t addr) {
    asm volatile("ldmatrix.sync.aligned.m8n8.x4.trans.shared.b16 {%0,%1,%2,%3}, [%4];"
        : "=r"(r[0]), "=r"(r[1]), "=r"(r[2]), "=r"(r[3]) : "r"(addr));
}

// bf16 MMA (attention)
__device__ __forceinline__ void mma16816(float* d, const uint32_t* a,
                                         const uint32_t* b) {
    asm volatile(
        "mma.sync.aligned.m16n8k16.row.col.f32.bf16.bf16.f32 "
        "{%0,%1,%2,%3}, {%4,%5,%6,%7}, {%8,%9}, {%0,%1,%2,%3};"
        : "+f"(d[0]), "+f"(d[1]), "+f"(d[2]), "+f"(d[3])
        : "r"(a[0]), "r"(a[1]), "r"(a[2]), "r"(a[3]), "r"(b[0]), "r"(b[1]));
}
// fp16 MMA (projection GEMMs)
__device__ __forceinline__ void mma16816h(float* d, const uint32_t* a,
                                          const uint32_t* b) {
    asm volatile(
        "mma.sync.aligned.m16n8k16.row.col.f32.f16.f16.f32 "
        "{%0,%1,%2,%3}, {%4,%5,%6,%7}, {%8,%9}, {%0,%1,%2,%3};"
        : "+f"(d[0]), "+f"(d[1]), "+f"(d[2]), "+f"(d[3])
        : "r"(a[0]), "r"(a[1]), "r"(a[2]), "r"(a[3]), "r"(b[0]), "r"(b[1]));
}

// Fast 2^t on FMA/ALU pipes only (no MUFU, no CVT). |rel err| < 3e-6.
__device__ __forceinline__ float exp2_fast(float t) {
    t = fmaxf(t, -126.0f);
    const float MAGIC = 12582912.0f;          // 2^23 + 2^22
    float z = t + MAGIC;
    int i = __float_as_int(z);
    float r = z - MAGIC;
    float f = t - r;                          // f in [-0.5, 0.5]
    float p = 1.3333558146e-3f;
    p = fmaf(p, f, 9.6181291076e-3f);
    p = fmaf(p, f, 5.5504108664e-2f);
    p = fmaf(p, f, 2.4022650696e-1f);
    p = fmaf(p, f, 6.9314718056e-1f);
    p = fmaf(p, f, 1.0f);
    int eb = (i + (127 - 0x4B400000)) << 23;
    return p * __int_as_float(eb);
}

__device__ __forceinline__ __nv_bfloat162 split_hi(float v0, float v1, __nv_bfloat162& lo) {
    __nv_bfloat162 h;
    h.x = __float2bfloat16(v0);
    h.y = __float2bfloat16(v1);
    lo.x = __float2bfloat16(v0 - __bfloat162float(h.x));
    lo.y = __float2bfloat16(v1 - __bfloat162float(h.y));
    return h;
}
__device__ __forceinline__ uint32_t b2u(__nv_bfloat162 v) {
    return *(uint32_t*)&v;
}

// ---------------------------------------------------------------------------
// Conversion kernels
// ---------------------------------------------------------------------------
__global__ __launch_bounds__(256) void to_half_kernel(
    const float* __restrict__ in, __half* __restrict__ out, int n)
{
    int i = blockIdx.x * blockDim.x + threadIdx.x;
    int stride = gridDim.x * blockDim.x;
    for (; i < n; i += stride) out[i] = __float2half(in[i]);
}

// W[K,N] row-major -> T[N,K] fp16 hi + scaled lo
__global__ __launch_bounds__(256) void transpose_split_kernel(
    const float* __restrict__ W, __half* __restrict__ Th,
    __half* __restrict__ Tl, int K, int N)
{
    __shared__ float t[32][33];
    const int nb = blockIdx.x * 32;
    const int kb = blockIdx.y * 32;
    const int x = threadIdx.x, y = threadIdx.y;   // block (32,8)
    #pragma unroll
    for (int j = 0; j < 32; j += 8)
        t[y + j][x] = W[(size_t)(kb + y + j) * N + nb + x];
    __syncthreads();
    #pragma unroll
    for (int j = 0; j < 32; j += 8) {
        float v = t[x][y + j];
        __half h = __float2half(v);
        size_t o = (size_t)(nb + y + j) * K + kb + x;
        Th[o] = h;
        Tl[o] = __float2half((v - __half2float(h)) * LO_SCALE);
    }
}

// ---------------------------------------------------------------------------
// fp16 2-term HMMA mainloop (R3 geometry: block 128x128, 8 warps, K-chunk 64,
// 2-stage double buffer). C = A*Bh^T + (A*Bl^T)*2^-11 + bias.
// 3 smem tiles per stage (A, Bh, Bl) = 48 KB; 96 KB total.
// ---------------------------------------------------------------------------
#define GBK   64
#define NCHUNK (GK / GBK)
#define TBYTES 16384
#define STAGE  (3 * TBYTES)          // 48 KB
#define GEMM_SMEM (2 * STAGE)        // 96 KB

template <typename Epilogue>
__device__ __forceinline__ void gemm_mainloop(
    char* gsm,
    const __half* __restrict__ A,
    const __half* __restrict__ Bh, const __half* __restrict__ Bl,
    const float* __restrict__ bias, int bx, int by, Epilogue epi)
{
    const uint32_t sb = smem_to_u32(gsm);
    const int tid = threadIdx.x;
    const int w = tid >> 5, l = tid & 31;
    const int warp_m = w >> 2, warp_n = w & 3;

    const __half* srcs[3] = {
        A  + (size_t)(by * 128) * GK,
        Bh + (size_t)(bx * 128) * GK,
        Bl + (size_t)(bx * 128) * GK };

    float acc[4][4][4];     // hi term + bias
    float acc2[4][4][4];    // scaled lo term
    #pragma unroll
    for (int nt = 0; nt < 4; nt++) {
        const int n = bx * 128 + warp_n * 32 + nt * 8 + ((l & 3) << 1);
        const float b0 = bias[n], b1 = bias[n + 1];
        #pragma unroll
        for (int mt = 0; mt < 4; mt++) {
            acc[mt][nt][0] = b0; acc[mt][nt][1] = b1;
            acc[mt][nt][2] = b0; acc[mt][nt][3] = b1;
            acc2[mt][nt][0] = 0.f; acc2[mt][nt][1] = 0.f;
            acc2[mt][nt][2] = 0.f; acc2[mt][nt][3] = 0.f;
        }
    }

    auto load_chunk = [&](int kt) {
        const uint32_t st = sb + (kt & 1) * STAGE;
        const size_t kofs = (size_t)kt * GBK;
        #pragma unroll
        for (int a = 0; a < 3; a++) {
            const char* g = (const char*)(srcs[a] + kofs);
            #pragma unroll
            for (int j = 0; j < 4; j++) {
                const int u = tid + 256 * j;
                const int r = u >> 3;
                const int cu = u & 7;
                const uint32_t off = r * 128 + ((cu ^ (r & 7)) << 4);
                cp_async16(st + a * TBYTES + off,
                           g + (size_t)r * (GK * 2) + (cu << 4));
            }
        }
        CP_COMMIT();
    };

    load_chunk(0);

    for (int kt = 0; kt < NCHUNK; kt++) {
        if (kt + 1 < NCHUNK) { load_chunk(kt + 1); CP_WAIT(1); }
        else                 { CP_WAIT(0); }
        __syncthreads();

        const uint32_t st = sb + (kt & 1) * STAGE;
        const uint32_t sA  = st;
        const uint32_t sBh = st + TBYTES, sBl = st + 2 * TBYTES;

        #pragma unroll
        for (int kk = 0; kk < 4; kk++) {
            const int kb = kk * 32;

            uint32_t af[4][4];
            #pragma unroll
            for (int mt = 0; mt < 4; mt++) {
                const int row = warp_m * 64 + mt * 16 + (l & 15);
                const int bc = kb + ((l >> 4) << 4);
                const uint32_t off = row * 128 + (bc ^ ((row & 7) << 4));
                ldsm_x4(af[mt], sA + off);
            }

            uint32_t bh[2][4], bl[2][4];
            #pragma unroll
            for (int np = 0; np < 2; np++) {
                const int g = l >> 3, idx = l & 7;
                const int row = warp_n * 32 + np * 16 + ((g >> 1) << 3) + idx;
                const int bc = kb + ((g & 1) << 4);
                const uint32_t off = row * 128 + (bc ^ ((row & 7) << 4));
                ldsm_x4(bh[np], sBh + off);
                ldsm_x4(bl[np], sBl + off);
            }

            #pragma unroll
            for (int mt = 0; mt < 4; mt++)
                #pragma unroll
                for (int nt = 0; nt < 4; nt++) {
                    const uint32_t* bhp = &bh[nt >> 1][(nt & 1) * 2];
                    const uint32_t* blp = &bl[nt >> 1][(nt & 1) * 2];
                    mma16816h(acc[mt][nt],  af[mt], bhp);
                    mma16816h(acc2[mt][nt], af[mt], blp);
                }
        }
        __syncthreads();
    }

    // merge scaled lo term
    #pragma unroll
    for (int mt = 0; mt < 4; mt++)
        #pragma unroll
        for (int nt = 0; nt < 4; nt++)
            #pragma unroll
            for (int c = 0; c < 4; c++)
                acc[mt][nt][c] = fmaf(acc2[mt][nt][c], LO_INV, acc[mt][nt][c]);

    epi(acc, warp_m, warp_n, l);
}

// GEMM2: plain fp32 output C = A*B^T + bias
__global__ __launch_bounds__(256) void gemm_mma_kernel(
    int N,
    const __half* __restrict__ A,
    const __half* __restrict__ Bh, const __half* __restrict__ Bl,
    const float* __restrict__ bias, float* __restrict__ C)
{
    extern __shared__ char gsm[];
    const int bx = blockIdx.x, by = blockIdx.y;
    gemm_mainloop(gsm, A, Bh, Bl, bias, bx, by,
        [&](float acc[4][4][4], int warp_m, int warp_n, int l) {
            #pragma unroll
            for (int mt = 0; mt < 4; mt++) {
                const int m = by * 128 + warp_m * 64 + mt * 16 + (l >> 2);
                float* c0 = C + (size_t)m * N + bx * 128 + warp_n * 32 + ((l & 3) << 1);
                #pragma unroll
                for (int nt = 0; nt < 4; nt++) {
                    *(float2*)(c0 + nt * 8) =
                        make_float2(acc[mt][nt][0], acc[mt][nt][1]);
                    *(float2*)(c0 + (size_t)8 * N + nt * 8) =
                        make_float2(acc[mt][nt][2], acc[mt][nt][3]);
                }
            }
        });
}

// GEMM1 fused: writes per-head Q/K/V hi/lo bf16 directly (attention operands).
__global__ __launch_bounds__(256) void gemm_qkv_kernel(
    const __half* __restrict__ A,
    const __half* __restrict__ Bh, const __half* __restrict__ Bl,
    const float* __restrict__ bias)
{
    extern __shared__ char gsm[];
    const int bx = blockIdx.x, by = blockIdx.y;
    const int region = bx % 3;        // 0=q, 1=k, 2=v
    const int head   = bx / 3;
    __nv_bfloat16* H = (region == 0) ? g_qh : (region == 1) ? g_kh : g_vh;
    __nv_bfloat16* L = (region == 0) ? g_ql : (region == 1) ? g_kl : g_vl;
    const float scl = (region == 0) ? 0.12751744f : 1.0f;  // log2(e)/sqrt(128)

    gemm_mainloop(gsm, A, Bh, Bl, bias, bx, by,
        [&](float acc[4][4][4], int warp_m, int warp_n, int l) {
            #pragma unroll
            for (int mt = 0; mt < 4; mt++) {
                const int m = by * 128 + warp_m * 64 + mt * 16 + (l >> 2);
                const int b = m >> 11, s = m & (S_LEN - 1);
                const size_t base =
                    (((size_t)(b * NH + head)) * S_LEN + s) * DH;
                #pragma unroll
                for (int nt = 0; nt < 4; nt++) {
                    const int d = warp_n * 32 + nt * 8 + ((l & 3) << 1);
                    __nv_bfloat162 lo0, lo1;
                    __nv_bfloat162 h0 = split_hi(acc[mt][nt][0] * scl,
                                                 acc[mt][nt][1] * scl, lo0);
                    __nv_bfloat162 h1 = split_hi(acc[mt][nt][2] * scl,
                                                 acc[mt][nt][3] * scl, lo1);
                    *(__nv_bfloat162*)(H + base + d) = h0;
                    *(__nv_bfloat162*)(L + base + d) = lo0;
                    *(__nv_bfloat162*)(H + base + (size_t)8 * DH + d) = h1;
                    *(__nv_bfloat162*)(L + base + (size_t)8 * DH + d) = lo1;
                }
            }
        });
}

// ---------------------------------------------------------------------------
// FA2-style tensor-core attention (bf16 3-term, unchanged core).
// Epilogue writes GEMM2's A operand as a SINGLE fp16 array.
// ---------------------------------------------------------------------------
#define ATQ 128
#define AKT 32
#define ANT (S_LEN / AKT)

#define ASM_QH 0
#define ASM_QL 32768
#define ASM_KV 65536                  // 3 stages x 32768 (Kh|Kl|Vh|Vl x 8KB)
#define ATTN_SMEM (65536 + 3 * 32768) // 163840

#define SWZ(row, cu) ((row) * 256 + ((((cu) ^ ((row) & 7))) << 4))

__global__ __launch_bounds__(256) void attn_mma_kernel(
    const __nv_bfloat16* __restrict__ qh, const __nv_bfloat16* __restrict__ ql,
    const __nv_bfloat16* __restrict__ kh, const __nv_bfloat16* __restrict__ kl,
    const __nv_bfloat16* __restrict__ vh, const __nv_bfloat16* __restrict__ vl,
    __half* __restrict__ outA)
{
    extern __shared__ char gsm[];
    const uint32_t sb = smem_to_u32(gsm);
    const int tid = threadIdx.x;
    const int w = tid >> 5, l = tid & 31;
    const int qt = blockIdx.x, h = blockIdx.y, b = blockIdx.z;

    const size_t head = ((size_t)(b * NH + h)) * S_LEN * DH;
    const __nv_bfloat16* Qh_g = qh + head + (size_t)qt * ATQ * DH;
    const __nv_bfloat16* Ql_g = ql + head + (size_t)qt * ATQ * DH;

    auto load_kv = [&](int t) {
        const uint32_t st = sb + ASM_KV + (t % 3) * 32768;
        const size_t base = head + (size_t)t * AKT * DH;
        const __nv_bfloat16* srcs[4] = {kh + base, kl + base, vh + base, vl + base};
        #pragma unroll
        for (int a = 0; a < 4; a++) {
            #pragma unroll
            for (int j = 0; j < 2; j++) {
                const int u = tid + 256 * j;
                const int row = u >> 4, cu = u & 15;
                cp_async16(st + a * 8192 + SWZ(row, cu),
                           (const char*)srcs[a] + (size_t)row * 256 + cu * 16);
            }
        }
        CP_COMMIT();
    };

    // Q loads committed together with KV(0) as group 0.
    #pragma unroll
    for (int j = 0; j < 8; j++) {
        const int u = tid + 256 * j;
        const int row = u >> 4, cu = u & 15;
        cp_async16(sb + ASM_QH + SWZ(row, cu),
                   (const char*)Qh_g + (size_t)row * 256 + cu * 16);
        cp_async16(sb + ASM_QL + SWZ(row, cu),
                   (const char*)Ql_g + (size_t)row * 256 + cu * 16);
    }
    load_kv(0);
    load_kv(1);

    // Wait for group 0 (Q + KV0), then cache ALL Q fragments in registers.
    CP_WAIT(1);
    __syncthreads();
    uint32_t qhf[8][4], qlf[8][4];
    #pragma unroll
    for (int kk = 0; kk < 8; kk++) {
        const int row = w * 16 + (l & 15);
        const int cu = kk * 2 + (l >> 4);
        const uint32_t off = SWZ(row, cu);
        ldsm_x4(qhf[kk], sb + ASM_QH + off);
        ldsm_x4(qlf[kk], sb + ASM_QL + off);
    }

    float m0 = -1e9f, m1 = -1e9f, ls0 = 0.f, ls1 = 0.f;
    float O[16][4];
    #pragma unroll
    for (int nt = 0; nt < 16; nt++)
        #pragma unroll
        for (int c = 0; c < 4; c++) O[nt][c] = 0.f;

    for (int t = 0; t < ANT; t++) {
        if (t > 0) {
            if (t + 1 < ANT) { CP_WAIT(1); } else { CP_WAIT(0); }
            __syncthreads();
        }
        if (t + 2 < ANT) load_kv(t + 2);

        const uint32_t stg = sb + ASM_KV + (t % 3) * 32768;

        // ---- QK: sacc[nt][4], warp tile 16x32, Q from registers ------------
        float sacc[4][4];
        #pragma unroll
        for (int nt = 0; nt < 4; nt++)
            #pragma unroll
            for (int c = 0; c < 4; c++) sacc[nt][c] = 0.f;

        #pragma unroll
        for (int kk = 0; kk < 8; kk++) {
            uint32_t khf[2][4], klf[2][4];
            #pragma unroll
            for (int np = 0; np < 2; np++) {
                const int g = l >> 3, idx = l & 7;
                const int krow = np * 16 + ((g >> 1) << 3) + idx;
                const int bcu = kk * 2 + (g & 1);
                const uint32_t off = SWZ(krow, bcu);
                ldsm_x4(khf[np], stg + off);
                ldsm_x4(klf[np], stg + 8192 + off);
            }
            #pragma unroll
            for (int nt = 0; nt < 4; nt++) {
                const uint32_t* bhp = &khf[nt >> 1][(nt & 1) * 2];
                const uint32_t* blp = &klf[nt >> 1][(nt & 1) * 2];
                mma16816(sacc[nt], qhf[kk], bhp);
                mma16816(sacc[nt], qhf[kk], blp);
                mma16816(sacc[nt], qlf[kk], bhp);
            }
        }

        // ---- softmax in registers ------------------------------------------
        float mx0 = sacc[0][0], mx1 = sacc[0][2];
        #pragma unroll
        for (int nt = 0; nt < 4; nt++) {
            mx0 = fmaxf(mx0, fmaxf(sacc[nt][0], sacc[nt][1]));
            mx1 = fmaxf(mx1, fmaxf(sacc[nt][2], sacc[nt][3]));
        }
        mx0 = fmaxf(mx0, __shfl_xor_sync(0xffffffffu, mx0, 1));
        mx0 = fmaxf(mx0, __shfl_xor_sync(0xffffffffu, mx0, 2));
        mx1 = fmaxf(mx1, __shfl_xor_sync(0xffffffffu, mx1, 1));
        mx1 = fmaxf(mx1, __shfl_xor_sync(0xffffffffu, mx1, 2));
        const float mn0 = fmaxf(m0, mx0);
        const float mn1 = fmaxf(m1, mx1);

        uint32_t ph[2][4], pl[2][4];
        float s0 = 0.f, s1 = 0.f;
        #pragma unroll
        for (int nt = 0; nt < 4; nt++) {
            const float p0 = exp2_fast(sacc[nt][0] - mn0);
            const float p1 = exp2_fast(sacc[nt][1] - mn0);
            const float p2 = exp2_fast(sacc[nt][2] - mn1);
            const float p3 = exp2_fast(sacc[nt][3] - mn1);
            s0 += p0 + p1;
            s1 += p2 + p3;
            __nv_bfloat162 lo01, lo23;
            const __nv_bfloat162 h01 = split_hi(p0, p1, lo01);
            const __nv_bfloat162 h23 = split_hi(p2, p3, lo23);
            const int kk = nt >> 1, base = (nt & 1) * 2;
            ph[kk][base]     = b2u(h01);
            ph[kk][base + 1] = b2u(h23);
            pl[kk][base]     = b2u(lo01);
            pl[kk][base + 1] = b2u(lo23);
        }
        s0 += __shfl_xor_sync(0xffffffffu, s0, 1);
        s0 += __shfl_xor_sync(0xffffffffu, s0, 2);
        s1 += __shfl_xor_sync(0xffffffffu, s1, 1);
        s1 += __shfl_xor_sync(0xffffffffu, s1, 2);
        const float f0 = exp2_fast(m0 - mn0);
        const float f1 = exp2_fast(m1 - mn1);
        ls0 = ls0 * f0 + s0;
        ls1 = ls1 * f1 + s1;
        m0 = mn0; m1 = mn1;

        #pragma unroll
        for (int nt = 0; nt < 16; nt++) {
            O[nt][0] *= f0; O[nt][1] *= f0;
            O[nt][2] *= f1; O[nt][3] *= f1;
        }

        // ---- PV: warp tile 16x128, P from registers ------------------------
        const uint32_t sVh = stg + 16384, sVl = stg + 24576;
        #pragma unroll
        for (int kk = 0; kk < 2; kk++) {
            #pragma unroll
            for (int np = 0; np < 8; np++) {
                uint32_t vbh[4], vbl[4];
                const int mat = l >> 3, idx = l & 7;
                const int key = kk * 16 + ((mat & 1) << 3) + idx;
                const int cu = np * 2 + (mat >> 1);
                const uint32_t off = SWZ(key, cu);
                ldsm_x4_t(vbh, sVh + off);
                ldsm_x4_t(vbl, sVl + off);
                #pragma unroll
                for (int half = 0; half < 2; half++) {
                    const int nt = np * 2 + half;
                    mma16816(O[nt], ph[kk], &vbh[half * 2]);
                    mma16816(O[nt], ph[kk], &vbl[half * 2]);
                    mma16816(O[nt], pl[kk], &vbh[half * 2]);
                }
            }
        }
    }

    // ---- epilogue: normalize, write GEMM2's A (single fp16) ---------------
    const float inv0 = 1.f / ls0;
    const float inv1 = 1.f / ls1;
    const int row0 = qt * ATQ + w * 16 + (l >> 2);
    const size_t s0o = (size_t)(b * S_LEN + row0) * EMB + h * DH;
    #pragma unroll
    for (int nt = 0; nt < 16; nt++) {
        const int col = nt * 8 + ((l & 3) << 1);
        const __half2 h0 = __floats2half2_rn(O[nt][0] * inv0, O[nt][1] * inv0);
        const __half2 h1 = __floats2half2_rn(O[nt][2] * inv1, O[nt][3] * inv1);
        *(__half2*)(outA + s0o + col) = h0;
        *(__half2*)(outA + s0o + (size_t)8 * EMB + col) = h1;
    }
}

// ---------------------------------------------------------------------------
extern "C" void kernel_launch(void* const* d_in, const int* in_sizes, int n_in,
                              void* d_out, int out_size)
{
    (void)in_sizes; (void)n_in; (void)out_size;
    const float* x    = (const float*)d_in[0];
    const float* Wqkv = (const float*)d_in[1];
    const float* bqkv = (const float*)d_in[2];
    const float* Wout = (const float*)d_in[3];
    const float* bout = (const float*)d_in[4];
    float* out = (float*)d_out;

    __half *a16, *wqh, *wql, *woh, *wol;
    __nv_bfloat16 *qhp, *qlp, *khp, *klp, *vhp, *vlp;
    cudaGetSymbolAddress((void**)&a16, g_a16);
    cudaGetSymbolAddress((void**)&wqh, g_wqh);
    cudaGetSymbolAddress((void**)&wql, g_wql);
    cudaGetSymbolAddress((void**)&woh, g_woh);
    cudaGetSymbolAddress((void**)&wol, g_wol);
    cudaGetSymbolAddress((void**)&qhp, g_qh);
    cudaGetSymbolAddress((void**)&qlp, g_ql);
    cudaGetSymbolAddress((void**)&khp, g_kh);
    cudaGetSymbolAddress((void**)&klp, g_kl);
    cudaGetSymbolAddress((void**)&vhp, g_vh);
    cudaGetSymbolAddress((void**)&vlp, g_vl);

    cudaFuncSetAttribute(gemm_mma_kernel,
                         cudaFuncAttributeMaxDynamicSharedMemorySize, GEMM_SMEM);
    cudaFuncSetAttribute(gemm_qkv_kernel,
                         cudaFuncAttributeMaxDynamicSharedMemorySize, GEMM_SMEM);
    cudaFuncSetAttribute(attn_mma_kernel,
                         cudaFuncAttributeMaxDynamicSharedMemorySize, ATTN_SMEM);

    // 0) conversions (inputs only)
    to_half_kernel<<<2048, 256>>>(x, a16, MROWS * EMB);
    transpose_split_kernel<<<dim3((3 * EMB) / 32, GK / 32), dim3(32, 8)>>>(
        Wqkv, wqh, wql, GK, 3 * EMB);
    transpose_split_kernel<<<dim3(EMB / 32, GK / 32), dim3(32, 8)>>>(
        Wout, woh, wol, GK, EMB);

    // 1) qkv projection (fp16 2-term) fused with per-head bf16 hi/lo split
    gemm_qkv_kernel<<<dim3((3 * EMB) / 128, MROWS / 128), 256, GEMM_SMEM>>>(
        a16, wqh, wql, bqkv);

    // 2) FA2-style tensor-core attention (bf16 3-term); writes GEMM2's A (fp16)
    attn_mma_kernel<<<dim3(S_LEN / ATQ, NH, BATCH), 256, ATTN_SMEM>>>(
        qhp, qlp, khp, klp, vhp, vlp, a16);

    // 3) out = attn @ W_out + b_out  (fp16 2-term)
    gemm_mma_kernel<<<dim3(EMB / 128, MROWS / 128), 256, GEMM_SMEM>>>(
        EMB, a16, woh, wol, bout, out);
}

// round 10
// speedup vs baseline: 4.6608x; 1.0956x over previous
#include <cuda_runtime.h>
#include <cuda_bf16.h>
#include <cuda_fp16.h>
#include <cstdint>

#define S_LEN 2048
#define EMB   2048
#define NH    16
#define DH    128
#define BATCH 2
#define MROWS (BATCH * S_LEN)   // 4096
#define GK    2048              // K for both projection GEMMs

#define LO_SCALE 2048.0f        // 2^11: keeps W-lo residuals in fp16 normal range
#define LO_INV   (1.0f / 2048.0f)

// ---------------------------------------------------------------------------
// Device scratch (no cudaMalloc allowed)
// ---------------------------------------------------------------------------
__device__ __half g_a16[(size_t)MROWS * GK];              // A operand (x, then attn-out), fp16
__device__ __half g_wqh[(size_t)(3 * EMB) * GK];          // W_qkv^T hi fp16
__device__ __half g_wql[(size_t)(3 * EMB) * GK];          // W_qkv^T lo*2^11 fp16
__device__ __half g_woh[(size_t)EMB * GK];
__device__ __half g_wol[(size_t)EMB * GK];
// per-head Q/K/V (fp16 2-term attention), layout [B, H, S, DH]
// Q split unscaled (qh+ql, residual ~4e-4 = normal fp16); K single; V split unscaled.
#define QKV_ELEMS ((size_t)BATCH * NH * S_LEN * DH)
__device__ __half g_q16h[QKV_ELEMS];
__device__ __half g_q16l[QKV_ELEMS];
__device__ __half g_k16[QKV_ELEMS];
__device__ __half g_v16h[QKV_ELEMS];
__device__ __half g_v16l[QKV_ELEMS];

// ---------------------------------------------------------------------------
// PTX helpers (plain sm_80+ instructions only)
// ---------------------------------------------------------------------------
__device__ __forceinline__ uint32_t smem_to_u32(const void* p) {
    uint32_t a;
    asm("{ .reg .u64 t; cvta.to.shared.u64 t, %1; cvt.u32.u64 %0, t; }"
        : "=r"(a) : "l"(p));
    return a;
}

__device__ __forceinline__ void cp_async16(uint32_t saddr, const void* gaddr) {
    asm volatile("cp.async.cg.shared.global [%0], [%1], 16;"
        :: "r"(saddr), "l"(gaddr) : "memory");
}
#define CP_COMMIT() asm volatile("cp.async.commit_group;" ::: "memory")
#define CP_WAIT(n)  asm volatile("cp.async.wait_group %0;" :: "n"(n) : "memory")

__device__ __forceinline__ void ldsm_x4(uint32_t* r, uint32_t addr) {
    asm volatile("ldmatrix.sync.aligned.m8n8.x4.shared.b16 {%0,%1,%2,%3}, [%4];"
        : "=r"(r[0]), "=r"(r[1]), "=r"(r[2]), "=r"(r[3]) : "r"(addr));
}
__device__ __forceinline__ void ldsm_x4_t(uint32_t* r, uint32_t addr) {
    asm volatile("ldmatrix.sync.aligned.m8n8.x4.trans.shared.b16 {%0,%1,%2,%3}, [%4];"
        : "=r"(r[0]), "=r"(r[1]), "=r"(r[2]), "=r"(r[3]) : "r"(addr));
}

// fp16 MMA (all tensor work)
__device__ __forceinline__ void mma16816h(float* d, const uint32_t* a,
                                          const uint32_t* b) {
    asm volatile(
        "mma.sync.aligned.m16n8k16.row.col.f32.f16.f16.f32 "
        "{%0,%1,%2,%3}, {%4,%5,%6,%7}, {%8,%9}, {%0,%1,%2,%3};"
        : "+f"(d[0]), "+f"(d[1]), "+f"(d[2]), "+f"(d[3])
        : "r"(a[0]), "r"(a[1]), "r"(a[2]), "r"(a[3]), "r"(b[0]), "r"(b[1]));
}

// Fast 2^t on FMA/ALU pipes only (no MUFU, no CVT). |rel err| < 3e-6.
__device__ __forceinline__ float exp2_fast(float t) {
    t = fmaxf(t, -126.0f);
    const float MAGIC = 12582912.0f;          // 2^23 + 2^22
    float z = t + MAGIC;
    int i = __float_as_int(z);
    float r = z - MAGIC;
    float f = t - r;                          // f in [-0.5, 0.5]
    float p = 1.3333558146e-3f;
    p = fmaf(p, f, 9.6181291076e-3f);
    p = fmaf(p, f, 5.5504108664e-2f);
    p = fmaf(p, f, 2.4022650696e-1f);
    p = fmaf(p, f, 6.9314718056e-1f);
    p = fmaf(p, f, 1.0f);
    int eb = (i + (127 - 0x4B400000)) << 23;
    return p * __int_as_float(eb);
}

__device__ __forceinline__ __half2 split_hi_h(float v0, float v1, __half2& lo) {
    __half2 h;
    h.x = __float2half(v0);
    h.y = __float2half(v1);
    lo.x = __float2half(v0 - __half2float(h.x));
    lo.y = __float2half(v1 - __half2float(h.y));
    return h;
}
__device__ __forceinline__ uint32_t h2u(__half2 v) {
    return *(uint32_t*)&v;
}

// ---------------------------------------------------------------------------
// Conversion kernels
// ---------------------------------------------------------------------------
__global__ __launch_bounds__(256) void to_half_kernel(
    const float* __restrict__ in, __half* __restrict__ out, int n)
{
    int i = blockIdx.x * blockDim.x + threadIdx.x;
    int stride = gridDim.x * blockDim.x;
    for (; i < n; i += stride) out[i] = __float2half(in[i]);
}

// W[K,N] row-major -> T[N,K] fp16 hi + scaled lo
__global__ __launch_bounds__(256) void transpose_split_kernel(
    const float* __restrict__ W, __half* __restrict__ Th,
    __half* __restrict__ Tl, int K, int N)
{
    __shared__ float t[32][33];
    const int nb = blockIdx.x * 32;
    const int kb = blockIdx.y * 32;
    const int x = threadIdx.x, y = threadIdx.y;   // block (32,8)
    #pragma unroll
    for (int j = 0; j < 32; j += 8)
        t[y + j][x] = W[(size_t)(kb + y + j) * N + nb + x];
    __syncthreads();
    #pragma unroll
    for (int j = 0; j < 32; j += 8) {
        float v = t[x][y + j];
        __half h = __float2half(v);
        size_t o = (size_t)(nb + y + j) * K + kb + x;
        Th[o] = h;
        Tl[o] = __float2half((v - __half2float(h)) * LO_SCALE);
    }
}

// ---------------------------------------------------------------------------
// fp16 2-term HMMA mainloop (unchanged from R9).
// C = A*Bh^T + (A*Bl^T)*2^-11 + bias. Block 128x128, 8 warps, K-chunk 64.
// ---------------------------------------------------------------------------
#define GBK   64
#define NCHUNK (GK / GBK)
#define TBYTES 16384
#define STAGE  (3 * TBYTES)          // 48 KB
#define GEMM_SMEM (2 * STAGE)        // 96 KB

template <typename Epilogue>
__device__ __forceinline__ void gemm_mainloop(
    char* gsm,
    const __half* __restrict__ A,
    const __half* __restrict__ Bh, const __half* __restrict__ Bl,
    const float* __restrict__ bias, int bx, int by, Epilogue epi)
{
    const uint32_t sb = smem_to_u32(gsm);
    const int tid = threadIdx.x;
    const int w = tid >> 5, l = tid & 31;
    const int warp_m = w >> 2, warp_n = w & 3;

    const __half* srcs[3] = {
        A  + (size_t)(by * 128) * GK,
        Bh + (size_t)(bx * 128) * GK,
        Bl + (size_t)(bx * 128) * GK };

    float acc[4][4][4];     // hi term + bias
    float acc2[4][4][4];    // scaled lo term
    #pragma unroll
    for (int nt = 0; nt < 4; nt++) {
        const int n = bx * 128 + warp_n * 32 + nt * 8 + ((l & 3) << 1);
        const float b0 = bias[n], b1 = bias[n + 1];
        #pragma unroll
        for (int mt = 0; mt < 4; mt++) {
            acc[mt][nt][0] = b0; acc[mt][nt][1] = b1;
            acc[mt][nt][2] = b0; acc[mt][nt][3] = b1;
            acc2[mt][nt][0] = 0.f; acc2[mt][nt][1] = 0.f;
            acc2[mt][nt][2] = 0.f; acc2[mt][nt][3] = 0.f;
        }
    }

    auto load_chunk = [&](int kt) {
        const uint32_t st = sb + (kt & 1) * STAGE;
        const size_t kofs = (size_t)kt * GBK;
        #pragma unroll
        for (int a = 0; a < 3; a++) {
            const char* g = (const char*)(srcs[a] + kofs);
            #pragma unroll
            for (int j = 0; j < 4; j++) {
                const int u = tid + 256 * j;
                const int r = u >> 3;
                const int cu = u & 7;
                const uint32_t off = r * 128 + ((cu ^ (r & 7)) << 4);
                cp_async16(st + a * TBYTES + off,
                           g + (size_t)r * (GK * 2) + (cu << 4));
            }
        }
        CP_COMMIT();
    };

    load_chunk(0);

    for (int kt = 0; kt < NCHUNK; kt++) {
        if (kt + 1 < NCHUNK) { load_chunk(kt + 1); CP_WAIT(1); }
        else                 { CP_WAIT(0); }
        __syncthreads();

        const uint32_t st = sb + (kt & 1) * STAGE;
        const uint32_t sA  = st;
        const uint32_t sBh = st + TBYTES, sBl = st + 2 * TBYTES;

        #pragma unroll
        for (int kk = 0; kk < 4; kk++) {
            const int kb = kk * 32;

            uint32_t af[4][4];
            #pragma unroll
            for (int mt = 0; mt < 4; mt++) {
                const int row = warp_m * 64 + mt * 16 + (l & 15);
                const int bc = kb + ((l >> 4) << 4);
                const uint32_t off = row * 128 + (bc ^ ((row & 7) << 4));
                ldsm_x4(af[mt], sA + off);
            }

            uint32_t bh[2][4], bl[2][4];
            #pragma unroll
            for (int np = 0; np < 2; np++) {
                const int g = l >> 3, idx = l & 7;
                const int row = warp_n * 32 + np * 16 + ((g >> 1) << 3) + idx;
                const int bc = kb + ((g & 1) << 4);
                const uint32_t off = row * 128 + (bc ^ ((row & 7) << 4));
                ldsm_x4(bh[np], sBh + off);
                ldsm_x4(bl[np], sBl + off);
            }

            #pragma unroll
            for (int mt = 0; mt < 4; mt++)
                #pragma unroll
                for (int nt = 0; nt < 4; nt++) {
                    const uint32_t* bhp = &bh[nt >> 1][(nt & 1) * 2];
                    const uint32_t* blp = &bl[nt >> 1][(nt & 1) * 2];
                    mma16816h(acc[mt][nt],  af[mt], bhp);
                    mma16816h(acc2[mt][nt], af[mt], blp);
                }
        }
        __syncthreads();
    }

    // merge scaled lo term
    #pragma unroll
    for (int mt = 0; mt < 4; mt++)
        #pragma unroll
        for (int nt = 0; nt < 4; nt++)
            #pragma unroll
            for (int c = 0; c < 4; c++)
                acc[mt][nt][c] = fmaf(acc2[mt][nt][c], LO_INV, acc[mt][nt][c]);

    epi(acc, warp_m, warp_n, l);
}

// GEMM2: plain fp32 output C = A*B^T + bias
__global__ __launch_bounds__(256) void gemm_mma_kernel(
    int N,
    const __half* __restrict__ A,
    const __half* __restrict__ Bh, const __half* __restrict__ Bl,
    const float* __restrict__ bias, float* __restrict__ C)
{
    extern __shared__ char gsm[];
    const int bx = blockIdx.x, by = blockIdx.y;
    gemm_mainloop(gsm, A, Bh, Bl, bias, bx, by,
        [&](float acc[4][4][4], int warp_m, int warp_n, int l) {
            #pragma unroll
            for (int mt = 0; mt < 4; mt++) {
                const int m = by * 128 + warp_m * 64 + mt * 16 + (l >> 2);
                float* c0 = C + (size_t)m * N + bx * 128 + warp_n * 32 + ((l & 3) << 1);
                #pragma unroll
                for (int nt = 0; nt < 4; nt++) {
                    *(float2*)(c0 + nt * 8) =
                        make_float2(acc[mt][nt][0], acc[mt][nt][1]);
                    *(float2*)(c0 + (size_t)8 * N + nt * 8) =
                        make_float2(acc[mt][nt][2], acc[mt][nt][3]);
                }
            }
        });
}

// GEMM1 fused: writes per-head fp16 Q (split) / K (single) / V (split).
// Q/K/V stored UNSCALED (raw activations) — softmax scale applied on scores.
__global__ __launch_bounds__(256) void gemm_qkv_kernel(
    const __half* __restrict__ A,
    const __half* __restrict__ Bh, const __half* __restrict__ Bl,
    const float* __restrict__ bias)
{
    extern __shared__ char gsm[];
    const int bx = blockIdx.x, by = blockIdx.y;
    const int region = bx % 3;        // 0=q, 1=k, 2=v
    const int head   = bx / 3;
    __half* H = (region == 0) ? g_q16h : (region == 1) ? g_k16 : g_v16h;
    __half* L = (region == 0) ? g_q16l : (region == 1) ? (__half*)nullptr : g_v16l;
    const bool has_lo = (region != 1);

    gemm_mainloop(gsm, A, Bh, Bl, bias, bx, by,
        [&](float acc[4][4][4], int warp_m, int warp_n, int l) {
            #pragma unroll
            for (int mt = 0; mt < 4; mt++) {
                const int m = by * 128 + warp_m * 64 + mt * 16 + (l >> 2);
                const int b = m >> 11, s = m & (S_LEN - 1);
                const size_t base =
                    (((size_t)(b * NH + head)) * S_LEN + s) * DH;
                #pragma unroll
                for (int nt = 0; nt < 4; nt++) {
                    const int d = warp_n * 32 + nt * 8 + ((l & 3) << 1);
                    __half2 lo0, lo1;
                    __half2 h0 = split_hi_h(acc[mt][nt][0], acc[mt][nt][1], lo0);
                    __half2 h1 = split_hi_h(acc[mt][nt][2], acc[mt][nt][3], lo1);
                    *(__half2*)(H + base + d) = h0;
                    *(__half2*)(H + base + (size_t)8 * DH + d) = h1;
                    if (has_lo) {
                        *(__half2*)(L + base + d) = lo0;
                        *(__half2*)(L + base + (size_t)8 * DH + d) = lo1;
                    }
                }
            }
        });
}

// ---------------------------------------------------------------------------
// FA2-style tensor-core attention, fp16 2-term, single accumulators:
//   QK: (qh + ql) * K      (K single-rounded; ql = Q - qh, normal fp16)
//   PV: P * (vh + vl)      (P single-rounded; vl = V - vh, normal fp16)
// Softmax scale log2(e)/sqrt(dh) applied to scores post-MMA.
// 8 warps; each warp owns 16 Q rows. 3-stage KV pipeline, 1 sync/tile.
// ---------------------------------------------------------------------------
#define ATQ 128
#define AKT 32
#define ANT (S_LEN / AKT)

#define ASM_QH 0
#define ASM_QL 32768
#define ASM_KV 65536                  // 3 stages x 24576 (K|Vh|Vl x 8KB)
#define KVSTAGE 24576
#define ATTN_SMEM (65536 + 3 * KVSTAGE) // 139264

#define SWZ(row, cu) ((row) * 256 + ((((cu) ^ ((row) & 7))) << 4))

#define SOFTMAX_SCALE 0.12751744f     // log2(e) / sqrt(128)

__global__ __launch_bounds__(256) void attn_mma_kernel(
    const __half* __restrict__ qh, const __half* __restrict__ ql,
    const __half* __restrict__ kk16, const __half* __restrict__ vh,
    const __half* __restrict__ vl,
    __half* __restrict__ outA)
{
    extern __shared__ char gsm[];
    const uint32_t sb = smem_to_u32(gsm);
    const int tid = threadIdx.x;
    const int w = tid >> 5, l = tid & 31;
    const int qt = blockIdx.x, h = blockIdx.y, b = blockIdx.z;

    const size_t head = ((size_t)(b * NH + h)) * S_LEN * DH;
    const __half* Qh_g = qh + head + (size_t)qt * ATQ * DH;
    const __half* Ql_g = ql + head + (size_t)qt * ATQ * DH;

    auto load_kv = [&](int t) {
        const uint32_t st = sb + ASM_KV + (t % 3) * KVSTAGE;
        const size_t base = head + (size_t)t * AKT * DH;
        const __half* srcs[3] = {kk16 + base, vh + base, vl + base};
        #pragma unroll
        for (int a = 0; a < 3; a++) {
            #pragma unroll
            for (int j = 0; j < 2; j++) {
                const int u = tid + 256 * j;
                const int row = u >> 4, cu = u & 15;
                cp_async16(st + a * 8192 + SWZ(row, cu),
                           (const char*)srcs[a] + (size_t)row * 256 + cu * 16);
            }
        }
        CP_COMMIT();
    };

    // Q loads committed together with KV(0) as group 0.
    #pragma unroll
    for (int j = 0; j < 8; j++) {
        const int u = tid + 256 * j;
        const int row = u >> 4, cu = u & 15;
        cp_async16(sb + ASM_QH + SWZ(row, cu),
                   (const char*)Qh_g + (size_t)row * 256 + cu * 16);
        cp_async16(sb + ASM_QL + SWZ(row, cu),
                   (const char*)Ql_g + (size_t)row * 256 + cu * 16);
    }
    load_kv(0);
    load_kv(1);

    // Wait for group 0 (Q + KV0), then cache ALL Q fragments in registers.
    CP_WAIT(1);
    __syncthreads();
    uint32_t qhf[8][4], qlf[8][4];
    #pragma unroll
    for (int kk = 0; kk < 8; kk++) {
        const int row = w * 16 + (l & 15);
        const int cu = kk * 2 + (l >> 4);
        const uint32_t off = SWZ(row, cu);
        ldsm_x4(qhf[kk], sb + ASM_QH + off);
        ldsm_x4(qlf[kk], sb + ASM_QL + off);
    }

    float m0 = -1e9f, m1 = -1e9f, ls0 = 0.f, ls1 = 0.f;
    float O[16][4];
    #pragma unroll
    for (int nt = 0; nt < 16; nt++)
        #pragma unroll
        for (int c = 0; c < 4; c++) O[nt][c] = 0.f;

    for (int t = 0; t < ANT; t++) {
        if (t > 0) {
            if (t + 1 < ANT) { CP_WAIT(1); } else { CP_WAIT(0); }
            __syncthreads();
        }
        if (t + 2 < ANT) load_kv(t + 2);

        const uint32_t stg = sb + ASM_KV + (t % 3) * KVSTAGE;

        // ---- QK: sacc[nt][4], warp tile 16x32, Q (hi+lo) from registers ----
        float sacc[4][4];
        #pragma unroll
        for (int nt = 0; nt < 4; nt++)
            #pragma unroll
            for (int c = 0; c < 4; c++) sacc[nt][c] = 0.f;

        #pragma unroll
        for (int kk = 0; kk < 8; kk++) {
            uint32_t khf[2][4];
            #pragma unroll
            for (int np = 0; np < 2; np++) {
                const int g = l >> 3, idx = l & 7;
                const int krow = np * 16 + ((g >> 1) << 3) + idx;
                const int bcu = kk * 2 + (g & 1);
                const uint32_t off = SWZ(krow, bcu);
                ldsm_x4(khf[np], stg + off);
            }
            #pragma unroll
            for (int nt = 0; nt < 4; nt++) {
                const uint32_t* bhp = &khf[nt >> 1][(nt & 1) * 2];
                mma16816h(sacc[nt], qhf[kk], bhp);
                mma16816h(sacc[nt], qlf[kk], bhp);
            }
        }

        // scale scores into exp2 domain
        #pragma unroll
        for (int nt = 0; nt < 4; nt++)
            #pragma unroll
            for (int c = 0; c < 4; c++) sacc[nt][c] *= SOFTMAX_SCALE;

        // ---- softmax in registers ------------------------------------------
        float mx0 = sacc[0][0], mx1 = sacc[0][2];
        #pragma unroll
        for (int nt = 0; nt < 4; nt++) {
            mx0 = fmaxf(mx0, fmaxf(sacc[nt][0], sacc[nt][1]));
            mx1 = fmaxf(mx1, fmaxf(sacc[nt][2], sacc[nt][3]));
        }
        mx0 = fmaxf(mx0, __shfl_xor_sync(0xffffffffu, mx0, 1));
        mx0 = fmaxf(mx0, __shfl_xor_sync(0xffffffffu, mx0, 2));
        mx1 = fmaxf(mx1, __shfl_xor_sync(0xffffffffu, mx1, 1));
        mx1 = fmaxf(mx1, __shfl_xor_sync(0xffffffffu, mx1, 2));
        const float mn0 = fmaxf(m0, mx0);
        const float mn1 = fmaxf(m1, mx1);

        uint32_t ph[2][4];
        float s0 = 0.f, s1 = 0.f;
        #pragma unroll
        for (int nt = 0; nt < 4; nt++) {
            const float p0 = exp2_fast(sacc[nt][0] - mn0);
            const float p1 = exp2_fast(sacc[nt][1] - mn0);
            const float p2 = exp2_fast(sacc[nt][2] - mn1);
            const float p3 = exp2_fast(sacc[nt][3] - mn1);
            s0 += p0 + p1;
            s1 += p2 + p3;
            const __half2 h01 = __floats2half2_rn(p0, p1);
            const __half2 h23 = __floats2half2_rn(p2, p3);
            const int kk = nt >> 1, base = (nt & 1) * 2;
            ph[kk][base]     = h2u(h01);
            ph[kk][base + 1] = h2u(h23);
        }
        s0 += __shfl_xor_sync(0xffffffffu, s0, 1);
        s0 += __shfl_xor_sync(0xffffffffu, s0, 2);
        s1 += __shfl_xor_sync(0xffffffffu, s1, 1);
        s1 += __shfl_xor_sync(0xffffffffu, s1, 2);
        const float f0 = exp2_fast(m0 - mn0);
        const float f1 = exp2_fast(m1 - mn1);
        ls0 = ls0 * f0 + s0;
        ls1 = ls1 * f1 + s1;
        m0 = mn0; m1 = mn1;

        #pragma unroll
        for (int nt = 0; nt < 16; nt++) {
            O[nt][0] *= f0; O[nt][1] *= f0;
            O[nt][2] *= f1; O[nt][3] *= f1;
        }

        // ---- PV: warp tile 16x128, P from registers, V = vh + vl -----------
        const uint32_t sVh = stg + 8192, sVl = stg + 16384;
        #pragma unroll
        for (int kk = 0; kk < 2; kk++) {
            #pragma unroll
            for (int np = 0; np < 8; np++) {
                uint32_t vbh[4], vbl[4];
                const int mat = l >> 3, idx = l & 7;
                const int key = kk * 16 + ((mat & 1) << 3) + idx;
                const int cu = np * 2 + (mat >> 1);
                const uint32_t off = SWZ(key, cu);
                ldsm_x4_t(vbh, sVh + off);
                ldsm_x4_t(vbl, sVl + off);
                #pragma unroll
                for (int half = 0; half < 2; half++) {
                    const int nt = np * 2 + half;
                    mma16816h(O[nt], ph[kk], &vbh[half * 2]);
                    mma16816h(O[nt], ph[kk], &vbl[half * 2]);
                }
            }
        }
    }

    // ---- epilogue: normalize, write GEMM2's A (single fp16) ---------------
    const float inv0 = 1.f / ls0;
    const float inv1 = 1.f / ls1;
    const int row0 = qt * ATQ + w * 16 + (l >> 2);
    const size_t s0o = (size_t)(b * S_LEN + row0) * EMB + h * DH;
    #pragma unroll
    for (int nt = 0; nt < 16; nt++) {
        const int col = nt * 8 + ((l & 3) << 1);
        const __half2 h0 = __floats2half2_rn(O[nt][0] * inv0, O[nt][1] * inv0);
        const __half2 h1 = __floats2half2_rn(O[nt][2] * inv1, O[nt][3] * inv1);
        *(__half2*)(outA + s0o + col) = h0;
        *(__half2*)(outA + s0o + (size_t)8 * EMB + col) = h1;
    }
}

// ---------------------------------------------------------------------------
extern "C" void kernel_launch(void* const* d_in, const int* in_sizes, int n_in,
                              void* d_out, int out_size)
{
    (void)in_sizes; (void)n_in; (void)out_size;
    const float* x    = (const float*)d_in[0];
    const float* Wqkv = (const float*)d_in[1];
    const float* bqkv = (const float*)d_in[2];
    const float* Wout = (const float*)d_in[3];
    const float* bout = (const float*)d_in[4];
    float* out = (float*)d_out;

    __half *a16, *wqh, *wql, *woh, *wol;
    __half *q16h, *q16l, *k16, *v16h, *v16l;
    cudaGetSymbolAddress((void**)&a16, g_a16);
    cudaGetSymbolAddress((void**)&wqh, g_wqh);
    cudaGetSymbolAddress((void**)&wql, g_wql);
    cudaGetSymbolAddress((void**)&woh, g_woh);
    cudaGetSymbolAddress((void**)&wol, g_wol);
    cudaGetSymbolAddress((void**)&q16h, g_q16h);
    cudaGetSymbolAddress((void**)&q16l, g_q16l);
    cudaGetSymbolAddress((void**)&k16, g_k16);
    cudaGetSymbolAddress((void**)&v16h, g_v16h);
    cudaGetSymbolAddress((void**)&v16l, g_v16l);

    cudaFuncSetAttribute(gemm_mma_kernel,
                         cudaFuncAttributeMaxDynamicSharedMemorySize, GEMM_SMEM);
    cudaFuncSetAttribute(gemm_qkv_kernel,
                         cudaFuncAttributeMaxDynamicSharedMemorySize, GEMM_SMEM);
    cudaFuncSetAttribute(attn_mma_kernel,
                         cudaFuncAttributeMaxDynamicSharedMemorySize, ATTN_SMEM);

    // 0) conversions (inputs only)
    to_half_kernel<<<2048, 256>>>(x, a16, MROWS * EMB);
    transpose_split_kernel<<<dim3((3 * EMB) / 32, GK / 32), dim3(32, 8)>>>(
        Wqkv, wqh, wql, GK, 3 * EMB);
    transpose_split_kernel<<<dim3(EMB / 32, GK / 32), dim3(32, 8)>>>(
        Wout, woh, wol, GK, EMB);

    // 1) qkv projection (fp16 2-term) fused with per-head fp16 split
    gemm_qkv_kernel<<<dim3((3 * EMB) / 128, MROWS / 128), 256, GEMM_SMEM>>>(
        a16, wqh, wql, bqkv);

    // 2) FA2-style attention (fp16 2-term); writes GEMM2's A (fp16)
    attn_mma_kernel<<<dim3(S_LEN / ATQ, NH, BATCH), 256, ATTN_SMEM>>>(
        q16h, q16l, k16, v16h, v16l, a16);

    // 3) out = attn @ W_out + b_out  (fp16 2-term)
    gemm_mma_kernel<<<dim3(EMB / 128, MROWS / 128), 256, GEMM_SMEM>>>(
        EMB, a16, woh, wol, bout, out);
}

// round 11
// speedup vs baseline: 6.5237x; 1.3997x over previous
#include <cuda_runtime.h>
#include <cuda_bf16.h>
#include <cuda_fp16.h>
#include <cstdint>

#define S_LEN 2048
#define EMB   2048
#define NH    16
#define DH    128
#define BATCH 2
#define MROWS (BATCH * S_LEN)   // 4096
#define GK    2048              // K for both projection GEMMs

// ---------------------------------------------------------------------------
// Device scratch (no cudaMalloc allowed)
// ---------------------------------------------------------------------------
__device__ __half g_a16[(size_t)MROWS * GK];              // A operand (x, then attn-out), fp16
__device__ __half g_wq[(size_t)(3 * EMB) * GK];           // W_qkv^T fp16 [6144,2048]
__device__ __half g_wo[(size_t)EMB * GK];                 // W_out^T fp16 [2048,2048]
// per-head Q/K/V (fp16 2-term attention), layout [B, H, S, DH]
// Q split unscaled (qh+ql, residual = normal fp16); K single; V split unscaled.
#define QKV_ELEMS ((size_t)BATCH * NH * S_LEN * DH)
__device__ __half g_q16h[QKV_ELEMS];
__device__ __half g_q16l[QKV_ELEMS];
__device__ __half g_k16[QKV_ELEMS];
__device__ __half g_v16h[QKV_ELEMS];
__device__ __half g_v16l[QKV_ELEMS];

// ---------------------------------------------------------------------------
// PTX helpers (plain sm_80+ instructions only)
// ---------------------------------------------------------------------------
__device__ __forceinline__ uint32_t smem_to_u32(const void* p) {
    uint32_t a;
    asm("{ .reg .u64 t; cvta.to.shared.u64 t, %1; cvt.u32.u64 %0, t; }"
        : "=r"(a) : "l"(p));
    return a;
}

__device__ __forceinline__ void cp_async16(uint32_t saddr, const void* gaddr) {
    asm volatile("cp.async.cg.shared.global [%0], [%1], 16;"
        :: "r"(saddr), "l"(gaddr) : "memory");
}
#define CP_COMMIT() asm volatile("cp.async.commit_group;" ::: "memory")
#define CP_WAIT(n)  asm volatile("cp.async.wait_group %0;" :: "n"(n) : "memory")

__device__ __forceinline__ void ldsm_x4(uint32_t* r, uint32_t addr) {
    asm volatile("ldmatrix.sync.aligned.m8n8.x4.shared.b16 {%0,%1,%2,%3}, [%4];"
        : "=r"(r[0]), "=r"(r[1]), "=r"(r[2]), "=r"(r[3]) : "r"(addr));
}
__device__ __forceinline__ void ldsm_x4_t(uint32_t* r, uint32_t addr) {
    asm volatile("ldmatrix.sync.aligned.m8n8.x4.trans.shared.b16 {%0,%1,%2,%3}, [%4];"
        : "=r"(r[0]), "=r"(r[1]), "=r"(r[2]), "=r"(r[3]) : "r"(addr));
}

// fp16 MMA (all tensor work)
__device__ __forceinline__ void mma16816h(float* d, const uint32_t* a,
                                          const uint32_t* b) {
    asm volatile(
        "mma.sync.aligned.m16n8k16.row.col.f32.f16.f16.f32 "
        "{%0,%1,%2,%3}, {%4,%5,%6,%7}, {%8,%9}, {%0,%1,%2,%3};"
        : "+f"(d[0]), "+f"(d[1]), "+f"(d[2]), "+f"(d[3])
        : "r"(a[0]), "r"(a[1]), "r"(a[2]), "r"(a[3]), "r"(b[0]), "r"(b[1]));
}

// Fast 2^t on FMA/ALU pipes only (no MUFU, no CVT). |rel err| < 3e-6.
__device__ __forceinline__ float exp2_fast(float t) {
    t = fmaxf(t, -126.0f);
    const float MAGIC = 12582912.0f;          // 2^23 + 2^22
    float z = t + MAGIC;
    int i = __float_as_int(z);
    float r = z - MAGIC;
    float f = t - r;                          // f in [-0.5, 0.5]
    float p = 1.3333558146e-3f;
    p = fmaf(p, f, 9.6181291076e-3f);
    p = fmaf(p, f, 5.5504108664e-2f);
    p = fmaf(p, f, 2.4022650696e-1f);
    p = fmaf(p, f, 6.9314718056e-1f);
    p = fmaf(p, f, 1.0f);
    int eb = (i + (127 - 0x4B400000)) << 23;
    return p * __int_as_float(eb);
}

__device__ __forceinline__ __half2 split_hi_h(float v0, float v1, __half2& lo) {
    __half2 h;
    h.x = __float2half(v0);
    h.y = __float2half(v1);
    lo.x = __float2half(v0 - __half2float(h.x));
    lo.y = __float2half(v1 - __half2float(h.y));
    return h;
}
__device__ __forceinline__ uint32_t h2u(__half2 v) {
    return *(uint32_t*)&v;
}

// ---------------------------------------------------------------------------
// Conversion kernels
// ---------------------------------------------------------------------------
__global__ __launch_bounds__(256) void to_half_kernel(
    const float* __restrict__ in, __half* __restrict__ out, int n)
{
    int i = blockIdx.x * blockDim.x + threadIdx.x;
    int stride = gridDim.x * blockDim.x;
    for (; i < n; i += stride) out[i] = __float2half(in[i]);
}

// W[K,N] row-major -> T[N,K] fp16 (single rounding)
__global__ __launch_bounds__(256) void transpose_half_kernel(
    const float* __restrict__ W, __half* __restrict__ T, int K, int N)
{
    __shared__ float t[32][33];
    const int nb = blockIdx.x * 32;
    const int kb = blockIdx.y * 32;
    const int x = threadIdx.x, y = threadIdx.y;   // block (32,8)
    #pragma unroll
    for (int j = 0; j < 32; j += 8)
        t[y + j][x] = W[(size_t)(kb + y + j) * N + nb + x];
    __syncthreads();
    #pragma unroll
    for (int j = 0; j < 32; j += 8)
        T[(size_t)(nb + y + j) * K + kb + x] = __float2half(t[x][y + j]);
}

// ---------------------------------------------------------------------------
// fp16 1-term HMMA mainloop: C = A*B^T + bias.
// Block 128x128, 8 warps (2x4), warp tile 64x32, K-chunk 64, 2-stage buffer.
// ---------------------------------------------------------------------------
#define GBK   64
#define NCHUNK (GK / GBK)
#define TBYTES 16384
#define STAGE  (2 * TBYTES)          // 32 KB (A + B)
#define GEMM_SMEM (2 * STAGE)        // 64 KB

template <typename Epilogue>
__device__ __forceinline__ void gemm_mainloop(
    char* gsm,
    const __half* __restrict__ A, const __half* __restrict__ B,
    const float* __restrict__ bias, int bx, int by, Epilogue epi)
{
    const uint32_t sb = smem_to_u32(gsm);
    const int tid = threadIdx.x;
    const int w = tid >> 5, l = tid & 31;
    const int warp_m = w >> 2, warp_n = w & 3;

    const __half* srcs[2] = {
        A + (size_t)(by * 128) * GK,
        B + (size_t)(bx * 128) * GK };

    float acc[4][4][4];
    #pragma unroll
    for (int nt = 0; nt < 4; nt++) {
        const int n = bx * 128 + warp_n * 32 + nt * 8 + ((l & 3) << 1);
        const float b0 = bias[n], b1 = bias[n + 1];
        #pragma unroll
        for (int mt = 0; mt < 4; mt++) {
            acc[mt][nt][0] = b0; acc[mt][nt][1] = b1;
            acc[mt][nt][2] = b0; acc[mt][nt][3] = b1;
        }
    }

    auto load_chunk = [&](int kt) {
        const uint32_t st = sb + (kt & 1) * STAGE;
        const size_t kofs = (size_t)kt * GBK;
        #pragma unroll
        for (int a = 0; a < 2; a++) {
            const char* g = (const char*)(srcs[a] + kofs);
            #pragma unroll
            for (int j = 0; j < 4; j++) {
                const int u = tid + 256 * j;
                const int r = u >> 3;
                const int cu = u & 7;
                const uint32_t off = r * 128 + ((cu ^ (r & 7)) << 4);
                cp_async16(st + a * TBYTES + off,
                           g + (size_t)r * (GK * 2) + (cu << 4));
            }
        }
        CP_COMMIT();
    };

    load_chunk(0);

    for (int kt = 0; kt < NCHUNK; kt++) {
        if (kt + 1 < NCHUNK) { load_chunk(kt + 1); CP_WAIT(1); }
        else                 { CP_WAIT(0); }
        __syncthreads();

        const uint32_t st = sb + (kt & 1) * STAGE;
        const uint32_t sA = st, sB = st + TBYTES;

        #pragma unroll
        for (int kk = 0; kk < 4; kk++) {
            const int kb = kk * 32;

            uint32_t af[4][4];
            #pragma unroll
            for (int mt = 0; mt < 4; mt++) {
                const int row = warp_m * 64 + mt * 16 + (l & 15);
                const int bc = kb + ((l >> 4) << 4);
                const uint32_t off = row * 128 + (bc ^ ((row & 7) << 4));
                ldsm_x4(af[mt], sA + off);
            }

            uint32_t bf[2][4];
            #pragma unroll
            for (int np = 0; np < 2; np++) {
                const int g = l >> 3, idx = l & 7;
                const int row = warp_n * 32 + np * 16 + ((g >> 1) << 3) + idx;
                const int bc = kb + ((g & 1) << 4);
                const uint32_t off = row * 128 + (bc ^ ((row & 7) << 4));
                ldsm_x4(bf[np], sB + off);
            }

            #pragma unroll
            for (int mt = 0; mt < 4; mt++)
                #pragma unroll
                for (int nt = 0; nt < 4; nt++)
                    mma16816h(acc[mt][nt], af[mt], &bf[nt >> 1][(nt & 1) * 2]);
        }
        __syncthreads();
    }

    epi(acc, warp_m, warp_n, l);
}

// GEMM2: plain fp32 output C = A*B^T + bias
__global__ __launch_bounds__(256) void gemm_mma_kernel(
    int N,
    const __half* __restrict__ A, const __half* __restrict__ B,
    const float* __restrict__ bias, float* __restrict__ C)
{
    extern __shared__ char gsm[];
    const int bx = blockIdx.x, by = blockIdx.y;
    gemm_mainloop(gsm, A, B, bias, bx, by,
        [&](float acc[4][4][4], int warp_m, int warp_n, int l) {
            #pragma unroll
            for (int mt = 0; mt < 4; mt++) {
                const int m = by * 128 + warp_m * 64 + mt * 16 + (l >> 2);
                float* c0 = C + (size_t)m * N + bx * 128 + warp_n * 32 + ((l & 3) << 1);
                #pragma unroll
                for (int nt = 0; nt < 4; nt++) {
                    *(float2*)(c0 + nt * 8) =
                        make_float2(acc[mt][nt][0], acc[mt][nt][1]);
                    *(float2*)(c0 + (size_t)8 * N + nt * 8) =
                        make_float2(acc[mt][nt][2], acc[mt][nt][3]);
                }
            }
        });
}

// GEMM1 fused: writes per-head fp16 Q (split) / K (single) / V (split).
// Q/K/V stored UNSCALED — softmax scale applied on scores in attention.
__global__ __launch_bounds__(256) void gemm_qkv_kernel(
    const __half* __restrict__ A, const __half* __restrict__ B,
    const float* __restrict__ bias)
{
    extern __shared__ char gsm[];
    const int bx = blockIdx.x, by = blockIdx.y;
    const int region = bx % 3;        // 0=q, 1=k, 2=v
    const int head   = bx / 3;
    __half* H = (region == 0) ? g_q16h : (region == 1) ? g_k16 : g_v16h;
    __half* L = (region == 0) ? g_q16l : (region == 1) ? (__half*)nullptr : g_v16l;
    const bool has_lo = (region != 1);

    gemm_mainloop(gsm, A, B, bias, bx, by,
        [&](float acc[4][4][4], int warp_m, int warp_n, int l) {
            #pragma unroll
            for (int mt = 0; mt < 4; mt++) {
                const int m = by * 128 + warp_m * 64 + mt * 16 + (l >> 2);
                const int b = m >> 11, s = m & (S_LEN - 1);
                const size_t base =
                    (((size_t)(b * NH + head)) * S_LEN + s) * DH;
                #pragma unroll
                for (int nt = 0; nt < 4; nt++) {
                    const int d = warp_n * 32 + nt * 8 + ((l & 3) << 1);
                    __half2 lo0, lo1;
                    __half2 h0 = split_hi_h(acc[mt][nt][0], acc[mt][nt][1], lo0);
                    __half2 h1 = split_hi_h(acc[mt][nt][2], acc[mt][nt][3], lo1);
                    *(__half2*)(H + base + d) = h0;
                    *(__half2*)(H + base + (size_t)8 * DH + d) = h1;
                    if (has_lo) {
                        *(__half2*)(L + base + d) = lo0;
                        *(__half2*)(L + base + (size_t)8 * DH + d) = lo1;
                    }
                }
            }
        });
}

// ---------------------------------------------------------------------------
// FA2-style tensor-core attention, fp16 2-term (unchanged from R10):
//   QK: (qh + ql) * K ; PV: P * (vh + vl)
// ---------------------------------------------------------------------------
#define ATQ 128
#define AKT 32
#define ANT (S_LEN / AKT)

#define ASM_QH 0
#define ASM_QL 32768
#define ASM_KV 65536                  // 3 stages x 24576 (K|Vh|Vl x 8KB)
#define KVSTAGE 24576
#define ATTN_SMEM (65536 + 3 * KVSTAGE) // 139264

#define SWZ(row, cu) ((row) * 256 + ((((cu) ^ ((row) & 7))) << 4))

#define SOFTMAX_SCALE 0.12751744f     // log2(e) / sqrt(128)

__global__ __launch_bounds__(256) void attn_mma_kernel(
    const __half* __restrict__ qh, const __half* __restrict__ ql,
    const __half* __restrict__ kk16, const __half* __restrict__ vh,
    const __half* __restrict__ vl,
    __half* __restrict__ outA)
{
    extern __shared__ char gsm[];
    const uint32_t sb = smem_to_u32(gsm);
    const int tid = threadIdx.x;
    const int w = tid >> 5, l = tid & 31;
    const int qt = blockIdx.x, h = blockIdx.y, b = blockIdx.z;

    const size_t head = ((size_t)(b * NH + h)) * S_LEN * DH;
    const __half* Qh_g = qh + head + (size_t)qt * ATQ * DH;
    const __half* Ql_g = ql + head + (size_t)qt * ATQ * DH;

    auto load_kv = [&](int t) {
        const uint32_t st = sb + ASM_KV + (t % 3) * KVSTAGE;
        const size_t base = head + (size_t)t * AKT * DH;
        const __half* srcs[3] = {kk16 + base, vh + base, vl + base};
        #pragma unroll
        for (int a = 0; a < 3; a++) {
            #pragma unroll
            for (int j = 0; j < 2; j++) {
                const int u = tid + 256 * j;
                const int row = u >> 4, cu = u & 15;
                cp_async16(st + a * 8192 + SWZ(row, cu),
                           (const char*)srcs[a] + (size_t)row * 256 + cu * 16);
            }
        }
        CP_COMMIT();
    };

    // Q loads committed together with KV(0) as group 0.
    #pragma unroll
    for (int j = 0; j < 8; j++) {
        const int u = tid + 256 * j;
        const int row = u >> 4, cu = u & 15;
        cp_async16(sb + ASM_QH + SWZ(row, cu),
                   (const char*)Qh_g + (size_t)row * 256 + cu * 16);
        cp_async16(sb + ASM_QL + SWZ(row, cu),
                   (const char*)Ql_g + (size_t)row * 256 + cu * 16);
    }
    load_kv(0);
    load_kv(1);

    // Wait for group 0 (Q + KV0), then cache ALL Q fragments in registers.
    CP_WAIT(1);
    __syncthreads();
    uint32_t qhf[8][4], qlf[8][4];
    #pragma unroll
    for (int kk = 0; kk < 8; kk++) {
        const int row = w * 16 + (l & 15);
        const int cu = kk * 2 + (l >> 4);
        const uint32_t off = SWZ(row, cu);
        ldsm_x4(qhf[kk], sb + ASM_QH + off);
        ldsm_x4(qlf[kk], sb + ASM_QL + off);
    }

    float m0 = -1e9f, m1 = -1e9f, ls0 = 0.f, ls1 = 0.f;
    float O[16][4];
    #pragma unroll
    for (int nt = 0; nt < 16; nt++)
        #pragma unroll
        for (int c = 0; c < 4; c++) O[nt][c] = 0.f;

    for (int t = 0; t < ANT; t++) {
        if (t > 0) {
            if (t + 1 < ANT) { CP_WAIT(1); } else { CP_WAIT(0); }
            __syncthreads();
        }
        if (t + 2 < ANT) load_kv(t + 2);

        const uint32_t stg = sb + ASM_KV + (t % 3) * KVSTAGE;

        // ---- QK: sacc[nt][4], warp tile 16x32, Q (hi+lo) from registers ----
        float sacc[4][4];
        #pragma unroll
        for (int nt = 0; nt < 4; nt++)
            #pragma unroll
            for (int c = 0; c < 4; c++) sacc[nt][c] = 0.f;

        #pragma unroll
        for (int kk = 0; kk < 8; kk++) {
            uint32_t khf[2][4];
            #pragma unroll
            for (int np = 0; np < 2; np++) {
                const int g = l >> 3, idx = l & 7;
                const int krow = np * 16 + ((g >> 1) << 3) + idx;
                const int bcu = kk * 2 + (g & 1);
                const uint32_t off = SWZ(krow, bcu);
                ldsm_x4(khf[np], stg + off);
            }
            #pragma unroll
            for (int nt = 0; nt < 4; nt++) {
                const uint32_t* bhp = &khf[nt >> 1][(nt & 1) * 2];
                mma16816h(sacc[nt], qhf[kk], bhp);
                mma16816h(sacc[nt], qlf[kk], bhp);
            }
        }

        // scale scores into exp2 domain
        #pragma unroll
        for (int nt = 0; nt < 4; nt++)
            #pragma unroll
            for (int c = 0; c < 4; c++) sacc[nt][c] *= SOFTMAX_SCALE;

        // ---- softmax in registers ------------------------------------------
        float mx0 = sacc[0][0], mx1 = sacc[0][2];
        #pragma unroll
        for (int nt = 0; nt < 4; nt++) {
            mx0 = fmaxf(mx0, fmaxf(sacc[nt][0], sacc[nt][1]));
            mx1 = fmaxf(mx1, fmaxf(sacc[nt][2], sacc[nt][3]));
        }
        mx0 = fmaxf(mx0, __shfl_xor_sync(0xffffffffu, mx0, 1));
        mx0 = fmaxf(mx0, __shfl_xor_sync(0xffffffffu, mx0, 2));
        mx1 = fmaxf(mx1, __shfl_xor_sync(0xffffffffu, mx1, 1));
        mx1 = fmaxf(mx1, __shfl_xor_sync(0xffffffffu, mx1, 2));
        const float mn0 = fmaxf(m0, mx0);
        const float mn1 = fmaxf(m1, mx1);

        uint32_t ph[2][4];
        float s0 = 0.f, s1 = 0.f;
        #pragma unroll
        for (int nt = 0; nt < 4; nt++) {
            const float p0 = exp2_fast(sacc[nt][0] - mn0);
            const float p1 = exp2_fast(sacc[nt][1] - mn0);
            const float p2 = exp2_fast(sacc[nt][2] - mn1);
            const float p3 = exp2_fast(sacc[nt][3] - mn1);
            s0 += p0 + p1;
            s1 += p2 + p3;
            const __half2 h01 = __floats2half2_rn(p0, p1);
            const __half2 h23 = __floats2half2_rn(p2, p3);
            const int kk = nt >> 1, base = (nt & 1) * 2;
            ph[kk][base]     = h2u(h01);
            ph[kk][base + 1] = h2u(h23);
        }
        s0 += __shfl_xor_sync(0xffffffffu, s0, 1);
        s0 += __shfl_xor_sync(0xffffffffu, s0, 2);
        s1 += __shfl_xor_sync(0xffffffffu, s1, 1);
        s1 += __shfl_xor_sync(0xffffffffu, s1, 2);
        const float f0 = exp2_fast(m0 - mn0);
        const float f1 = exp2_fast(m1 - mn1);
        ls0 = ls0 * f0 + s0;
        ls1 = ls1 * f1 + s1;
        m0 = mn0; m1 = mn1;

        #pragma unroll
        for (int nt = 0; nt < 16; nt++) {
            O[nt][0] *= f0; O[nt][1] *= f0;
            O[nt][2] *= f1; O[nt][3] *= f1;
        }

        // ---- PV: warp tile 16x128, P from registers, V = vh + vl -----------
        const uint32_t sVh = stg + 8192, sVl = stg + 16384;
        #pragma unroll
        for (int kk = 0; kk < 2; kk++) {
            #pragma unroll
            for (int np = 0; np < 8; np++) {
                uint32_t vbh[4], vbl[4];
                const int mat = l >> 3, idx = l & 7;
                const int key = kk * 16 + ((mat & 1) << 3) + idx;
                const int cu = np * 2 + (mat >> 1);
                const uint32_t off = SWZ(key, cu);
                ldsm_x4_t(vbh, sVh + off);
                ldsm_x4_t(vbl, sVl + off);
                #pragma unroll
                for (int half = 0; half < 2; half++) {
                    const int nt = np * 2 + half;
                    mma16816h(O[nt], ph[kk], &vbh[half * 2]);
                    mma16816h(O[nt], ph[kk], &vbl[half * 2]);
                }
            }
        }
    }

    // ---- epilogue: normalize, write GEMM2's A (single fp16) ---------------
    const float inv0 = 1.f / ls0;
    const float inv1 = 1.f / ls1;
    const int row0 = qt * ATQ + w * 16 + (l >> 2);
    const size_t s0o = (size_t)(b * S_LEN + row0) * EMB + h * DH;
    #pragma unroll
    for (int nt = 0; nt < 16; nt++) {
        const int col = nt * 8 + ((l & 3) << 1);
        const __half2 h0 = __floats2half2_rn(O[nt][0] * inv0, O[nt][1] * inv0);
        const __half2 h1 = __floats2half2_rn(O[nt][2] * inv1, O[nt][3] * inv1);
        *(__half2*)(outA + s0o + col) = h0;
        *(__half2*)(outA + s0o + (size_t)8 * EMB + col) = h1;
    }
}

// ---------------------------------------------------------------------------
extern "C" void kernel_launch(void* const* d_in, const int* in_sizes, int n_in,
                              void* d_out, int out_size)
{
    (void)in_sizes; (void)n_in; (void)out_size;
    const float* x    = (const float*)d_in[0];
    const float* Wqkv = (const float*)d_in[1];
    const float* bqkv = (const float*)d_in[2];
    const float* Wout = (const float*)d_in[3];
    const float* bout = (const float*)d_in[4];
    float* out = (float*)d_out;

    __half *a16, *wq, *wo;
    __half *q16h, *q16l, *k16, *v16h, *v16l;
    cudaGetSymbolAddress((void**)&a16, g_a16);
    cudaGetSymbolAddress((void**)&wq, g_wq);
    cudaGetSymbolAddress((void**)&wo, g_wo);
    cudaGetSymbolAddress((void**)&q16h, g_q16h);
    cudaGetSymbolAddress((void**)&q16l, g_q16l);
    cudaGetSymbolAddress((void**)&k16, g_k16);
    cudaGetSymbolAddress((void**)&v16h, g_v16h);
    cudaGetSymbolAddress((void**)&v16l, g_v16l);

    cudaFuncSetAttribute(gemm_mma_kernel,
                         cudaFuncAttributeMaxDynamicSharedMemorySize, GEMM_SMEM);
    cudaFuncSetAttribute(gemm_qkv_kernel,
                         cudaFuncAttributeMaxDynamicSharedMemorySize, GEMM_SMEM);
    cudaFuncSetAttribute(attn_mma_kernel,
                         cudaFuncAttributeMaxDynamicSharedMemorySize, ATTN_SMEM);

    // 0) conversions (inputs only)
    to_half_kernel<<<2048, 256>>>(x, a16, MROWS * EMB);
    transpose_half_kernel<<<dim3((3 * EMB) / 32, GK / 32), dim3(32, 8)>>>(
        Wqkv, wq, GK, 3 * EMB);
    transpose_half_kernel<<<dim3(EMB / 32, GK / 32), dim3(32, 8)>>>(
        Wout, wo, GK, EMB);

    // 1) qkv projection (fp16 1-term) fused with per-head fp16 split
    gemm_qkv_kernel<<<dim3((3 * EMB) / 128, MROWS / 128), 256, GEMM_SMEM>>>(
        a16, wq, bqkv);

    // 2) FA2-style attention (fp16 2-term); writes GEMM2's A (fp16)
    attn_mma_kernel<<<dim3(S_LEN / ATQ, NH, BATCH), 256, ATTN_SMEM>>>(
        q16h, q16l, k16, v16h, v16l, a16);

    // 3) out = attn @ W_out + b_out  (fp16 1-term)
    gemm_mma_kernel<<<dim3(EMB / 128, MROWS / 128), 256, GEMM_SMEM>>>(
        EMB, a16, wo, bout, out);
}

// round 12
// speedup vs baseline: 8.3022x; 1.2726x over previous
#include <cuda_runtime.h>
#include <cuda_fp16.h>
#include <cstdint>

#define S_LEN 2048
#define EMB   2048
#define NH    16
#define DH    128
#define BATCH 2
#define MROWS (BATCH * S_LEN)   // 4096
#define GK    2048              // K for both projection GEMMs

// ---------------------------------------------------------------------------
// Device scratch (no cudaMalloc allowed)
// ---------------------------------------------------------------------------
__device__ __half g_a16[(size_t)MROWS * GK];              // A operand (x, then attn-out), fp16
__device__ __half g_wq[(size_t)(3 * EMB) * GK];           // W_qkv^T fp16 [6144,2048]
__device__ __half g_wo[(size_t)EMB * GK];                 // W_out^T fp16 [2048,2048]
// per-head Q/K/V fp16 (all single-rounded), layout [B, H, S, DH]
// Q pre-scaled by log2(e)/sqrt(dh) so softmax runs in exp2 domain directly.
#define QKV_ELEMS ((size_t)BATCH * NH * S_LEN * DH)
__device__ __half g_q16[QKV_ELEMS];
__device__ __half g_k16[QKV_ELEMS];
__device__ __half g_v16[QKV_ELEMS];

// ---------------------------------------------------------------------------
// PTX helpers (plain sm_80+ instructions only)
// ---------------------------------------------------------------------------
__device__ __forceinline__ uint32_t smem_to_u32(const void* p) {
    uint32_t a;
    asm("{ .reg .u64 t; cvta.to.shared.u64 t, %1; cvt.u32.u64 %0, t; }"
        : "=r"(a) : "l"(p));
    return a;
}

__device__ __forceinline__ void cp_async16(uint32_t saddr, const void* gaddr) {
    asm volatile("cp.async.cg.shared.global [%0], [%1], 16;"
        :: "r"(saddr), "l"(gaddr) : "memory");
}
#define CP_COMMIT() asm volatile("cp.async.commit_group;" ::: "memory")
#define CP_WAIT(n)  asm volatile("cp.async.wait_group %0;" :: "n"(n) : "memory")

__device__ __forceinline__ void ldsm_x4(uint32_t* r, uint32_t addr) {
    asm volatile("ldmatrix.sync.aligned.m8n8.x4.shared.b16 {%0,%1,%2,%3}, [%4];"
        : "=r"(r[0]), "=r"(r[1]), "=r"(r[2]), "=r"(r[3]) : "r"(addr));
}
__device__ __forceinline__ void ldsm_x4_t(uint32_t* r, uint32_t addr) {
    asm volatile("ldmatrix.sync.aligned.m8n8.x4.trans.shared.b16 {%0,%1,%2,%3}, [%4];"
        : "=r"(r[0]), "=r"(r[1]), "=r"(r[2]), "=r"(r[3]) : "r"(addr));
}

// fp16 MMA (all tensor work)
__device__ __forceinline__ void mma16816h(float* d, const uint32_t* a,
                                          const uint32_t* b) {
    asm volatile(
        "mma.sync.aligned.m16n8k16.row.col.f32.f16.f16.f32 "
        "{%0,%1,%2,%3}, {%4,%5,%6,%7}, {%8,%9}, {%0,%1,%2,%3};"
        : "+f"(d[0]), "+f"(d[1]), "+f"(d[2]), "+f"(d[3])
        : "r"(a[0]), "r"(a[1]), "r"(a[2]), "r"(a[3]), "r"(b[0]), "r"(b[1]));
}

// Fast 2^t on FMA/ALU pipes only (no MUFU, no CVT). |rel err| < 3e-6.
__device__ __forceinline__ float exp2_fast(float t) {
    t = fmaxf(t, -126.0f);
    const float MAGIC = 12582912.0f;          // 2^23 + 2^22
    float z = t + MAGIC;
    int i = __float_as_int(z);
    float r = z - MAGIC;
    float f = t - r;                          // f in [-0.5, 0.5]
    float p = 1.3333558146e-3f;
    p = fmaf(p, f, 9.6181291076e-3f);
    p = fmaf(p, f, 5.5504108664e-2f);
    p = fmaf(p, f, 2.4022650696e-1f);
    p = fmaf(p, f, 6.9314718056e-1f);
    p = fmaf(p, f, 1.0f);
    int eb = (i + (127 - 0x4B400000)) << 23;
    return p * __int_as_float(eb);
}

__device__ __forceinline__ uint32_t h2u(__half2 v) {
    return *(uint32_t*)&v;
}

#define SOFTMAX_SCALE 0.12751744f     // log2(e) / sqrt(128)

// ---------------------------------------------------------------------------
// Conversion kernels
// ---------------------------------------------------------------------------
__global__ __launch_bounds__(256) void to_half_kernel(
    const float* __restrict__ in, __half* __restrict__ out, int n)
{
    int i = blockIdx.x * blockDim.x + threadIdx.x;
    int stride = gridDim.x * blockDim.x;
    for (; i < n; i += stride) out[i] = __float2half(in[i]);
}

// W[K,N] row-major -> T[N,K] fp16 (single rounding)
__global__ __launch_bounds__(256) void transpose_half_kernel(
    const float* __restrict__ W, __half* __restrict__ T, int K, int N)
{
    __shared__ float t[32][33];
    const int nb = blockIdx.x * 32;
    const int kb = blockIdx.y * 32;
    const int x = threadIdx.x, y = threadIdx.y;   // block (32,8)
    #pragma unroll
    for (int j = 0; j < 32; j += 8)
        t[y + j][x] = W[(size_t)(kb + y + j) * N + nb + x];
    __syncthreads();
    #pragma unroll
    for (int j = 0; j < 32; j += 8)
        T[(size_t)(nb + y + j) * K + kb + x] = __float2half(t[x][y + j]);
}

// ---------------------------------------------------------------------------
// fp16 1-term HMMA mainloop: C = A*B^T + bias.
// Block 128x128, 8 warps (2x4), warp tile 64x32, K-chunk 64, 2-stage buffer.
// ---------------------------------------------------------------------------
#define GBK   64
#define NCHUNK (GK / GBK)
#define TBYTES 16384
#define STAGE  (2 * TBYTES)          // 32 KB (A + B)
#define GEMM_SMEM (2 * STAGE)        // 64 KB

template <typename Epilogue>
__device__ __forceinline__ void gemm_mainloop(
    char* gsm,
    const __half* __restrict__ A, const __half* __restrict__ B,
    const float* __restrict__ bias, int bx, int by, Epilogue epi)
{
    const uint32_t sb = smem_to_u32(gsm);
    const int tid = threadIdx.x;
    const int w = tid >> 5, l = tid & 31;
    const int warp_m = w >> 2, warp_n = w & 3;

    const __half* srcs[2] = {
        A + (size_t)(by * 128) * GK,
        B + (size_t)(bx * 128) * GK };

    float acc[4][4][4];
    #pragma unroll
    for (int nt = 0; nt < 4; nt++) {
        const int n = bx * 128 + warp_n * 32 + nt * 8 + ((l & 3) << 1);
        const float b0 = bias[n], b1 = bias[n + 1];
        #pragma unroll
        for (int mt = 0; mt < 4; mt++) {
            acc[mt][nt][0] = b0; acc[mt][nt][1] = b1;
            acc[mt][nt][2] = b0; acc[mt][nt][3] = b1;
        }
    }

    auto load_chunk = [&](int kt) {
        const uint32_t st = sb + (kt & 1) * STAGE;
        const size_t kofs = (size_t)kt * GBK;
        #pragma unroll
        for (int a = 0; a < 2; a++) {
            const char* g = (const char*)(srcs[a] + kofs);
            #pragma unroll
            for (int j = 0; j < 4; j++) {
                const int u = tid + 256 * j;
                const int r = u >> 3;
                const int cu = u & 7;
                const uint32_t off = r * 128 + ((cu ^ (r & 7)) << 4);
                cp_async16(st + a * TBYTES + off,
                           g + (size_t)r * (GK * 2) + (cu << 4));
            }
        }
        CP_COMMIT();
    };

    load_chunk(0);

    for (int kt = 0; kt < NCHUNK; kt++) {
        if (kt + 1 < NCHUNK) { load_chunk(kt + 1); CP_WAIT(1); }
        else                 { CP_WAIT(0); }
        __syncthreads();

        const uint32_t st = sb + (kt & 1) * STAGE;
        const uint32_t sA = st, sB = st + TBYTES;

        #pragma unroll
        for (int kk = 0; kk < 4; kk++) {
            const int kb = kk * 32;

            uint32_t af[4][4];
            #pragma unroll
            for (int mt = 0; mt < 4; mt++) {
                const int row = warp_m * 64 + mt * 16 + (l & 15);
                const int bc = kb + ((l >> 4) << 4);
                const uint32_t off = row * 128 + (bc ^ ((row & 7) << 4));
                ldsm_x4(af[mt], sA + off);
            }

            uint32_t bf[2][4];
            #pragma unroll
            for (int np = 0; np < 2; np++) {
                const int g = l >> 3, idx = l & 7;
                const int row = warp_n * 32 + np * 16 + ((g >> 1) << 3) + idx;
                const int bc = kb + ((g & 1) << 4);
                const uint32_t off = row * 128 + (bc ^ ((row & 7) << 4));
                ldsm_x4(bf[np], sB + off);
            }

            #pragma unroll
            for (int mt = 0; mt < 4; mt++)
                #pragma unroll
                for (int nt = 0; nt < 4; nt++)
                    mma16816h(acc[mt][nt], af[mt], &bf[nt >> 1][(nt & 1) * 2]);
        }
        __syncthreads();
    }

    epi(acc, warp_m, warp_n, l);
}

// GEMM2: plain fp32 output C = A*B^T + bias
__global__ __launch_bounds__(256) void gemm_mma_kernel(
    int N,
    const __half* __restrict__ A, const __half* __restrict__ B,
    const float* __restrict__ bias, float* __restrict__ C)
{
    extern __shared__ char gsm[];
    const int bx = blockIdx.x, by = blockIdx.y;
    gemm_mainloop(gsm, A, B, bias, bx, by,
        [&](float acc[4][4][4], int warp_m, int warp_n, int l) {
            #pragma unroll
            for (int mt = 0; mt < 4; mt++) {
                const int m = by * 128 + warp_m * 64 + mt * 16 + (l >> 2);
                float* c0 = C + (size_t)m * N + bx * 128 + warp_n * 32 + ((l & 3) << 1);
                #pragma unroll
                for (int nt = 0; nt < 4; nt++) {
                    *(float2*)(c0 + nt * 8) =
                        make_float2(acc[mt][nt][0], acc[mt][nt][1]);
                    *(float2*)(c0 + (size_t)8 * N + nt * 8) =
                        make_float2(acc[mt][nt][2], acc[mt][nt][3]);
                }
            }
        });
}

// GEMM1 fused: writes per-head fp16 Q (pre-scaled), K, V (all single-rounded).
__global__ __launch_bounds__(256) void gemm_qkv_kernel(
    const __half* __restrict__ A, const __half* __restrict__ B,
    const float* __restrict__ bias)
{
    extern __shared__ char gsm[];
    const int bx = blockIdx.x, by = blockIdx.y;
    const int region = bx % 3;        // 0=q, 1=k, 2=v
    const int head   = bx / 3;
    __half* H = (region == 0) ? g_q16 : (region == 1) ? g_k16 : g_v16;
    const float scl = (region == 0) ? SOFTMAX_SCALE : 1.0f;

    gemm_mainloop(gsm, A, B, bias, bx, by,
        [&](float acc[4][4][4], int warp_m, int warp_n, int l) {
            #pragma unroll
            for (int mt = 0; mt < 4; mt++) {
                const int m = by * 128 + warp_m * 64 + mt * 16 + (l >> 2);
                const int b = m >> 11, s = m & (S_LEN - 1);
                const size_t base =
                    (((size_t)(b * NH + head)) * S_LEN + s) * DH;
                #pragma unroll
                for (int nt = 0; nt < 4; nt++) {
                    const int d = warp_n * 32 + nt * 8 + ((l & 3) << 1);
                    const __half2 h0 = __floats2half2_rn(acc[mt][nt][0] * scl,
                                                         acc[mt][nt][1] * scl);
                    const __half2 h1 = __floats2half2_rn(acc[mt][nt][2] * scl,
                                                         acc[mt][nt][3] * scl);
                    *(__half2*)(H + base + d) = h0;
                    *(__half2*)(H + base + (size_t)8 * DH + d) = h1;
                }
            }
        });
}

// ---------------------------------------------------------------------------
// FA2-style tensor-core attention, fp16 single-term:
//   QK: Q * K  (Q pre-scaled into exp2 domain) ; PV: P * V
// 8 warps; each warp owns 16 Q rows. 3-stage KV pipeline, 1 sync/tile.
// Epilogue writes GEMM2's A operand (fp16).
// ---------------------------------------------------------------------------
#define ATQ 128
#define AKT 32
#define ANT (S_LEN / AKT)

#define ASM_Q  0                      // 32768 bytes (128 rows x 256B)
#define ASM_KV 32768                  // 3 stages x 16384 (K|V x 8KB)
#define KVSTAGE 16384
#define ATTN_SMEM (32768 + 3 * KVSTAGE)  // 81920

#define SWZ(row, cu) ((row) * 256 + ((((cu) ^ ((row) & 7))) << 4))

__global__ __launch_bounds__(256) void attn_mma_kernel(
    const __half* __restrict__ q16, const __half* __restrict__ k16,
    const __half* __restrict__ v16,
    __half* __restrict__ outA)
{
    extern __shared__ char gsm[];
    const uint32_t sb = smem_to_u32(gsm);
    const int tid = threadIdx.x;
    const int w = tid >> 5, l = tid & 31;
    const int qt = blockIdx.x, h = blockIdx.y, b = blockIdx.z;

    const size_t head = ((size_t)(b * NH + h)) * S_LEN * DH;
    const __half* Q_g = q16 + head + (size_t)qt * ATQ * DH;

    auto load_kv = [&](int t) {
        const uint32_t st = sb + ASM_KV + (t % 3) * KVSTAGE;
        const size_t base = head + (size_t)t * AKT * DH;
        const __half* srcs[2] = {k16 + base, v16 + base};
        #pragma unroll
        for (int a = 0; a < 2; a++) {
            #pragma unroll
            for (int j = 0; j < 2; j++) {
                const int u = tid + 256 * j;
                const int row = u >> 4, cu = u & 15;
                cp_async16(st + a * 8192 + SWZ(row, cu),
                           (const char*)srcs[a] + (size_t)row * 256 + cu * 16);
            }
        }
        CP_COMMIT();
    };

    // Q loads committed together with KV(0) as group 0.
    #pragma unroll
    for (int j = 0; j < 8; j++) {
        const int u = tid + 256 * j;
        const int row = u >> 4, cu = u & 15;
        cp_async16(sb + ASM_Q + SWZ(row, cu),
                   (const char*)Q_g + (size_t)row * 256 + cu * 16);
    }
    load_kv(0);
    load_kv(1);

    // Wait for group 0 (Q + KV0), then cache ALL Q fragments in registers.
    CP_WAIT(1);
    __syncthreads();
    uint32_t qf[8][4];
    #pragma unroll
    for (int kk = 0; kk < 8; kk++) {
        const int row = w * 16 + (l & 15);
        const int cu = kk * 2 + (l >> 4);
        ldsm_x4(qf[kk], sb + ASM_Q + SWZ(row, cu));
    }

    float m0 = -1e9f, m1 = -1e9f, ls0 = 0.f, ls1 = 0.f;
    float O[16][4];
    #pragma unroll
    for (int nt = 0; nt < 16; nt++)
        #pragma unroll
        for (int c = 0; c < 4; c++) O[nt][c] = 0.f;

    for (int t = 0; t < ANT; t++) {
        if (t > 0) {
            if (t + 1 < ANT) { CP_WAIT(1); } else { CP_WAIT(0); }
            __syncthreads();
        }
        if (t + 2 < ANT) load_kv(t + 2);

        const uint32_t stg = sb + ASM_KV + (t % 3) * KVSTAGE;

        // ---- QK: sacc[nt][4], warp tile 16x32, Q from registers ------------
        float sacc[4][4];
        #pragma unroll
        for (int nt = 0; nt < 4; nt++)
            #pragma unroll
            for (int c = 0; c < 4; c++) sacc[nt][c] = 0.f;

        #pragma unroll
        for (int kk = 0; kk < 8; kk++) {
            uint32_t kf[2][4];
            #pragma unroll
            for (int np = 0; np < 2; np++) {
                const int g = l >> 3, idx = l & 7;
                const int krow = np * 16 + ((g >> 1) << 3) + idx;
                const int bcu = kk * 2 + (g & 1);
                ldsm_x4(kf[np], stg + SWZ(krow, bcu));
            }
            #pragma unroll
            for (int nt = 0; nt < 4; nt++)
                mma16816h(sacc[nt], qf[kk], &kf[nt >> 1][(nt & 1) * 2]);
        }

        // ---- softmax in registers (scores already in exp2 domain) ----------
        float mx0 = sacc[0][0], mx1 = sacc[0][2];
        #pragma unroll
        for (int nt = 0; nt < 4; nt++) {
            mx0 = fmaxf(mx0, fmaxf(sacc[nt][0], sacc[nt][1]));
            mx1 = fmaxf(mx1, fmaxf(sacc[nt][2], sacc[nt][3]));
        }
        mx0 = fmaxf(mx0, __shfl_xor_sync(0xffffffffu, mx0, 1));
        mx0 = fmaxf(mx0, __shfl_xor_sync(0xffffffffu, mx0, 2));
        mx1 = fmaxf(mx1, __shfl_xor_sync(0xffffffffu, mx1, 1));
        mx1 = fmaxf(mx1, __shfl_xor_sync(0xffffffffu, mx1, 2));
        const float mn0 = fmaxf(m0, mx0);
        const float mn1 = fmaxf(m1, mx1);

        uint32_t ph[2][4];
        float s0 = 0.f, s1 = 0.f;
        #pragma unroll
        for (int nt = 0; nt < 4; nt++) {
            const float p0 = exp2_fast(sacc[nt][0] - mn0);
            const float p1 = exp2_fast(sacc[nt][1] - mn0);
            const float p2 = exp2_fast(sacc[nt][2] - mn1);
            const float p3 = exp2_fast(sacc[nt][3] - mn1);
            s0 += p0 + p1;
            s1 += p2 + p3;
            const __half2 h01 = __floats2half2_rn(p0, p1);
            const __half2 h23 = __floats2half2_rn(p2, p3);
            const int kk = nt >> 1, base = (nt & 1) * 2;
            ph[kk][base]     = h2u(h01);
            ph[kk][base + 1] = h2u(h23);
        }
        s0 += __shfl_xor_sync(0xffffffffu, s0, 1);
        s0 += __shfl_xor_sync(0xffffffffu, s0, 2);
        s1 += __shfl_xor_sync(0xffffffffu, s1, 1);
        s1 += __shfl_xor_sync(0xffffffffu, s1, 2);
        const float f0 = exp2_fast(m0 - mn0);
        const float f1 = exp2_fast(m1 - mn1);
        ls0 = ls0 * f0 + s0;
        ls1 = ls1 * f1 + s1;
        m0 = mn0; m1 = mn1;

        #pragma unroll
        for (int nt = 0; nt < 16; nt++) {
            O[nt][0] *= f0; O[nt][1] *= f0;
            O[nt][2] *= f1; O[nt][3] *= f1;
        }

        // ---- PV: warp tile 16x128, P from registers -------------------------
        const uint32_t sV = stg + 8192;
        #pragma unroll
        for (int kk = 0; kk < 2; kk++) {
            #pragma unroll
            for (int np = 0; np < 8; np++) {
                uint32_t vb[4];
                const int mat = l >> 3, idx = l & 7;
                const int key = kk * 16 + ((mat & 1) << 3) + idx;
                const int cu = np * 2 + (mat >> 1);
                ldsm_x4_t(vb, sV + SWZ(key, cu));
                mma16816h(O[np * 2 + 0], ph[kk], &vb[0]);
                mma16816h(O[np * 2 + 1], ph[kk], &vb[2]);
            }
        }
    }

    // ---- epilogue: normalize, write GEMM2's A (fp16) ----------------------
    const float inv0 = 1.f / ls0;
    const float inv1 = 1.f / ls1;
    const int row0 = qt * ATQ + w * 16 + (l >> 2);
    const size_t s0o = (size_t)(b * S_LEN + row0) * EMB + h * DH;
    #pragma unroll
    for (int nt = 0; nt < 16; nt++) {
        const int col = nt * 8 + ((l & 3) << 1);
        const __half2 h0 = __floats2half2_rn(O[nt][0] * inv0, O[nt][1] * inv0);
        const __half2 h1 = __floats2half2_rn(O[nt][2] * inv1, O[nt][3] * inv1);
        *(__half2*)(outA + s0o + col) = h0;
        *(__half2*)(outA + s0o + (size_t)8 * EMB + col) = h1;
    }
}

// ---------------------------------------------------------------------------
extern "C" void kernel_launch(void* const* d_in, const int* in_sizes, int n_in,
                              void* d_out, int out_size)
{
    (void)in_sizes; (void)n_in; (void)out_size;
    const float* x    = (const float*)d_in[0];
    const float* Wqkv = (const float*)d_in[1];
    const float* bqkv = (const float*)d_in[2];
    const float* Wout = (const float*)d_in[3];
    const float* bout = (const float*)d_in[4];
    float* out = (float*)d_out;

    __half *a16, *wq, *wo, *q16, *k16, *v16;
    cudaGetSymbolAddress((void**)&a16, g_a16);
    cudaGetSymbolAddress((void**)&wq, g_wq);
    cudaGetSymbolAddress((void**)&wo, g_wo);
    cudaGetSymbolAddress((void**)&q16, g_q16);
    cudaGetSymbolAddress((void**)&k16, g_k16);
    cudaGetSymbolAddress((void**)&v16, g_v16);

    cudaFuncSetAttribute(gemm_mma_kernel,
                         cudaFuncAttributeMaxDynamicSharedMemorySize, GEMM_SMEM);
    cudaFuncSetAttribute(gemm_qkv_kernel,
                         cudaFuncAttributeMaxDynamicSharedMemorySize, GEMM_SMEM);
    cudaFuncSetAttribute(attn_mma_kernel,
                         cudaFuncAttributeMaxDynamicSharedMemorySize, ATTN_SMEM);

    // 0) conversions (inputs only)
    to_half_kernel<<<2048, 256>>>(x, a16, MROWS * EMB);
    transpose_half_kernel<<<dim3((3 * EMB) / 32, GK / 32), dim3(32, 8)>>>(
        Wqkv, wq, GK, 3 * EMB);
    transpose_half_kernel<<<dim3(EMB / 32, GK / 32), dim3(32, 8)>>>(
        Wout, wo, GK, EMB);

    // 1) qkv projection (fp16) fused with per-head write (Q pre-scaled)
    gemm_qkv_kernel<<<dim3((3 * EMB) / 128, MROWS / 128), 256, GEMM_SMEM>>>(
        a16, wq, bqkv);

    // 2) FA2-style attention (fp16 single-term); writes GEMM2's A (fp16)
    attn_mma_kernel<<<dim3(S_LEN / ATQ, NH, BATCH), 256, ATTN_SMEM>>>(
        q16, k16, v16, a16);

    // 3) out = attn @ W_out + b_out  (fp16)
    gemm_mma_kernel<<<dim3(EMB / 128, MROWS / 128), 256, GEMM_SMEM>>>(
        EMB, a16, wo, bout, out);
}